// round 8
// baseline (speedup 1.0000x reference)
#include <cuda_runtime.h>
#include <math.h>
#include <float.h>
#include <stdint.h>

#define N 8192
#define D 512
#define KNN 16
#define NPAIRS 120   // 16*15/2

// ---------------- scratch (device globals; no runtime allocation) ----------
__device__ float g_sq[N];
__device__ float g_embr[(size_t)N * D];     // tf32-rounded (rna) copy of embeddings
__device__ float g_dist[(size_t)N * N];     // 256 MB full symmetric distance matrix
__device__ int   g_knn_idx[N * KNN];
__device__ float g_knn_d[N * KNN];
__device__ float g_curv_err[N];
__device__ float g_knn_sum[N];

// ---------------- PTX helpers ----------------------------------------------
__device__ __forceinline__ uint32_t smem_u32(const void* p) {
    uint32_t a;
    asm("{ .reg .u64 t; cvta.to.shared.u64 t, %1; cvt.u32.u64 %0, t; }" : "=r"(a) : "l"(p));
    return a;
}
__device__ __forceinline__ uint32_t f2tf32(float v) {
    uint32_t o;
    asm("cvt.rna.tf32.f32 %0, %1;" : "=r"(o) : "f"(v));
    return o;
}
#define CP_ASYNC16(dst, src) \
    asm volatile("cp.async.cg.shared.global [%0], [%1], 16;" :: "r"(dst), "l"(src))
#define CP_COMMIT() asm volatile("cp.async.commit_group;" ::: "memory")
#define CP_WAIT(n)  asm volatile("cp.async.wait_group %0;" :: "n"(n) : "memory")

__device__ __forceinline__ void ldsm_x4(uint32_t* r, uint32_t addr) {
    asm volatile("ldmatrix.sync.aligned.m8n8.x4.shared.b16 {%0,%1,%2,%3}, [%4];"
                 : "=r"(r[0]), "=r"(r[1]), "=r"(r[2]), "=r"(r[3]) : "r"(addr));
}
__device__ __forceinline__ void ldsm_x2(uint32_t* r, uint32_t addr) {
    asm volatile("ldmatrix.sync.aligned.m8n8.x2.shared.b16 {%0,%1}, [%2];"
                 : "=r"(r[0]), "=r"(r[1]) : "r"(addr));
}
__device__ __forceinline__ void mma_tf32(float* c, const uint32_t* a, const uint32_t* b) {
    asm volatile(
        "mma.sync.aligned.m16n8k8.row.col.f32.tf32.tf32.f32 "
        "{%0,%1,%2,%3}, {%4,%5,%6,%7}, {%8,%9}, {%0,%1,%2,%3};"
        : "+f"(c[0]), "+f"(c[1]), "+f"(c[2]), "+f"(c[3])
        : "r"(a[0]), "r"(a[1]), "r"(a[2]), "r"(a[3]), "r"(b[0]), "r"(b[1]));
}

// ---------------- K1: row squared norms + tf32-rounded copy ----------------
__global__ void row_norms_kernel(const float* __restrict__ A) {
    int row = blockIdx.x;
    int t = threadIdx.x;                         // 128 threads, D/4 = 128
    const float4* a4 = (const float4*)(A + (size_t)row * D);
    float4 v = a4[t];
    uint4 q;
    q.x = f2tf32(v.x); q.y = f2tf32(v.y); q.z = f2tf32(v.z); q.w = f2tf32(v.w);
    *(uint4*)(g_embr + (size_t)row * D + t * 4) = q;
    float s = v.x * v.x + v.y * v.y + v.z * v.z + v.w * v.w;
    #pragma unroll
    for (int o = 16; o > 0; o >>= 1) s += __shfl_down_sync(0xffffffffu, s, o);
    __shared__ float red[4];
    if ((t & 31) == 0) red[t >> 5] = s;
    __syncthreads();
    if (t == 0) g_sq[row] = red[0] + red[1] + red[2] + red[3];
}

// ---------------- K2: tf32 mma.sync distance GEMM (symmetric) --------------
#define BM 128
#define BN 256
#define BKC 32
#define NCHUNK (D / BKC)   // 16
#define NTILES 1056
#define GEMM_SPLIT 888

#define SM_SQJ   0
#define SM_SQI   1024
#define SM_STAGE 2048
#define STAGE_BYTES 49152                   // A 16KB + B 32KB
#define SM_TOTAL (SM_STAGE + 3 * STAGE_BYTES)

static __device__ __forceinline__ uint32_t sw128(uint32_t b) { return b ^ ((b >> 3) & 0x70); }

__global__ __launch_bounds__(256, 1)
void dist_gemm_mma_kernel(int tile_base) {
    extern __shared__ char smem[];
    const uint32_t sbase = smem_u32(smem);
    const int t    = threadIdx.x;
    const int wid  = t >> 5;
    const int lane = t & 31;
    const int g    = lane >> 2;
    const int tq   = lane & 3;
    const int warpM = (wid >> 2) * 64;
    const int warpN = (wid & 3) * 64;

    int flat = tile_base + blockIdx.x;
    int bi = 0, cnt = 32;
    while (flat >= cnt) { flat -= cnt; ++bi; cnt = 32 - (bi >> 1); }
    const int bj = (bi >> 1) + flat;
    const int rowA0 = bi * BM;
    const int colB0 = bj * BN;

    *(float*)(smem + SM_SQJ + t * 4) = g_sq[colB0 + t];
    if (t < 128) *(float*)(smem + SM_SQI + t * 4) = g_sq[rowA0 + t];

    const uint32_t laneRowA = (lane & 7) + ((lane >> 3) & 1) * 8;
    const uint32_t laneColA = (lane >> 4) * 16;
    const uint32_t laneRowB = lane & 7;
    const uint32_t laneColB = ((lane >> 3) & 1) * 16;

    auto issue_chunk = [&](int kt, int stg) {
        const int kc = kt * BKC;
        const uint32_t sb = sbase + SM_STAGE + (uint32_t)stg * STAGE_BYTES;
        #pragma unroll
        for (int l = 0; l < 12; l++) {
            int idx = t + l * 256;
            int r   = idx >> 3;
            int c4  = idx & 7;
            int isA = (r < 128);
            int grow = isA ? (rowA0 + r) : (colB0 + r - 128);
            const float* src = g_embr + (size_t)grow * D + kc + c4 * 4;
            uint32_t off = (isA ? 0u : 16384u) +
                           sw128((uint32_t)(isA ? r : r - 128) * 128u + (uint32_t)c4 * 16u);
            CP_ASYNC16(sb + off, src);
        }
        CP_COMMIT();
    };

    float acc[4][8][4];
    #pragma unroll
    for (int mt = 0; mt < 4; mt++)
        #pragma unroll
        for (int nt = 0; nt < 8; nt++)
            #pragma unroll
            for (int q = 0; q < 4; q++) acc[mt][nt][q] = 0.f;

    issue_chunk(0, 0);
    issue_chunk(1, 1);

    #pragma unroll 1
    for (int kt = 0; kt < NCHUNK; kt++) {
        const int stg = kt % 3;
        CP_WAIT(1);
        __syncthreads();
        if (kt + 2 < NCHUNK) issue_chunk(kt + 2, (kt + 2) % 3);

        const uint32_t abase = sbase + SM_STAGE + (uint32_t)stg * STAGE_BYTES;
        const uint32_t bbase = abase + 16384u;
        #pragma unroll
        for (int ks = 0; ks < 4; ks++) {
            uint32_t af[4][4], bf[8][2];
            #pragma unroll
            for (int mt = 0; mt < 4; mt++) {
                uint32_t byte = (uint32_t)(warpM + mt * 16 + laneRowA) * 128u +
                                (uint32_t)ks * 32u + laneColA;
                ldsm_x4(af[mt], abase + sw128(byte));
            }
            #pragma unroll
            for (int nt = 0; nt < 8; nt++) {
                uint32_t byte = (uint32_t)(warpN + nt * 8 + laneRowB) * 128u +
                                (uint32_t)ks * 32u + laneColB;
                ldsm_x2(bf[nt], bbase + sw128(byte));
            }
            #pragma unroll
            for (int mt = 0; mt < 4; mt++)
                #pragma unroll
                for (int nt = 0; nt < 8; nt++)
                    mma_tf32(acc[mt][nt], af[mt], bf[nt]);
        }
        __syncthreads();
    }

    const float* sqj = (const float*)(smem + SM_SQJ);
    const float* sqi = (const float*)(smem + SM_SQI);
    #pragma unroll
    for (int mt = 0; mt < 4; mt++) {
        const int r0 = warpM + mt * 16 + g;
        const int r1 = r0 + 8;
        const int gr0 = rowA0 + r0, gr1 = rowA0 + r1;
        const float si0 = sqi[r0], si1 = sqi[r1];
        #pragma unroll
        for (int nt = 0; nt < 8; nt++) {
            const int cl = warpN + nt * 8 + tq * 2;
            const int gc = colB0 + cl;
            const float sj0 = sqj[cl], sj1 = sqj[cl + 1];
            float d2;
            float2 o0, o1;
            d2 = si0 + sj0 - 2.f * acc[mt][nt][0];
            o0.x = (d2 > 0.f) ? sqrtf(fmaxf(d2, 1e-12f)) : 0.f;
            d2 = si0 + sj1 - 2.f * acc[mt][nt][1];
            o0.y = (d2 > 0.f) ? sqrtf(fmaxf(d2, 1e-12f)) : 0.f;
            d2 = si1 + sj0 - 2.f * acc[mt][nt][2];
            o1.x = (d2 > 0.f) ? sqrtf(fmaxf(d2, 1e-12f)) : 0.f;
            d2 = si1 + sj1 - 2.f * acc[mt][nt][3];
            o1.y = (d2 > 0.f) ? sqrtf(fmaxf(d2, 1e-12f)) : 0.f;
            *(float2*)(g_dist + (size_t)gr0 * N + gc) = o0;
            *(float2*)(g_dist + (size_t)gr1 * N + gc) = o1;
            g_dist[(size_t)gc * N + gr0]       = o0.x;
            g_dist[(size_t)gc * N + gr1]       = o1.x;
            g_dist[(size_t)(gc + 1) * N + gr0] = o0.y;
            g_dist[(size_t)(gc + 1) * N + gr1] = o1.y;
        }
    }
}

// ---------------- K3: warp-per-row top-16 with cooperative prune -----------
// Each warp owns one row (8 rows/block). Lanes keep a register top-16 and a
// prune threshold thr = min(warp-min of lane vmaxes, own vmax) refreshed every
// 16 elements/lane. Safe filter: any true top-16 element is < global 16th
// <= thr at all times. Merge: bitonic-sorted lists -> 16 shuffle-min rounds.
#define CAS(a,b) { bool sw_ = v[a] > v[b]; \
    float tv_ = sw_ ? v[a] : v[b]; v[a] = sw_ ? v[b] : v[a]; v[b] = tv_; \
    int   ti_ = sw_ ? id[a] : id[b]; id[a] = sw_ ? id[b] : id[a]; id[b] = ti_; }

__global__ __launch_bounds__(256)
void topk_kernel() {
    const int w    = threadIdx.x >> 5;
    const int lane = threadIdx.x & 31;
    const int i    = blockIdx.x * 8 + w;
    const float* __restrict__ drow = g_dist + (size_t)i * N;

    float v[KNN]; int id[KNN];
    #pragma unroll
    for (int u = 0; u < KNN; u++) { v[u] = FLT_MAX; id[u] = -1; }
    float vmax = FLT_MAX; int pmax = 0;
    float thr = FLT_MAX;

    // 64 float4 batches per lane, MLP-4, threshold refresh per outer iter
    #pragma unroll 1
    for (int b = 0; b < 64; b += 4) {
        float4 q[4];
        #pragma unroll
        for (int u = 0; u < 4; u++)
            q[u] = *(const float4*)(drow + ((b + u) * 32 + lane) * 4);
        #pragma unroll
        for (int u = 0; u < 4; u++) {
            const int j4 = ((b + u) * 32 + lane) * 4;
            if ((unsigned)(i - j4) < 4u) ((float*)&q[u])[i - j4] = FLT_MAX;
            #pragma unroll
            for (int c = 0; c < 4; c++) {
                float dv = ((float*)&q[u])[c];
                if (dv < thr) {
                    const int jj = j4 + c;
                    #pragma unroll
                    for (int uu = 0; uu < KNN; uu++)
                        if (uu == pmax) { v[uu] = dv; id[uu] = jj; }
                    float m = -1.f; int p = 0;
                    #pragma unroll
                    for (int uu = 0; uu < KNN; uu++)
                        if (v[uu] > m) { m = v[uu]; p = uu; }
                    vmax = m; pmax = p;
                    thr = fminf(thr, vmax);
                }
            }
        }
        // warp-min of vmax -> tighter safe threshold
        float tm = vmax;
        #pragma unroll
        for (int o = 16; o > 0; o >>= 1)
            tm = fminf(tm, __shfl_xor_sync(0xffffffffu, tm, o));
        thr = tm;
    }

    // bitonic sort own 16 (ascending), compile-time indices
    #pragma unroll
    for (int kk = 2; kk <= 16; kk <<= 1) {
        #pragma unroll
        for (int jj = kk >> 1; jj > 0; jj >>= 1) {
            #pragma unroll
            for (int ii = 0; ii < 16; ii++) {
                int l = ii ^ jj;
                if (l > ii) {
                    if ((ii & kk) == 0) { CAS(ii, l) } else { CAS(l, ii) }
                }
            }
        }
    }

    // spill sorted lists to smem (warp-local region; warp-sync only)
    __shared__ float sv[256 * KNN];
    __shared__ int   si[256 * KNN];
    #pragma unroll
    for (int u = 0; u < KNN; u++) {
        sv[threadIdx.x * KNN + u] = v[u];
        si[threadIdx.x * KNN + u] = id[u];
    }
    __syncwarp();

    int p = 0;
    #pragma unroll 1
    for (int r = 0; r < KNN; r++) {
        const int slot = threadIdx.x * KNN + p;
        const float cand = sv[slot];
        unsigned long long key =
            ((unsigned long long)__float_as_uint(cand) << 32) | (unsigned)slot;
        unsigned long long k2 = key;
        #pragma unroll
        for (int o = 16; o > 0; o >>= 1) {
            unsigned long long other = __shfl_xor_sync(0xffffffffu, k2, o);
            k2 = (other < k2) ? other : k2;
        }
        if (key == k2) {                     // unique winner (slot unique)
            g_knn_d[i * KNN + r]   = cand;
            g_knn_idx[i * KNN + r] = si[slot];
            p++;
        }
    }
}

// ---------------- K4: curvature per point ----------------------------------
__global__ __launch_bounds__(256)
void curvature_kernel(const float* __restrict__ ref_curv) {
    const int i = blockIdx.x;
    const int t = threadIdx.x;
    __shared__ int   nidx[KNN];
    __shared__ float nd[KNN];
    if (t < KNN) { nidx[t] = g_knn_idx[i * KNN + t]; nd[t] = g_knn_d[i * KNN + t]; }
    __syncthreads();

    int j = t >> 4, k = t & 15;
    float inter = 0.f;
    if (j < k) inter = g_dist[(size_t)nidx[j] * N + nidx[k]];
    float dsum = (t < KNN) ? nd[t] : 0.f;

    __shared__ float r1[256], r2[256];
    r1[t] = inter; r2[t] = dsum;
    __syncthreads();
    for (int s = 128; s > 0; s >>= 1) {
        if (t < s) { r1[t] += r1[t + s]; r2[t] += r2[t + s]; }
        __syncthreads();
    }
    if (t == 0) {
        float avg        = r2[0] / (float)KNN;
        float inter_mean = r1[0] / (float)NPAIRS;
        float curv       = inter_mean / (avg + 1e-8f);
        float diff       = curv - ref_curv[i];
        g_curv_err[i] = diff * diff;
        g_knn_sum[i]  = r2[0];
    }
}

// ---------------- K5: final scalar (fp64 accumulation, deterministic) ------
__global__ void final_kernel(const float* __restrict__ ref_dist, float* __restrict__ out) {
    const int t = threadIdx.x;
    double s_err = 0.0, s_knn = 0.0, s_ref = 0.0;
    for (int i = t; i < N; i += 256) { s_err += (double)g_curv_err[i]; s_knn += (double)g_knn_sum[i]; }
    for (int i = t; i < N * KNN; i += 256) s_ref += (double)ref_dist[i];
    __shared__ double d1[256], d2[256], d3[256];
    d1[t] = s_err; d2[t] = s_knn; d3[t] = s_ref;
    __syncthreads();
    for (int s = 128; s > 0; s >>= 1) {
        if (t < s) { d1[t] += d1[t + s]; d2[t] += d2[t + s]; d3[t] += d3[t + s]; }
        __syncthreads();
    }
    if (t == 0) {
        double curv_loss = d1[0] / (double)N;
        double m_knn = d2[0] / (double)(N * KNN);
        double m_ref = d3[0] / (double)(N * KNN);
        double diff  = m_knn - m_ref;
        out[0] = (float)(curv_loss + 0.1 * diff * diff);
    }
}

// ---------------- launch ----------------------------------------------------
extern "C" void kernel_launch(void* const* d_in, const int* in_sizes, int n_in,
                              void* d_out, int out_size) {
    const float* emb      = (const float*)d_in[0];   // [N, D]
    const float* ref_curv = (const float*)d_in[1];   // [N]
    const float* ref_dist = (const float*)d_in[2];   // [N, K]
    float* out = (float*)d_out;

    static int smem_set = 0;
    if (!smem_set) {
        cudaFuncSetAttribute(dist_gemm_mma_kernel,
                             cudaFuncAttributeMaxDynamicSharedMemorySize, SM_TOTAL);
        smem_set = 1;
    }

    row_norms_kernel<<<N, 128>>>(emb);
    dist_gemm_mma_kernel<<<GEMM_SPLIT, 256, SM_TOTAL>>>(0);
    dist_gemm_mma_kernel<<<NTILES - GEMM_SPLIT, 256, SM_TOTAL>>>(GEMM_SPLIT);
    topk_kernel<<<N / 8, 256>>>();
    curvature_kernel<<<N, 256>>>(ref_curv);
    final_kernel<<<1, 256>>>(ref_dist, out);
}

// round 9
// speedup vs baseline: 1.4835x; 1.4835x over previous
#include <cuda_runtime.h>
#include <math.h>
#include <float.h>
#include <stdint.h>

#define N 8192
#define D 512
#define KNN 16
#define NPAIRS 120   // 16*15/2

// ---------------- scratch (device globals; no runtime allocation) ----------
__device__ float g_sq[N];
__device__ float g_embr[(size_t)N * D];     // tf32-rounded (rna) copy of embeddings
__device__ float g_dist[(size_t)N * N];     // 256 MB full symmetric distance matrix
__device__ int   g_knn_idx[N * KNN];
__device__ float g_knn_d[N * KNN];
__device__ float g_curv_err[N];
__device__ float g_knn_sum[N];

// ---------------- PTX helpers ----------------------------------------------
__device__ __forceinline__ uint32_t smem_u32(const void* p) {
    uint32_t a;
    asm("{ .reg .u64 t; cvta.to.shared.u64 t, %1; cvt.u32.u64 %0, t; }" : "=r"(a) : "l"(p));
    return a;
}
__device__ __forceinline__ uint32_t f2tf32(float v) {
    uint32_t o;
    asm("cvt.rna.tf32.f32 %0, %1;" : "=r"(o) : "f"(v));
    return o;
}
#define CP_ASYNC16(dst, src) \
    asm volatile("cp.async.cg.shared.global [%0], [%1], 16;" :: "r"(dst), "l"(src))
#define CP_COMMIT() asm volatile("cp.async.commit_group;" ::: "memory")
#define CP_WAIT(n)  asm volatile("cp.async.wait_group %0;" :: "n"(n) : "memory")

__device__ __forceinline__ void ldsm_x4(uint32_t* r, uint32_t addr) {
    asm volatile("ldmatrix.sync.aligned.m8n8.x4.shared.b16 {%0,%1,%2,%3}, [%4];"
                 : "=r"(r[0]), "=r"(r[1]), "=r"(r[2]), "=r"(r[3]) : "r"(addr));
}
__device__ __forceinline__ void ldsm_x2(uint32_t* r, uint32_t addr) {
    asm volatile("ldmatrix.sync.aligned.m8n8.x2.shared.b16 {%0,%1}, [%2];"
                 : "=r"(r[0]), "=r"(r[1]) : "r"(addr));
}
__device__ __forceinline__ void mma_tf32(float* c, const uint32_t* a, const uint32_t* b) {
    asm volatile(
        "mma.sync.aligned.m16n8k8.row.col.f32.tf32.tf32.f32 "
        "{%0,%1,%2,%3}, {%4,%5,%6,%7}, {%8,%9}, {%0,%1,%2,%3};"
        : "+f"(c[0]), "+f"(c[1]), "+f"(c[2]), "+f"(c[3])
        : "r"(a[0]), "r"(a[1]), "r"(a[2]), "r"(a[3]), "r"(b[0]), "r"(b[1]));
}

// ---------------- K1: row squared norms + tf32-rounded copy ----------------
__global__ void row_norms_kernel(const float* __restrict__ A) {
    int row = blockIdx.x;
    int t = threadIdx.x;                         // 128 threads, D/4 = 128
    const float4* a4 = (const float4*)(A + (size_t)row * D);
    float4 v = a4[t];
    uint4 q;
    q.x = f2tf32(v.x); q.y = f2tf32(v.y); q.z = f2tf32(v.z); q.w = f2tf32(v.w);
    *(uint4*)(g_embr + (size_t)row * D + t * 4) = q;
    float s = v.x * v.x + v.y * v.y + v.z * v.z + v.w * v.w;
    #pragma unroll
    for (int o = 16; o > 0; o >>= 1) s += __shfl_down_sync(0xffffffffu, s, o);
    __shared__ float red[4];
    if ((t & 31) == 0) red[t >> 5] = s;
    __syncthreads();
    if (t == 0) g_sq[row] = red[0] + red[1] + red[2] + red[3];
}

// ---------------- K2: tf32 mma.sync distance GEMM (symmetric) --------------
#define BM 128
#define BN 256
#define BKC 32
#define NCHUNK (D / BKC)   // 16
#define NTILES 1056
#define GEMM_SPLIT 888

#define SM_SQJ   0
#define SM_SQI   1024
#define SM_STAGE 2048
#define STAGE_BYTES 49152                   // A 16KB + B 32KB
#define SM_TOTAL (SM_STAGE + 3 * STAGE_BYTES)

static __device__ __forceinline__ uint32_t sw128(uint32_t b) { return b ^ ((b >> 3) & 0x70); }

__global__ __launch_bounds__(256, 1)
void dist_gemm_mma_kernel(int tile_base) {
    extern __shared__ char smem[];
    const uint32_t sbase = smem_u32(smem);
    const int t    = threadIdx.x;
    const int wid  = t >> 5;
    const int lane = t & 31;
    const int g    = lane >> 2;
    const int tq   = lane & 3;
    const int warpM = (wid >> 2) * 64;
    const int warpN = (wid & 3) * 64;

    int flat = tile_base + blockIdx.x;
    int bi = 0, cnt = 32;
    while (flat >= cnt) { flat -= cnt; ++bi; cnt = 32 - (bi >> 1); }
    const int bj = (bi >> 1) + flat;
    const int rowA0 = bi * BM;
    const int colB0 = bj * BN;

    *(float*)(smem + SM_SQJ + t * 4) = g_sq[colB0 + t];
    if (t < 128) *(float*)(smem + SM_SQI + t * 4) = g_sq[rowA0 + t];

    const uint32_t laneRowA = (lane & 7) + ((lane >> 3) & 1) * 8;
    const uint32_t laneColA = (lane >> 4) * 16;
    const uint32_t laneRowB = lane & 7;
    const uint32_t laneColB = ((lane >> 3) & 1) * 16;

    auto issue_chunk = [&](int kt, int stg) {
        const int kc = kt * BKC;
        const uint32_t sb = sbase + SM_STAGE + (uint32_t)stg * STAGE_BYTES;
        #pragma unroll
        for (int l = 0; l < 12; l++) {
            int idx = t + l * 256;
            int r   = idx >> 3;
            int c4  = idx & 7;
            int isA = (r < 128);
            int grow = isA ? (rowA0 + r) : (colB0 + r - 128);
            const float* src = g_embr + (size_t)grow * D + kc + c4 * 4;
            uint32_t off = (isA ? 0u : 16384u) +
                           sw128((uint32_t)(isA ? r : r - 128) * 128u + (uint32_t)c4 * 16u);
            CP_ASYNC16(sb + off, src);
        }
        CP_COMMIT();
    };

    float acc[4][8][4];
    #pragma unroll
    for (int mt = 0; mt < 4; mt++)
        #pragma unroll
        for (int nt = 0; nt < 8; nt++)
            #pragma unroll
            for (int q = 0; q < 4; q++) acc[mt][nt][q] = 0.f;

    issue_chunk(0, 0);
    issue_chunk(1, 1);

    #pragma unroll 1
    for (int kt = 0; kt < NCHUNK; kt++) {
        const int stg = kt % 3;
        CP_WAIT(1);
        __syncthreads();
        if (kt + 2 < NCHUNK) issue_chunk(kt + 2, (kt + 2) % 3);

        const uint32_t abase = sbase + SM_STAGE + (uint32_t)stg * STAGE_BYTES;
        const uint32_t bbase = abase + 16384u;
        #pragma unroll
        for (int ks = 0; ks < 4; ks++) {
            uint32_t af[4][4], bf[8][2];
            #pragma unroll
            for (int mt = 0; mt < 4; mt++) {
                uint32_t byte = (uint32_t)(warpM + mt * 16 + laneRowA) * 128u +
                                (uint32_t)ks * 32u + laneColA;
                ldsm_x4(af[mt], abase + sw128(byte));
            }
            #pragma unroll
            for (int nt = 0; nt < 8; nt++) {
                uint32_t byte = (uint32_t)(warpN + nt * 8 + laneRowB) * 128u +
                                (uint32_t)ks * 32u + laneColB;
                ldsm_x2(bf[nt], bbase + sw128(byte));
            }
            #pragma unroll
            for (int mt = 0; mt < 4; mt++)
                #pragma unroll
                for (int nt = 0; nt < 8; nt++)
                    mma_tf32(acc[mt][nt], af[mt], bf[nt]);
        }
        __syncthreads();
    }

    const float* sqj = (const float*)(smem + SM_SQJ);
    const float* sqi = (const float*)(smem + SM_SQI);
    #pragma unroll
    for (int mt = 0; mt < 4; mt++) {
        const int r0 = warpM + mt * 16 + g;
        const int r1 = r0 + 8;
        const int gr0 = rowA0 + r0, gr1 = rowA0 + r1;
        const float si0 = sqi[r0], si1 = sqi[r1];
        #pragma unroll
        for (int nt = 0; nt < 8; nt++) {
            const int cl = warpN + nt * 8 + tq * 2;
            const int gc = colB0 + cl;
            const float sj0 = sqj[cl], sj1 = sqj[cl + 1];
            float d2;
            float2 o0, o1;
            d2 = si0 + sj0 - 2.f * acc[mt][nt][0];
            o0.x = (d2 > 0.f) ? sqrtf(fmaxf(d2, 1e-12f)) : 0.f;
            d2 = si0 + sj1 - 2.f * acc[mt][nt][1];
            o0.y = (d2 > 0.f) ? sqrtf(fmaxf(d2, 1e-12f)) : 0.f;
            d2 = si1 + sj0 - 2.f * acc[mt][nt][2];
            o1.x = (d2 > 0.f) ? sqrtf(fmaxf(d2, 1e-12f)) : 0.f;
            d2 = si1 + sj1 - 2.f * acc[mt][nt][3];
            o1.y = (d2 > 0.f) ? sqrtf(fmaxf(d2, 1e-12f)) : 0.f;
            *(float2*)(g_dist + (size_t)gr0 * N + gc) = o0;
            *(float2*)(g_dist + (size_t)gr1 * N + gc) = o1;
            g_dist[(size_t)gc * N + gr0]       = o0.x;
            g_dist[(size_t)gc * N + gr1]       = o1.x;
            g_dist[(size_t)(gc + 1) * N + gr0] = o0.y;
            g_dist[(size_t)(gc + 1) * N + gr1] = o1.y;
        }
    }
}

// ---------------- K3: block-per-row top-16, two-pass threshold filter ------
// Pass 1: per-thread min of its 32 elements (branchless). T = 16th smallest
// of the 256 minima — provable upper bound on the row's 16th smallest
// (the 16 smallest minima are 16 distinct elements <= T). Pass 2: rescan
// (L2-resident row) keeping only dv <= T into per-thread exact top-16
// (insert rate ~0). Survivors -> compact smem buffer -> 16 extraction rounds
// with order-independent key (val_bits<<32 | col) => deterministic.
__global__ __launch_bounds__(256)
void topk_kernel() {
    const int i    = blockIdx.x;
    const int t    = threadIdx.x;
    const int lane = t & 31;
    const int w    = t >> 5;
    const float4* __restrict__ row4 = (const float4*)(g_dist + (size_t)i * N);

    // ---- pass 1: per-thread min (self excluded)
    float m = FLT_MAX;
    #pragma unroll
    for (int b = 0; b < 8; b++) {
        const int idx4 = b * 256 + t;
        float4 q = row4[idx4];
        const int j0 = idx4 * 4;
        if ((unsigned)(i - j0) < 4u) ((float*)&q)[i - j0] = FLT_MAX;
        m = fminf(m, fminf(fminf(q.x, q.y), fminf(q.z, q.w)));
    }

    // ---- T = 16th smallest of 256 minima (16 extraction rounds)
    __shared__ unsigned long long wm[2][8];
    unsigned long long cur =
        ((unsigned long long)__float_as_uint(m) << 32) | (unsigned)t;
    float T = 0.f;
    #pragma unroll 1
    for (int r = 0; r < KNN; r++) {
        unsigned long long k2 = cur;
        #pragma unroll
        for (int o = 16; o > 0; o >>= 1) {
            unsigned long long other = __shfl_xor_sync(0xffffffffu, k2, o);
            k2 = (other < k2) ? other : k2;
        }
        if (lane == 0) wm[r & 1][w] = k2;
        __syncthreads();
        unsigned long long bmin = wm[r & 1][0];
        #pragma unroll
        for (int q = 1; q < 8; q++) {
            unsigned long long x = wm[r & 1][q];
            bmin = (x < bmin) ? x : bmin;
        }
        if (cur == bmin) cur = ~0ULL;          // extract (keys unique by t)
        T = __uint_as_float((uint32_t)(bmin >> 32));
    }

    // ---- pass 2: filtered rescan, per-thread exact top-16
    float v[KNN]; int id[KNN];
    #pragma unroll
    for (int u = 0; u < KNN; u++) { v[u] = FLT_MAX; id[u] = -1; }
    float vmax = FLT_MAX; int pmax = 0;
    #pragma unroll
    for (int b = 0; b < 8; b++) {
        const int idx4 = b * 256 + t;
        float4 q = row4[idx4];
        const int j0 = idx4 * 4;
        if ((unsigned)(i - j0) < 4u) ((float*)&q)[i - j0] = FLT_MAX;
        #pragma unroll
        for (int c = 0; c < 4; c++) {
            const float dv = ((float*)&q)[c];
            if (dv <= T && dv < vmax) {
                #pragma unroll
                for (int uu = 0; uu < KNN; uu++)
                    if (uu == pmax) { v[uu] = dv; id[uu] = j0 + c; }
                float mm = -1.f; int p = 0;
                #pragma unroll
                for (int uu = 0; uu < KNN; uu++)
                    if (v[uu] > mm) { mm = v[uu]; p = uu; }
                vmax = mm; pmax = p;
            }
        }
    }

    // ---- compact survivors
    __shared__ float bufv[4096];
    __shared__ int   bufi[4096];
    __shared__ int   s_cnt;
    if (t == 0) s_cnt = 0;
    __syncthreads();
    #pragma unroll
    for (int u = 0; u < KNN; u++) {
        if (v[u] <= T) {
            int e = atomicAdd(&s_cnt, 1);
            bufv[e] = v[u]; bufi[e] = id[u];
        }
    }
    __syncthreads();
    const int n_e = s_cnt;                      // >= 16 guaranteed

    // ---- merge: 16 extraction rounds, deterministic key (val, col)
    #pragma unroll 1
    for (int r = 0; r < KNN; r++) {
        unsigned long long best = ~0ULL;
        for (int e = t; e < n_e; e += 256) {
            unsigned long long k =
                ((unsigned long long)__float_as_uint(bufv[e]) << 32) | (unsigned)bufi[e];
            best = (k < best) ? k : best;
        }
        #pragma unroll
        for (int o = 16; o > 0; o >>= 1) {
            unsigned long long other = __shfl_xor_sync(0xffffffffu, best, o);
            best = (other < best) ? other : best;
        }
        if (lane == 0) wm[r & 1][w] = best;
        __syncthreads();
        unsigned long long bmin = wm[r & 1][0];
        #pragma unroll
        for (int q = 1; q < 8; q++) {
            unsigned long long x = wm[r & 1][q];
            bmin = (x < bmin) ? x : bmin;
        }
        if (t == 0) {
            g_knn_d[i * KNN + r]   = __uint_as_float((uint32_t)(bmin >> 32));
            g_knn_idx[i * KNN + r] = (int)(bmin & 0xffffffffu);
        }
        // mark extracted entry
        for (int e = t; e < n_e; e += 256) {
            unsigned long long k =
                ((unsigned long long)__float_as_uint(bufv[e]) << 32) | (unsigned)bufi[e];
            if (k == bmin) bufv[e] = FLT_MAX;
        }
        __syncthreads();
    }
}

// ---------------- K4: curvature per point ----------------------------------
__global__ __launch_bounds__(256)
void curvature_kernel(const float* __restrict__ ref_curv) {
    const int i = blockIdx.x;
    const int t = threadIdx.x;
    __shared__ int   nidx[KNN];
    __shared__ float nd[KNN];
    if (t < KNN) { nidx[t] = g_knn_idx[i * KNN + t]; nd[t] = g_knn_d[i * KNN + t]; }
    __syncthreads();

    int j = t >> 4, k = t & 15;
    float inter = 0.f;
    if (j < k) inter = g_dist[(size_t)nidx[j] * N + nidx[k]];
    float dsum = (t < KNN) ? nd[t] : 0.f;

    __shared__ float r1[256], r2[256];
    r1[t] = inter; r2[t] = dsum;
    __syncthreads();
    for (int s = 128; s > 0; s >>= 1) {
        if (t < s) { r1[t] += r1[t + s]; r2[t] += r2[t + s]; }
        __syncthreads();
    }
    if (t == 0) {
        float avg        = r2[0] / (float)KNN;
        float inter_mean = r1[0] / (float)NPAIRS;
        float curv       = inter_mean / (avg + 1e-8f);
        float diff       = curv - ref_curv[i];
        g_curv_err[i] = diff * diff;
        g_knn_sum[i]  = r2[0];
    }
}

// ---------------- K5: final scalar (fp64 accumulation, deterministic) ------
__global__ void final_kernel(const float* __restrict__ ref_dist, float* __restrict__ out) {
    const int t = threadIdx.x;
    double s_err = 0.0, s_knn = 0.0, s_ref = 0.0;
    for (int i = t; i < N; i += 256) { s_err += (double)g_curv_err[i]; s_knn += (double)g_knn_sum[i]; }
    for (int i = t; i < N * KNN; i += 256) s_ref += (double)ref_dist[i];
    __shared__ double d1[256], d2[256], d3[256];
    d1[t] = s_err; d2[t] = s_knn; d3[t] = s_ref;
    __syncthreads();
    for (int s = 128; s > 0; s >>= 1) {
        if (t < s) { d1[t] += d1[t + s]; d2[t] += d2[t + s]; d3[t] += d3[t + s]; }
        __syncthreads();
    }
    if (t == 0) {
        double curv_loss = d1[0] / (double)N;
        double m_knn = d2[0] / (double)(N * KNN);
        double m_ref = d3[0] / (double)(N * KNN);
        double diff  = m_knn - m_ref;
        out[0] = (float)(curv_loss + 0.1 * diff * diff);
    }
}

// ---------------- launch ----------------------------------------------------
extern "C" void kernel_launch(void* const* d_in, const int* in_sizes, int n_in,
                              void* d_out, int out_size) {
    const float* emb      = (const float*)d_in[0];   // [N, D]
    const float* ref_curv = (const float*)d_in[1];   // [N]
    const float* ref_dist = (const float*)d_in[2];   // [N, K]
    float* out = (float*)d_out;

    static int smem_set = 0;
    if (!smem_set) {
        cudaFuncSetAttribute(dist_gemm_mma_kernel,
                             cudaFuncAttributeMaxDynamicSharedMemorySize, SM_TOTAL);
        smem_set = 1;
    }

    row_norms_kernel<<<N, 128>>>(emb);
    dist_gemm_mma_kernel<<<GEMM_SPLIT, 256, SM_TOTAL>>>(0);
    dist_gemm_mma_kernel<<<NTILES - GEMM_SPLIT, 256, SM_TOTAL>>>(GEMM_SPLIT);
    topk_kernel<<<N, 256>>>();
    curvature_kernel<<<N, 256>>>(ref_curv);
    final_kernel<<<1, 256>>>(ref_dist, out);
}

// round 10
// speedup vs baseline: 2.3496x; 1.5838x over previous
#include <cuda_runtime.h>
#include <math.h>
#include <float.h>
#include <stdint.h>

#define N 8192
#define D 512
#define KNN 16
#define NPAIRS 120   // 16*15/2

// ---------------- scratch (device globals; no runtime allocation) ----------
__device__ float g_sq[N];
__device__ float g_embr[(size_t)N * D];     // tf32-rounded (rna) copy of embeddings
__device__ float g_dist[(size_t)N * N];     // 256 MB full symmetric distance matrix
__device__ float g_segmin[(size_t)N * 128]; // per-row min over 64-col segments
__device__ int   g_knn_idx[N * KNN];
__device__ float g_knn_d[N * KNN];
__device__ float g_curv_err[N];
__device__ float g_knn_sum[N];

// ---------------- PTX helpers ----------------------------------------------
__device__ __forceinline__ uint32_t smem_u32(const void* p) {
    uint32_t a;
    asm("{ .reg .u64 t; cvta.to.shared.u64 t, %1; cvt.u32.u64 %0, t; }" : "=r"(a) : "l"(p));
    return a;
}
__device__ __forceinline__ uint32_t f2tf32(float v) {
    uint32_t o;
    asm("cvt.rna.tf32.f32 %0, %1;" : "=r"(o) : "f"(v));
    return o;
}
#define CP_ASYNC16(dst, src) \
    asm volatile("cp.async.cg.shared.global [%0], [%1], 16;" :: "r"(dst), "l"(src))
#define CP_COMMIT() asm volatile("cp.async.commit_group;" ::: "memory")
#define CP_WAIT(n)  asm volatile("cp.async.wait_group %0;" :: "n"(n) : "memory")

__device__ __forceinline__ void ldsm_x4(uint32_t* r, uint32_t addr) {
    asm volatile("ldmatrix.sync.aligned.m8n8.x4.shared.b16 {%0,%1,%2,%3}, [%4];"
                 : "=r"(r[0]), "=r"(r[1]), "=r"(r[2]), "=r"(r[3]) : "r"(addr));
}
__device__ __forceinline__ void ldsm_x2(uint32_t* r, uint32_t addr) {
    asm volatile("ldmatrix.sync.aligned.m8n8.x2.shared.b16 {%0,%1}, [%2];"
                 : "=r"(r[0]), "=r"(r[1]) : "r"(addr));
}
__device__ __forceinline__ void mma_tf32(float* c, const uint32_t* a, const uint32_t* b) {
    asm volatile(
        "mma.sync.aligned.m16n8k8.row.col.f32.tf32.tf32.f32 "
        "{%0,%1,%2,%3}, {%4,%5,%6,%7}, {%8,%9}, {%0,%1,%2,%3};"
        : "+f"(c[0]), "+f"(c[1]), "+f"(c[2]), "+f"(c[3])
        : "r"(a[0]), "r"(a[1]), "r"(a[2]), "r"(a[3]), "r"(b[0]), "r"(b[1]));
}

// ---------------- K1: row squared norms + tf32-rounded copy ----------------
__global__ void row_norms_kernel(const float* __restrict__ A) {
    int row = blockIdx.x;
    int t = threadIdx.x;                         // 128 threads, D/4 = 128
    const float4* a4 = (const float4*)(A + (size_t)row * D);
    float4 v = a4[t];
    uint4 q;
    q.x = f2tf32(v.x); q.y = f2tf32(v.y); q.z = f2tf32(v.z); q.w = f2tf32(v.w);
    *(uint4*)(g_embr + (size_t)row * D + t * 4) = q;
    float s = v.x * v.x + v.y * v.y + v.z * v.z + v.w * v.w;
    #pragma unroll
    for (int o = 16; o > 0; o >>= 1) s += __shfl_down_sync(0xffffffffu, s, o);
    __shared__ float red[4];
    if ((t & 31) == 0) red[t >> 5] = s;
    __syncthreads();
    if (t == 0) g_sq[row] = red[0] + red[1] + red[2] + red[3];
}

// ---------------- K2: tf32 mma.sync distance GEMM (symmetric) --------------
#define BM 128
#define BN 256
#define BKC 32
#define NCHUNK (D / BKC)   // 16
#define NTILES 1056
#define GEMM_SPLIT 888

#define SM_SQJ   0
#define SM_SQI   1024
#define SM_STAGE 2048
#define STAGE_BYTES 49152                   // A 16KB + B 32KB
#define SM_TOTAL (SM_STAGE + 3 * STAGE_BYTES)

static __device__ __forceinline__ uint32_t sw128(uint32_t b) { return b ^ ((b >> 3) & 0x70); }

__global__ __launch_bounds__(256, 1)
void dist_gemm_mma_kernel(int tile_base) {
    extern __shared__ char smem[];
    const uint32_t sbase = smem_u32(smem);
    const int t    = threadIdx.x;
    const int wid  = t >> 5;
    const int lane = t & 31;
    const int g    = lane >> 2;
    const int tq   = lane & 3;
    const int warpM = (wid >> 2) * 64;
    const int warpN = (wid & 3) * 64;

    int flat = tile_base + blockIdx.x;
    int bi = 0, cnt = 32;
    while (flat >= cnt) { flat -= cnt; ++bi; cnt = 32 - (bi >> 1); }
    const int bj = (bi >> 1) + flat;
    const int rowA0 = bi * BM;
    const int colB0 = bj * BN;

    *(float*)(smem + SM_SQJ + t * 4) = g_sq[colB0 + t];
    if (t < 128) *(float*)(smem + SM_SQI + t * 4) = g_sq[rowA0 + t];

    const uint32_t laneRowA = (lane & 7) + ((lane >> 3) & 1) * 8;
    const uint32_t laneColA = (lane >> 4) * 16;
    const uint32_t laneRowB = lane & 7;
    const uint32_t laneColB = ((lane >> 3) & 1) * 16;

    auto issue_chunk = [&](int kt, int stg) {
        const int kc = kt * BKC;
        const uint32_t sb = sbase + SM_STAGE + (uint32_t)stg * STAGE_BYTES;
        #pragma unroll
        for (int l = 0; l < 12; l++) {
            int idx = t + l * 256;
            int r   = idx >> 3;
            int c4  = idx & 7;
            int isA = (r < 128);
            int grow = isA ? (rowA0 + r) : (colB0 + r - 128);
            const float* src = g_embr + (size_t)grow * D + kc + c4 * 4;
            uint32_t off = (isA ? 0u : 16384u) +
                           sw128((uint32_t)(isA ? r : r - 128) * 128u + (uint32_t)c4 * 16u);
            CP_ASYNC16(sb + off, src);
        }
        CP_COMMIT();
    };

    float acc[4][8][4];
    #pragma unroll
    for (int mt = 0; mt < 4; mt++)
        #pragma unroll
        for (int nt = 0; nt < 8; nt++)
            #pragma unroll
            for (int q = 0; q < 4; q++) acc[mt][nt][q] = 0.f;

    issue_chunk(0, 0);
    issue_chunk(1, 1);

    #pragma unroll 1
    for (int kt = 0; kt < NCHUNK; kt++) {
        const int stg = kt % 3;
        CP_WAIT(1);
        __syncthreads();
        if (kt + 2 < NCHUNK) issue_chunk(kt + 2, (kt + 2) % 3);

        const uint32_t abase = sbase + SM_STAGE + (uint32_t)stg * STAGE_BYTES;
        const uint32_t bbase = abase + 16384u;
        #pragma unroll
        for (int ks = 0; ks < 4; ks++) {
            uint32_t af[4][4], bf[8][2];
            #pragma unroll
            for (int mt = 0; mt < 4; mt++) {
                uint32_t byte = (uint32_t)(warpM + mt * 16 + laneRowA) * 128u +
                                (uint32_t)ks * 32u + laneColA;
                ldsm_x4(af[mt], abase + sw128(byte));
            }
            #pragma unroll
            for (int nt = 0; nt < 8; nt++) {
                uint32_t byte = (uint32_t)(warpN + nt * 8 + laneRowB) * 128u +
                                (uint32_t)ks * 32u + laneColB;
                ldsm_x2(bf[nt], bbase + sw128(byte));
            }
            #pragma unroll
            for (int mt = 0; mt < 4; mt++)
                #pragma unroll
                for (int nt = 0; nt < 8; nt++)
                    mma_tf32(acc[mt][nt], af[mt], bf[nt]);
        }
        __syncthreads();
    }

    // ---- epilogue: distances; direct + mirror stores + segment mins -------
    const float* sqj = (const float*)(smem + SM_SQJ);
    const float* sqi = (const float*)(smem + SM_SQI);
    float rmin[4][2];                       // per-row mins over warp's 64 cols
    float cmin[8][2];                       // per-col mins over warp's 64 rows
    #pragma unroll
    for (int mt = 0; mt < 4; mt++) { rmin[mt][0] = FLT_MAX; rmin[mt][1] = FLT_MAX; }
    #pragma unroll
    for (int nt = 0; nt < 8; nt++) { cmin[nt][0] = FLT_MAX; cmin[nt][1] = FLT_MAX; }

    #pragma unroll
    for (int mt = 0; mt < 4; mt++) {
        const int r0 = warpM + mt * 16 + g;
        const int r1 = r0 + 8;
        const int gr0 = rowA0 + r0, gr1 = rowA0 + r1;
        const float si0 = sqi[r0], si1 = sqi[r1];
        #pragma unroll
        for (int nt = 0; nt < 8; nt++) {
            const int cl = warpN + nt * 8 + tq * 2;
            const int gc = colB0 + cl;
            const float sj0 = sqj[cl], sj1 = sqj[cl + 1];
            float d2;
            float2 o0, o1;
            d2 = si0 + sj0 - 2.f * acc[mt][nt][0];
            o0.x = (d2 > 0.f) ? sqrtf(fmaxf(d2, 1e-12f)) : 0.f;
            d2 = si0 + sj1 - 2.f * acc[mt][nt][1];
            o0.y = (d2 > 0.f) ? sqrtf(fmaxf(d2, 1e-12f)) : 0.f;
            d2 = si1 + sj0 - 2.f * acc[mt][nt][2];
            o1.x = (d2 > 0.f) ? sqrtf(fmaxf(d2, 1e-12f)) : 0.f;
            d2 = si1 + sj1 - 2.f * acc[mt][nt][3];
            o1.y = (d2 > 0.f) ? sqrtf(fmaxf(d2, 1e-12f)) : 0.f;
            *(float2*)(g_dist + (size_t)gr0 * N + gc) = o0;
            *(float2*)(g_dist + (size_t)gr1 * N + gc) = o1;
            g_dist[(size_t)gc * N + gr0]       = o0.x;
            g_dist[(size_t)gc * N + gr1]       = o1.x;
            g_dist[(size_t)(gc + 1) * N + gr0] = o0.y;
            g_dist[(size_t)(gc + 1) * N + gr1] = o1.y;
            rmin[mt][0] = fminf(rmin[mt][0], fminf(o0.x, o0.y));
            rmin[mt][1] = fminf(rmin[mt][1], fminf(o1.x, o1.y));
            cmin[nt][0] = fminf(cmin[nt][0], fminf(o0.x, o1.x));
            cmin[nt][1] = fminf(cmin[nt][1], fminf(o0.y, o1.y));
        }
    }

    // row segment mins: reduce over tq lanes (same g)
    const int rseg = bj * 4 + (wid & 3);
    #pragma unroll
    for (int mt = 0; mt < 4; mt++) {
        #pragma unroll
        for (int h = 0; h < 2; h++) {
            float x = rmin[mt][h];
            x = fminf(x, __shfl_xor_sync(0xffffffffu, x, 1));
            x = fminf(x, __shfl_xor_sync(0xffffffffu, x, 2));
            if (tq == 0) {
                const int gr = rowA0 + warpM + mt * 16 + g + h * 8;
                g_segmin[(size_t)gr * 128 + rseg] = x;
            }
        }
    }
    // col segment mins: reduce over g lanes (same tq)
    const int cseg = bi * 2 + (wid >> 2);
    #pragma unroll
    for (int nt = 0; nt < 8; nt++) {
        #pragma unroll
        for (int p = 0; p < 2; p++) {
            float x = cmin[nt][p];
            x = fminf(x, __shfl_xor_sync(0xffffffffu, x, 4));
            x = fminf(x, __shfl_xor_sync(0xffffffffu, x, 8));
            x = fminf(x, __shfl_xor_sync(0xffffffffu, x, 16));
            if (g == 0) {
                const int gc = colB0 + warpN + nt * 8 + tq * 2 + p;
                g_segmin[(size_t)gc * 128 + cseg] = x;
            }
        }
    }
}

// ---------------- K3: segment-pruned top-16 --------------------------------
// T = max over 4 warps of (warp's 5th-smallest segmin) -> >=20 distinct row
// elements <= T -> >=19 non-self -> provable bound on 16th neighbor.
// Scan only segments with segmin <= T; survivors -> rank selection with
// deterministic key (val_bits<<32 | col).
__global__ __launch_bounds__(256)
void topk_kernel() {
    const int i    = blockIdx.x;
    const int t    = threadIdx.x;
    const int lane = t & 31;
    const int w    = t >> 5;

    __shared__ float warp5[4];
    __shared__ float s_T;
    __shared__ int   segs[128];
    __shared__ int   s_scnt;
    __shared__ float bufv[2048];
    __shared__ int   bufi[2048];
    __shared__ int   s_bcnt;

    if (t == 0) { s_scnt = 0; s_bcnt = 0; }

    const float sv = (t < 128) ? g_segmin[(size_t)i * 128 + t] : FLT_MAX;

    // warps 0..3: extract own 5th-smallest (keyed, duplicate-safe)
    if (w < 4) {
        unsigned long long key =
            ((unsigned long long)__float_as_uint(sv) << 32) | (unsigned)t;
        float fifth = FLT_MAX;
        #pragma unroll
        for (int r = 0; r < 5; r++) {
            unsigned long long k2 = key;
            #pragma unroll
            for (int o = 16; o > 0; o >>= 1) {
                unsigned long long other = __shfl_xor_sync(0xffffffffu, k2, o);
                k2 = (other < k2) ? other : k2;
            }
            if (key == k2) key = ~0ULL;
            fifth = __uint_as_float((uint32_t)(k2 >> 32));
        }
        if (lane == 0) warp5[w] = fifth;
    }
    __syncthreads();
    if (t == 0) {
        s_T = fmaxf(fmaxf(warp5[0], warp5[1]), fmaxf(warp5[2], warp5[3]));
    }
    __syncthreads();
    const float T = s_T;

    // gather qualifying segments
    if (t < 128 && sv <= T) {
        int e = atomicAdd(&s_scnt, 1);
        segs[e] = t;
    }
    __syncthreads();
    const int nseg = s_scnt;

    // scan qualifying segments, collect survivors
    const float* __restrict__ drow = g_dist + (size_t)i * N;
    const int total = nseg * 64;
    for (int e = t; e < total; e += 256) {
        const int j = (segs[e >> 6] << 6) | (e & 63);
        const float dv = drow[j];
        if (dv <= T && j != i) {
            int b = atomicAdd(&s_bcnt, 1);
            if (b < 2048) { bufv[b] = dv; bufi[b] = j; }
        }
    }
    __syncthreads();
    const int n_e = (s_bcnt < 2048) ? s_bcnt : 2048;

    // rank selection (keys unique by col; ascending ties by col like lax.top_k)
    for (int e = t; e < n_e; e += 256) {
        const unsigned long long mykey =
            ((unsigned long long)__float_as_uint(bufv[e]) << 32) | (unsigned)bufi[e];
        int rank = 0;
        for (int q = 0; q < n_e; q++) {
            const unsigned long long k =
                ((unsigned long long)__float_as_uint(bufv[q]) << 32) | (unsigned)bufi[q];
            rank += (k < mykey);
        }
        if (rank < KNN) {
            g_knn_d[i * KNN + rank]   = bufv[e];
            g_knn_idx[i * KNN + rank] = bufi[e];
        }
    }
}

// ---------------- K4: curvature per point ----------------------------------
__global__ __launch_bounds__(256)
void curvature_kernel(const float* __restrict__ ref_curv) {
    const int i = blockIdx.x;
    const int t = threadIdx.x;
    __shared__ int   nidx[KNN];
    __shared__ float nd[KNN];
    if (t < KNN) { nidx[t] = g_knn_idx[i * KNN + t]; nd[t] = g_knn_d[i * KNN + t]; }
    __syncthreads();

    int j = t >> 4, k = t & 15;
    float inter = 0.f;
    if (j < k) inter = g_dist[(size_t)nidx[j] * N + nidx[k]];
    float dsum = (t < KNN) ? nd[t] : 0.f;

    __shared__ float r1[256], r2[256];
    r1[t] = inter; r2[t] = dsum;
    __syncthreads();
    for (int s = 128; s > 0; s >>= 1) {
        if (t < s) { r1[t] += r1[t + s]; r2[t] += r2[t + s]; }
        __syncthreads();
    }
    if (t == 0) {
        float avg        = r2[0] / (float)KNN;
        float inter_mean = r1[0] / (float)NPAIRS;
        float curv       = inter_mean / (avg + 1e-8f);
        float diff       = curv - ref_curv[i];
        g_curv_err[i] = diff * diff;
        g_knn_sum[i]  = r2[0];
    }
}

// ---------------- K5: final scalar (fp64 accumulation, deterministic) ------
__global__ void final_kernel(const float* __restrict__ ref_dist, float* __restrict__ out) {
    const int t = threadIdx.x;
    double s_err = 0.0, s_knn = 0.0, s_ref = 0.0;
    for (int i = t; i < N; i += 256) { s_err += (double)g_curv_err[i]; s_knn += (double)g_knn_sum[i]; }
    for (int i = t; i < N * KNN; i += 256) s_ref += (double)ref_dist[i];
    __shared__ double d1[256], d2[256], d3[256];
    d1[t] = s_err; d2[t] = s_knn; d3[t] = s_ref;
    __syncthreads();
    for (int s = 128; s > 0; s >>= 1) {
        if (t < s) { d1[t] += d1[t + s]; d2[t] += d2[t + s]; d3[t] += d3[t + s]; }
        __syncthreads();
    }
    if (t == 0) {
        double curv_loss = d1[0] / (double)N;
        double m_knn = d2[0] / (double)(N * KNN);
        double m_ref = d3[0] / (double)(N * KNN);
        double diff  = m_knn - m_ref;
        out[0] = (float)(curv_loss + 0.1 * diff * diff);
    }
}

// ---------------- launch ----------------------------------------------------
extern "C" void kernel_launch(void* const* d_in, const int* in_sizes, int n_in,
                              void* d_out, int out_size) {
    const float* emb      = (const float*)d_in[0];   // [N, D]
    const float* ref_curv = (const float*)d_in[1];   // [N]
    const float* ref_dist = (const float*)d_in[2];   // [N, K]
    float* out = (float*)d_out;

    static int smem_set = 0;
    if (!smem_set) {
        cudaFuncSetAttribute(dist_gemm_mma_kernel,
                             cudaFuncAttributeMaxDynamicSharedMemorySize, SM_TOTAL);
        smem_set = 1;
    }

    row_norms_kernel<<<N, 128>>>(emb);
    dist_gemm_mma_kernel<<<GEMM_SPLIT, 256, SM_TOTAL>>>(0);
    dist_gemm_mma_kernel<<<NTILES - GEMM_SPLIT, 256, SM_TOTAL>>>(GEMM_SPLIT);
    topk_kernel<<<N, 256>>>();
    curvature_kernel<<<N, 256>>>(ref_curv);
    final_kernel<<<1, 256>>>(ref_dist, out);
}

// round 11
// speedup vs baseline: 2.9103x; 1.2386x over previous
#include <cuda_runtime.h>
#include <cuda_fp16.h>
#include <math.h>
#include <float.h>
#include <stdint.h>

#define N 8192
#define D 512
#define KNN 16
#define NPAIRS 120   // 16*15/2

// ---------------- scratch (device globals; no runtime allocation) ----------
__device__ float  g_sq[N];
__device__ __half g_embh[(size_t)N * D];    // fp16 (rn) copy of embeddings
__device__ float  g_dist[(size_t)N * N];    // 256 MB full symmetric distance matrix
__device__ float  g_segmin[(size_t)N * 128];// per-row min over 64-col segments
__device__ int    g_knn_idx[N * KNN];
__device__ float  g_knn_d[N * KNN];
__device__ float  g_curv_err[N];
__device__ float  g_knn_sum[N];

// ---------------- PTX helpers ----------------------------------------------
__device__ __forceinline__ uint32_t smem_u32(const void* p) {
    uint32_t a;
    asm("{ .reg .u64 t; cvta.to.shared.u64 t, %1; cvt.u32.u64 %0, t; }" : "=r"(a) : "l"(p));
    return a;
}
#define CP_ASYNC16(dst, src) \
    asm volatile("cp.async.cg.shared.global [%0], [%1], 16;" :: "r"(dst), "l"(src))
#define CP_COMMIT() asm volatile("cp.async.commit_group;" ::: "memory")
#define CP_WAIT(n)  asm volatile("cp.async.wait_group %0;" :: "n"(n) : "memory")

__device__ __forceinline__ void ldsm_x4(uint32_t* r, uint32_t addr) {
    asm volatile("ldmatrix.sync.aligned.m8n8.x4.shared.b16 {%0,%1,%2,%3}, [%4];"
                 : "=r"(r[0]), "=r"(r[1]), "=r"(r[2]), "=r"(r[3]) : "r"(addr));
}
__device__ __forceinline__ void ldsm_x2(uint32_t* r, uint32_t addr) {
    asm volatile("ldmatrix.sync.aligned.m8n8.x2.shared.b16 {%0,%1}, [%2];"
                 : "=r"(r[0]), "=r"(r[1]) : "r"(addr));
}
__device__ __forceinline__ void mma_f16(float* c, const uint32_t* a, const uint32_t* b) {
    asm volatile(
        "mma.sync.aligned.m16n8k16.row.col.f32.f16.f16.f32 "
        "{%0,%1,%2,%3}, {%4,%5,%6,%7}, {%8,%9}, {%0,%1,%2,%3};"
        : "+f"(c[0]), "+f"(c[1]), "+f"(c[2]), "+f"(c[3])
        : "r"(a[0]), "r"(a[1]), "r"(a[2]), "r"(a[3]), "r"(b[0]), "r"(b[1]));
}

// ---------------- K1: row squared norms + fp16 copy ------------------------
__global__ void row_norms_kernel(const float* __restrict__ A) {
    int row = blockIdx.x;
    int t = threadIdx.x;                         // 128 threads, D/4 = 128
    const float4* a4 = (const float4*)(A + (size_t)row * D);
    float4 v = a4[t];
    __half2 h0 = __floats2half2_rn(v.x, v.y);
    __half2 h1 = __floats2half2_rn(v.z, v.w);
    uint2 q;
    q.x = *(uint32_t*)&h0; q.y = *(uint32_t*)&h1;
    *(uint2*)(g_embh + (size_t)row * D + t * 4) = q;
    float s = v.x * v.x + v.y * v.y + v.z * v.z + v.w * v.w;
    #pragma unroll
    for (int o = 16; o > 0; o >>= 1) s += __shfl_down_sync(0xffffffffu, s, o);
    __shared__ float red[4];
    if ((t & 31) == 0) red[t >> 5] = s;
    __syncthreads();
    if (t == 0) g_sq[row] = red[0] + red[1] + red[2] + red[3];
}

// ---------------- K2: fp16 mma.sync distance GEMM (symmetric) --------------
// 128x256 upper-triangular tiles; K chunks of 64 halfs (128B SW128 rows);
// m16n8k16 f16 MMA w/ fp32 accum; 3-stage cp.async; segmin epilogue.
#define BM 128
#define BN 256
#define BKC 64
#define NCHUNK (D / BKC)   // 8
#define NTILES 1056
#define GEMM_SPLIT 888

#define SM_SQJ   0
#define SM_SQI   1024
#define SM_STAGE 2048
#define STAGE_BYTES 49152                   // A 16KB + B 32KB
#define SM_TOTAL (SM_STAGE + 3 * STAGE_BYTES)

static __device__ __forceinline__ uint32_t sw128(uint32_t b) { return b ^ ((b >> 3) & 0x70); }

__global__ __launch_bounds__(256, 1)
void dist_gemm_mma_kernel(int tile_base) {
    extern __shared__ char smem[];
    const uint32_t sbase = smem_u32(smem);
    const int t    = threadIdx.x;
    const int wid  = t >> 5;
    const int lane = t & 31;
    const int g    = lane >> 2;
    const int tq   = lane & 3;
    const int warpM = (wid >> 2) * 64;
    const int warpN = (wid & 3) * 64;

    int flat = tile_base + blockIdx.x;
    int bi = 0, cnt = 32;
    while (flat >= cnt) { flat -= cnt; ++bi; cnt = 32 - (bi >> 1); }
    const int bj = (bi >> 1) + flat;
    const int rowA0 = bi * BM;
    const int colB0 = bj * BN;

    *(float*)(smem + SM_SQJ + t * 4) = g_sq[colB0 + t];
    if (t < 128) *(float*)(smem + SM_SQI + t * 4) = g_sq[rowA0 + t];

    const uint32_t laneRowA = (lane & 7) + ((lane >> 3) & 1) * 8;
    const uint32_t laneColA = (lane >> 4) * 16;
    const uint32_t laneRowB = lane & 7;
    const uint32_t laneColB = ((lane >> 3) & 1) * 16;

    // chunk staging: 12 x 16B cp.async per thread (A:4, B:8); 16B = 8 halfs
    auto issue_chunk = [&](int kt, int stg) {
        const int kc = kt * BKC;
        const uint32_t sb = sbase + SM_STAGE + (uint32_t)stg * STAGE_BYTES;
        #pragma unroll
        for (int l = 0; l < 12; l++) {
            int idx = t + l * 256;            // 0..3071
            int r   = idx >> 3;               // 0..383
            int c4  = idx & 7;                // 16B unit within 128B row
            int isA = (r < 128);
            int grow = isA ? (rowA0 + r) : (colB0 + r - 128);
            const __half* src = g_embh + (size_t)grow * D + kc + c4 * 8;
            uint32_t off = (isA ? 0u : 16384u) +
                           sw128((uint32_t)(isA ? r : r - 128) * 128u + (uint32_t)c4 * 16u);
            CP_ASYNC16(sb + off, src);
        }
        CP_COMMIT();
    };

    float acc[4][8][4];
    #pragma unroll
    for (int mt = 0; mt < 4; mt++)
        #pragma unroll
        for (int nt = 0; nt < 8; nt++)
            #pragma unroll
            for (int q = 0; q < 4; q++) acc[mt][nt][q] = 0.f;

    issue_chunk(0, 0);
    issue_chunk(1, 1);

    #pragma unroll 1
    for (int kt = 0; kt < NCHUNK; kt++) {
        const int stg = kt % 3;
        CP_WAIT(1);
        __syncthreads();
        if (kt + 2 < NCHUNK) issue_chunk(kt + 2, (kt + 2) % 3);

        const uint32_t abase = sbase + SM_STAGE + (uint32_t)stg * STAGE_BYTES;
        const uint32_t bbase = abase + 16384u;
        #pragma unroll
        for (int ks = 0; ks < 4; ks++) {       // 4 k-steps of 16 halfs (32B)
            uint32_t af[4][4], bf[8][2];
            #pragma unroll
            for (int mt = 0; mt < 4; mt++) {
                uint32_t byte = (uint32_t)(warpM + mt * 16 + laneRowA) * 128u +
                                (uint32_t)ks * 32u + laneColA;
                ldsm_x4(af[mt], abase + sw128(byte));
            }
            #pragma unroll
            for (int nt = 0; nt < 8; nt++) {
                uint32_t byte = (uint32_t)(warpN + nt * 8 + laneRowB) * 128u +
                                (uint32_t)ks * 32u + laneColB;
                ldsm_x2(bf[nt], bbase + sw128(byte));
            }
            #pragma unroll
            for (int mt = 0; mt < 4; mt++)
                #pragma unroll
                for (int nt = 0; nt < 8; nt++)
                    mma_f16(acc[mt][nt], af[mt], bf[nt]);
        }
        __syncthreads();
    }

    // ---- epilogue: distances; direct + mirror stores + segment mins -------
    const float* sqj = (const float*)(smem + SM_SQJ);
    const float* sqi = (const float*)(smem + SM_SQI);
    float rmin[4][2];
    float cmin[8][2];
    #pragma unroll
    for (int mt = 0; mt < 4; mt++) { rmin[mt][0] = FLT_MAX; rmin[mt][1] = FLT_MAX; }
    #pragma unroll
    for (int nt = 0; nt < 8; nt++) { cmin[nt][0] = FLT_MAX; cmin[nt][1] = FLT_MAX; }

    #pragma unroll
    for (int mt = 0; mt < 4; mt++) {
        const int r0 = warpM + mt * 16 + g;
        const int r1 = r0 + 8;
        const int gr0 = rowA0 + r0, gr1 = rowA0 + r1;
        const float si0 = sqi[r0], si1 = sqi[r1];
        #pragma unroll
        for (int nt = 0; nt < 8; nt++) {
            const int cl = warpN + nt * 8 + tq * 2;
            const int gc = colB0 + cl;
            const float sj0 = sqj[cl], sj1 = sqj[cl + 1];
            float d2;
            float2 o0, o1;
            d2 = si0 + sj0 - 2.f * acc[mt][nt][0];
            o0.x = (d2 > 0.f) ? sqrtf(fmaxf(d2, 1e-12f)) : 0.f;
            d2 = si0 + sj1 - 2.f * acc[mt][nt][1];
            o0.y = (d2 > 0.f) ? sqrtf(fmaxf(d2, 1e-12f)) : 0.f;
            d2 = si1 + sj0 - 2.f * acc[mt][nt][2];
            o1.x = (d2 > 0.f) ? sqrtf(fmaxf(d2, 1e-12f)) : 0.f;
            d2 = si1 + sj1 - 2.f * acc[mt][nt][3];
            o1.y = (d2 > 0.f) ? sqrtf(fmaxf(d2, 1e-12f)) : 0.f;
            *(float2*)(g_dist + (size_t)gr0 * N + gc) = o0;
            *(float2*)(g_dist + (size_t)gr1 * N + gc) = o1;
            g_dist[(size_t)gc * N + gr0]       = o0.x;
            g_dist[(size_t)gc * N + gr1]       = o1.x;
            g_dist[(size_t)(gc + 1) * N + gr0] = o0.y;
            g_dist[(size_t)(gc + 1) * N + gr1] = o1.y;
            rmin[mt][0] = fminf(rmin[mt][0], fminf(o0.x, o0.y));
            rmin[mt][1] = fminf(rmin[mt][1], fminf(o1.x, o1.y));
            cmin[nt][0] = fminf(cmin[nt][0], fminf(o0.x, o1.x));
            cmin[nt][1] = fminf(cmin[nt][1], fminf(o0.y, o1.y));
        }
    }

    // row segment mins: reduce over tq lanes (same g)
    const int rseg = bj * 4 + (wid & 3);
    #pragma unroll
    for (int mt = 0; mt < 4; mt++) {
        #pragma unroll
        for (int h = 0; h < 2; h++) {
            float x = rmin[mt][h];
            x = fminf(x, __shfl_xor_sync(0xffffffffu, x, 1));
            x = fminf(x, __shfl_xor_sync(0xffffffffu, x, 2));
            if (tq == 0) {
                const int gr = rowA0 + warpM + mt * 16 + g + h * 8;
                g_segmin[(size_t)gr * 128 + rseg] = x;
            }
        }
    }
    // col segment mins: reduce over g lanes (same tq)
    const int cseg = bi * 2 + (wid >> 2);
    #pragma unroll
    for (int nt = 0; nt < 8; nt++) {
        #pragma unroll
        for (int p = 0; p < 2; p++) {
            float x = cmin[nt][p];
            x = fminf(x, __shfl_xor_sync(0xffffffffu, x, 4));
            x = fminf(x, __shfl_xor_sync(0xffffffffu, x, 8));
            x = fminf(x, __shfl_xor_sync(0xffffffffu, x, 16));
            if (g == 0) {
                const int gc = colB0 + warpN + nt * 8 + tq * 2 + p;
                g_segmin[(size_t)gc * 128 + cseg] = x;
            }
        }
    }
}

// ---------------- K3: segment-pruned top-16 --------------------------------
__global__ __launch_bounds__(256)
void topk_kernel() {
    const int i    = blockIdx.x;
    const int t    = threadIdx.x;
    const int lane = t & 31;
    const int w    = t >> 5;

    __shared__ float warp5[4];
    __shared__ float s_T;
    __shared__ int   segs[128];
    __shared__ int   s_scnt;
    __shared__ float bufv[2048];
    __shared__ int   bufi[2048];
    __shared__ int   s_bcnt;

    if (t == 0) { s_scnt = 0; s_bcnt = 0; }

    const float sv = (t < 128) ? g_segmin[(size_t)i * 128 + t] : FLT_MAX;

    if (w < 4) {
        unsigned long long key =
            ((unsigned long long)__float_as_uint(sv) << 32) | (unsigned)t;
        float fifth = FLT_MAX;
        #pragma unroll
        for (int r = 0; r < 5; r++) {
            unsigned long long k2 = key;
            #pragma unroll
            for (int o = 16; o > 0; o >>= 1) {
                unsigned long long other = __shfl_xor_sync(0xffffffffu, k2, o);
                k2 = (other < k2) ? other : k2;
            }
            if (key == k2) key = ~0ULL;
            fifth = __uint_as_float((uint32_t)(k2 >> 32));
        }
        if (lane == 0) warp5[w] = fifth;
    }
    __syncthreads();
    if (t == 0) {
        s_T = fmaxf(fmaxf(warp5[0], warp5[1]), fmaxf(warp5[2], warp5[3]));
    }
    __syncthreads();
    const float T = s_T;

    if (t < 128 && sv <= T) {
        int e = atomicAdd(&s_scnt, 1);
        segs[e] = t;
    }
    __syncthreads();
    const int nseg = s_scnt;

    const float* __restrict__ drow = g_dist + (size_t)i * N;
    const int total = nseg * 64;
    for (int e = t; e < total; e += 256) {
        const int j = (segs[e >> 6] << 6) | (e & 63);
        const float dv = drow[j];
        if (dv <= T && j != i) {
            int b = atomicAdd(&s_bcnt, 1);
            if (b < 2048) { bufv[b] = dv; bufi[b] = j; }
        }
    }
    __syncthreads();
    const int n_e = (s_bcnt < 2048) ? s_bcnt : 2048;

    for (int e = t; e < n_e; e += 256) {
        const unsigned long long mykey =
            ((unsigned long long)__float_as_uint(bufv[e]) << 32) | (unsigned)bufi[e];
        int rank = 0;
        for (int q = 0; q < n_e; q++) {
            const unsigned long long k =
                ((unsigned long long)__float_as_uint(bufv[q]) << 32) | (unsigned)bufi[q];
            rank += (k < mykey);
        }
        if (rank < KNN) {
            g_knn_d[i * KNN + rank]   = bufv[e];
            g_knn_idx[i * KNN + rank] = bufi[e];
        }
    }
}

// ---------------- K4: curvature per point ----------------------------------
__global__ __launch_bounds__(256)
void curvature_kernel(const float* __restrict__ ref_curv) {
    const int i = blockIdx.x;
    const int t = threadIdx.x;
    __shared__ int   nidx[KNN];
    __shared__ float nd[KNN];
    if (t < KNN) { nidx[t] = g_knn_idx[i * KNN + t]; nd[t] = g_knn_d[i * KNN + t]; }
    __syncthreads();

    int j = t >> 4, k = t & 15;
    float inter = 0.f;
    if (j < k) inter = g_dist[(size_t)nidx[j] * N + nidx[k]];
    float dsum = (t < KNN) ? nd[t] : 0.f;

    __shared__ float r1[256], r2[256];
    r1[t] = inter; r2[t] = dsum;
    __syncthreads();
    for (int s = 128; s > 0; s >>= 1) {
        if (t < s) { r1[t] += r1[t + s]; r2[t] += r2[t + s]; }
        __syncthreads();
    }
    if (t == 0) {
        float avg        = r2[0] / (float)KNN;
        float inter_mean = r1[0] / (float)NPAIRS;
        float curv       = inter_mean / (avg + 1e-8f);
        float diff       = curv - ref_curv[i];
        g_curv_err[i] = diff * diff;
        g_knn_sum[i]  = r2[0];
    }
}

// ---------------- K5: final scalar (fp64 accumulation, deterministic) ------
__global__ void final_kernel(const float* __restrict__ ref_dist, float* __restrict__ out) {
    const int t = threadIdx.x;
    double s_err = 0.0, s_knn = 0.0, s_ref = 0.0;
    for (int i = t; i < N; i += 256) { s_err += (double)g_curv_err[i]; s_knn += (double)g_knn_sum[i]; }
    for (int i = t; i < N * KNN; i += 256) s_ref += (double)ref_dist[i];
    __shared__ double d1[256], d2[256], d3[256];
    d1[t] = s_err; d2[t] = s_knn; d3[t] = s_ref;
    __syncthreads();
    for (int s = 128; s > 0; s >>= 1) {
        if (t < s) { d1[t] += d1[t + s]; d2[t] += d2[t + s]; d3[t] += d3[t + s]; }
        __syncthreads();
    }
    if (t == 0) {
        double curv_loss = d1[0] / (double)N;
        double m_knn = d2[0] / (double)(N * KNN);
        double m_ref = d3[0] / (double)(N * KNN);
        double diff  = m_knn - m_ref;
        out[0] = (float)(curv_loss + 0.1 * diff * diff);
    }
}

// ---------------- launch ----------------------------------------------------
extern "C" void kernel_launch(void* const* d_in, const int* in_sizes, int n_in,
                              void* d_out, int out_size) {
    const float* emb      = (const float*)d_in[0];   // [N, D]
    const float* ref_curv = (const float*)d_in[1];   // [N]
    const float* ref_dist = (const float*)d_in[2];   // [N, K]
    float* out = (float*)d_out;

    static int smem_set = 0;
    if (!smem_set) {
        cudaFuncSetAttribute(dist_gemm_mma_kernel,
                             cudaFuncAttributeMaxDynamicSharedMemorySize, SM_TOTAL);
        smem_set = 1;
    }

    row_norms_kernel<<<N, 128>>>(emb);
    dist_gemm_mma_kernel<<<GEMM_SPLIT, 256, SM_TOTAL>>>(0);
    dist_gemm_mma_kernel<<<NTILES - GEMM_SPLIT, 256, SM_TOTAL>>>(GEMM_SPLIT);
    topk_kernel<<<N, 256>>>();
    curvature_kernel<<<N, 256>>>(ref_curv);
    final_kernel<<<1, 256>>>(ref_dist, out);
}

// round 12
// speedup vs baseline: 3.8329x; 1.3170x over previous
#include <cuda_runtime.h>
#include <cuda_fp16.h>
#include <math.h>
#include <float.h>
#include <stdint.h>

#define N 8192
#define D 512
#define KNN 16
#define NPAIRS 120   // 16*15/2

// ---------------- scratch (device globals; no runtime allocation) ----------
__device__ float  g_sq[N];
__device__ __half g_embh[(size_t)N * D];    // fp16 (rn) copy of embeddings
__device__ float  g_dist[(size_t)N * N];    // 256 MB full symmetric distance matrix
__device__ float  g_segmin[(size_t)N * 128];// per-row min over 64-col segments
__device__ int    g_knn_idx[N * KNN];
__device__ float  g_knn_d[N * KNN];
__device__ float  g_curv_err[N];
__device__ float  g_knn_sum[N];
__device__ double g_part[32][3];            // two-stage final reduction

// ---------------- PTX helpers ----------------------------------------------
__device__ __forceinline__ uint32_t smem_u32(const void* p) {
    uint32_t a;
    asm("{ .reg .u64 t; cvta.to.shared.u64 t, %1; cvt.u32.u64 %0, t; }" : "=r"(a) : "l"(p));
    return a;
}
#define CP_ASYNC16(dst, src) \
    asm volatile("cp.async.cg.shared.global [%0], [%1], 16;" :: "r"(dst), "l"(src))
#define CP_COMMIT() asm volatile("cp.async.commit_group;" ::: "memory")
#define CP_WAIT(n)  asm volatile("cp.async.wait_group %0;" :: "n"(n) : "memory")
#define GROUP_BAR(id) \
    asm volatile("bar.sync %0, %1;" :: "r"(id), "r"(128) : "memory")

__device__ __forceinline__ void ldsm_x4(uint32_t* r, uint32_t addr) {
    asm volatile("ldmatrix.sync.aligned.m8n8.x4.shared.b16 {%0,%1,%2,%3}, [%4];"
                 : "=r"(r[0]), "=r"(r[1]), "=r"(r[2]), "=r"(r[3]) : "r"(addr));
}
__device__ __forceinline__ void ldsm_x2(uint32_t* r, uint32_t addr) {
    asm volatile("ldmatrix.sync.aligned.m8n8.x2.shared.b16 {%0,%1}, [%2];"
                 : "=r"(r[0]), "=r"(r[1]) : "r"(addr));
}
__device__ __forceinline__ void mma_f16(float* c, const uint32_t* a, const uint32_t* b) {
    asm volatile(
        "mma.sync.aligned.m16n8k16.row.col.f32.f16.f16.f32 "
        "{%0,%1,%2,%3}, {%4,%5,%6,%7}, {%8,%9}, {%0,%1,%2,%3};"
        : "+f"(c[0]), "+f"(c[1]), "+f"(c[2]), "+f"(c[3])
        : "r"(a[0]), "r"(a[1]), "r"(a[2]), "r"(a[3]), "r"(b[0]), "r"(b[1]));
}

// ---------------- K1: row squared norms + fp16 copy ------------------------
__global__ void row_norms_kernel(const float* __restrict__ A) {
    int row = blockIdx.x;
    int t = threadIdx.x;                         // 128 threads, D/4 = 128
    const float4* a4 = (const float4*)(A + (size_t)row * D);
    float4 v = a4[t];
    __half2 h0 = __floats2half2_rn(v.x, v.y);
    __half2 h1 = __floats2half2_rn(v.z, v.w);
    uint2 q;
    q.x = *(uint32_t*)&h0; q.y = *(uint32_t*)&h1;
    *(uint2*)(g_embh + (size_t)row * D + t * 4) = q;
    float s = v.x * v.x + v.y * v.y + v.z * v.z + v.w * v.w;
    #pragma unroll
    for (int o = 16; o > 0; o >>= 1) s += __shfl_down_sync(0xffffffffu, s, o);
    __shared__ float red[4];
    if ((t & 31) == 0) red[t >> 5] = s;
    __syncthreads();
    if (t == 0) g_sq[row] = red[0] + red[1] + red[2] + red[3];
}

// ---------------- K2: fp16 mma.sync distance GEMM (symmetric) --------------
#define BM 128
#define BN 256
#define BKC 64
#define NCHUNK (D / BKC)   // 8
#define NTILES 1056
#define GEMM_SPLIT 888

#define SM_SQJ   0
#define SM_SQI   1024
#define SM_STAGE 2048
#define STAGE_BYTES 49152                   // A 16KB + B 32KB
#define SM_TOTAL (SM_STAGE + 3 * STAGE_BYTES)

static __device__ __forceinline__ uint32_t sw128(uint32_t b) { return b ^ ((b >> 3) & 0x70); }

__global__ __launch_bounds__(256, 1)
void dist_gemm_mma_kernel(int tile_base) {
    extern __shared__ char smem[];
    const uint32_t sbase = smem_u32(smem);
    const int t    = threadIdx.x;
    const int wid  = t >> 5;
    const int lane = t & 31;
    const int g    = lane >> 2;
    const int tq   = lane & 3;
    const int warpM = (wid >> 2) * 64;
    const int warpN = (wid & 3) * 64;

    int flat = tile_base + blockIdx.x;
    int bi = 0, cnt = 32;
    while (flat >= cnt) { flat -= cnt; ++bi; cnt = 32 - (bi >> 1); }
    const int bj = (bi >> 1) + flat;
    const int rowA0 = bi * BM;
    const int colB0 = bj * BN;

    *(float*)(smem + SM_SQJ + t * 4) = g_sq[colB0 + t];
    if (t < 128) *(float*)(smem + SM_SQI + t * 4) = g_sq[rowA0 + t];

    const uint32_t laneRowA = (lane & 7) + ((lane >> 3) & 1) * 8;
    const uint32_t laneColA = (lane >> 4) * 16;
    const uint32_t laneRowB = lane & 7;
    const uint32_t laneColB = ((lane >> 3) & 1) * 16;

    auto issue_chunk = [&](int kt, int stg) {
        const int kc = kt * BKC;
        const uint32_t sb = sbase + SM_STAGE + (uint32_t)stg * STAGE_BYTES;
        #pragma unroll
        for (int l = 0; l < 12; l++) {
            int idx = t + l * 256;            // 0..3071
            int r   = idx >> 3;               // 0..383
            int c4  = idx & 7;                // 16B unit within 128B row
            int isA = (r < 128);
            int grow = isA ? (rowA0 + r) : (colB0 + r - 128);
            const __half* src = g_embh + (size_t)grow * D + kc + c4 * 8;
            uint32_t off = (isA ? 0u : 16384u) +
                           sw128((uint32_t)(isA ? r : r - 128) * 128u + (uint32_t)c4 * 16u);
            CP_ASYNC16(sb + off, src);
        }
        CP_COMMIT();
    };

    float acc[4][8][4];
    #pragma unroll
    for (int mt = 0; mt < 4; mt++)
        #pragma unroll
        for (int nt = 0; nt < 8; nt++)
            #pragma unroll
            for (int q = 0; q < 4; q++) acc[mt][nt][q] = 0.f;

    issue_chunk(0, 0);
    issue_chunk(1, 1);

    #pragma unroll 1
    for (int kt = 0; kt < NCHUNK; kt++) {
        const int stg = kt % 3;
        CP_WAIT(1);
        __syncthreads();
        if (kt + 2 < NCHUNK) issue_chunk(kt + 2, (kt + 2) % 3);

        const uint32_t abase = sbase + SM_STAGE + (uint32_t)stg * STAGE_BYTES;
        const uint32_t bbase = abase + 16384u;
        #pragma unroll
        for (int ks = 0; ks < 4; ks++) {       // 4 k-steps of 16 halfs (32B)
            uint32_t af[4][4], bf[8][2];
            #pragma unroll
            for (int mt = 0; mt < 4; mt++) {
                uint32_t byte = (uint32_t)(warpM + mt * 16 + laneRowA) * 128u +
                                (uint32_t)ks * 32u + laneColA;
                ldsm_x4(af[mt], abase + sw128(byte));
            }
            #pragma unroll
            for (int nt = 0; nt < 8; nt++) {
                uint32_t byte = (uint32_t)(warpN + nt * 8 + laneRowB) * 128u +
                                (uint32_t)ks * 32u + laneColB;
                ldsm_x2(bf[nt], bbase + sw128(byte));
            }
            #pragma unroll
            for (int mt = 0; mt < 4; mt++)
                #pragma unroll
                for (int nt = 0; nt < 8; nt++)
                    mma_f16(acc[mt][nt], af[mt], bf[nt]);
        }
        __syncthreads();
    }

    // ---- epilogue: distances; direct + mirror stores + segment mins -------
    const float* sqj = (const float*)(smem + SM_SQJ);
    const float* sqi = (const float*)(smem + SM_SQI);
    float rmin[4][2];
    float cmin[8][2];
    #pragma unroll
    for (int mt = 0; mt < 4; mt++) { rmin[mt][0] = FLT_MAX; rmin[mt][1] = FLT_MAX; }
    #pragma unroll
    for (int nt = 0; nt < 8; nt++) { cmin[nt][0] = FLT_MAX; cmin[nt][1] = FLT_MAX; }

    #pragma unroll
    for (int mt = 0; mt < 4; mt++) {
        const int r0 = warpM + mt * 16 + g;
        const int r1 = r0 + 8;
        const int gr0 = rowA0 + r0, gr1 = rowA0 + r1;
        const float si0 = sqi[r0], si1 = sqi[r1];
        #pragma unroll
        for (int nt = 0; nt < 8; nt++) {
            const int cl = warpN + nt * 8 + tq * 2;
            const int gc = colB0 + cl;
            const float sj0 = sqj[cl], sj1 = sqj[cl + 1];
            float d2;
            float2 o0, o1;
            d2 = si0 + sj0 - 2.f * acc[mt][nt][0];
            o0.x = (d2 > 0.f) ? sqrtf(fmaxf(d2, 1e-12f)) : 0.f;
            d2 = si0 + sj1 - 2.f * acc[mt][nt][1];
            o0.y = (d2 > 0.f) ? sqrtf(fmaxf(d2, 1e-12f)) : 0.f;
            d2 = si1 + sj0 - 2.f * acc[mt][nt][2];
            o1.x = (d2 > 0.f) ? sqrtf(fmaxf(d2, 1e-12f)) : 0.f;
            d2 = si1 + sj1 - 2.f * acc[mt][nt][3];
            o1.y = (d2 > 0.f) ? sqrtf(fmaxf(d2, 1e-12f)) : 0.f;
            *(float2*)(g_dist + (size_t)gr0 * N + gc) = o0;
            *(float2*)(g_dist + (size_t)gr1 * N + gc) = o1;
            g_dist[(size_t)gc * N + gr0]       = o0.x;
            g_dist[(size_t)gc * N + gr1]       = o1.x;
            g_dist[(size_t)(gc + 1) * N + gr0] = o0.y;
            g_dist[(size_t)(gc + 1) * N + gr1] = o1.y;
            rmin[mt][0] = fminf(rmin[mt][0], fminf(o0.x, o0.y));
            rmin[mt][1] = fminf(rmin[mt][1], fminf(o1.x, o1.y));
            cmin[nt][0] = fminf(cmin[nt][0], fminf(o0.x, o1.x));
            cmin[nt][1] = fminf(cmin[nt][1], fminf(o0.y, o1.y));
        }
    }

    // row segment mins: reduce over tq lanes (same g)
    const int rseg = bj * 4 + (wid & 3);
    #pragma unroll
    for (int mt = 0; mt < 4; mt++) {
        #pragma unroll
        for (int h = 0; h < 2; h++) {
            float x = rmin[mt][h];
            x = fminf(x, __shfl_xor_sync(0xffffffffu, x, 1));
            x = fminf(x, __shfl_xor_sync(0xffffffffu, x, 2));
            if (tq == 0) {
                const int gr = rowA0 + warpM + mt * 16 + g + h * 8;
                g_segmin[(size_t)gr * 128 + rseg] = x;
            }
        }
    }
    // col segment mins: reduce over g lanes (same tq)
    const int cseg = bi * 2 + (wid >> 2);
    #pragma unroll
    for (int nt = 0; nt < 8; nt++) {
        #pragma unroll
        for (int p = 0; p < 2; p++) {
            float x = cmin[nt][p];
            x = fminf(x, __shfl_xor_sync(0xffffffffu, x, 4));
            x = fminf(x, __shfl_xor_sync(0xffffffffu, x, 8));
            x = fminf(x, __shfl_xor_sync(0xffffffffu, x, 16));
            if (g == 0) {
                const int gc = colB0 + warpN + nt * 8 + tq * 2 + p;
                g_segmin[(size_t)gc * 128 + cseg] = x;
            }
        }
    }
}

// ---------------- K3: segment-pruned top-16, 2 rows per block --------------
// Warps 0-3 own row A, warps 4-7 own row B; each 128-thread group syncs only
// via its own named barrier -> two independent latency chains per block.
__global__ __launch_bounds__(256)
void topk_kernel() {
    const int t    = threadIdx.x;
    const int grp  = t >> 7;              // 0 or 1
    const int gt   = t & 127;             // thread within group
    const int lane = t & 31;
    const int gw   = (t >> 5) & 3;        // warp within group
    const int i    = blockIdx.x * 2 + grp;

    __shared__ float warp5[2][4];
    __shared__ int   segs[2][128];
    __shared__ int   s_scnt[2];
    __shared__ float bufv[2][1024];
    __shared__ int   bufi[2][1024];
    __shared__ int   s_bcnt[2];

    if (gt == 0) { s_scnt[grp] = 0; s_bcnt[grp] = 0; }

    const float sv = g_segmin[(size_t)i * 128 + gt];

    // each warp: its 5th-smallest segmin (keyed, duplicate-safe)
    {
        unsigned long long key =
            ((unsigned long long)__float_as_uint(sv) << 32) | (unsigned)gt;
        float fifth = FLT_MAX;
        #pragma unroll
        for (int r = 0; r < 5; r++) {
            unsigned long long k2 = key;
            #pragma unroll
            for (int o = 16; o > 0; o >>= 1) {
                unsigned long long other = __shfl_xor_sync(0xffffffffu, k2, o);
                k2 = (other < k2) ? other : k2;
            }
            if (key == k2) key = ~0ULL;
            fifth = __uint_as_float((uint32_t)(k2 >> 32));
        }
        if (lane == 0) warp5[grp][gw] = fifth;
    }
    GROUP_BAR(grp + 1);
    const float T = fmaxf(fmaxf(warp5[grp][0], warp5[grp][1]),
                          fmaxf(warp5[grp][2], warp5[grp][3]));

    if (sv <= T) {
        int e = atomicAdd(&s_scnt[grp], 1);
        segs[grp][e] = gt;
    }
    GROUP_BAR(grp + 1);
    const int nseg = s_scnt[grp];

    const float* __restrict__ drow = g_dist + (size_t)i * N;
    const int total = nseg * 64;
    for (int e = gt; e < total; e += 128) {
        const int j = (segs[grp][e >> 6] << 6) | (e & 63);
        const float dv = drow[j];
        if (dv <= T && j != i) {
            int b = atomicAdd(&s_bcnt[grp], 1);
            if (b < 1024) { bufv[grp][b] = dv; bufi[grp][b] = j; }
        }
    }
    GROUP_BAR(grp + 1);
    const int n_e = (s_bcnt[grp] < 1024) ? s_bcnt[grp] : 1024;

    // rank selection (keys unique by col; ties by col like lax.top_k)
    for (int e = gt; e < n_e; e += 128) {
        const unsigned long long mykey =
            ((unsigned long long)__float_as_uint(bufv[grp][e]) << 32) | (unsigned)bufi[grp][e];
        int rank = 0;
        for (int q = 0; q < n_e; q++) {
            const unsigned long long k =
                ((unsigned long long)__float_as_uint(bufv[grp][q]) << 32) | (unsigned)bufi[grp][q];
            rank += (k < mykey);
        }
        if (rank < KNN) {
            g_knn_d[i * KNN + rank]   = bufv[grp][e];
            g_knn_idx[i * KNN + rank] = bufi[grp][e];
        }
    }
}

// ---------------- K4: curvature, warp per point -----------------------------
__global__ __launch_bounds__(256)
void curvature_kernel(const float* __restrict__ ref_curv) {
    const int w    = threadIdx.x >> 5;
    const int lane = threadIdx.x & 31;
    const int i    = blockIdx.x * 8 + w;

    int   myidx = 0;
    float myd   = 0.f;
    if (lane < KNN) {
        myidx = g_knn_idx[i * KNN + lane];
        myd   = g_knn_d[i * KNN + lane];
    }

    // sum of knn distances (lanes >=16 contribute 0)
    float dsum = myd;
    #pragma unroll
    for (int o = 16; o > 0; o >>= 1)
        dsum += __shfl_xor_sync(0xffffffffu, dsum, o);

    // 120 neighbor pairs, 4 predicated rounds (converged shuffles)
    float isum = 0.f;
    #pragma unroll
    for (int u = 0; u < 4; u++) {
        const int p = lane + u * 32;
        const bool act = (p < NPAIRS);
        int L = act ? p : 0;
        int j = 0;
        while (L >= 15 - j) { L -= 15 - j; j++; }
        const int k = j + 1 + L;
        const int ij = __shfl_sync(0xffffffffu, myidx, j);
        const int ik = __shfl_sync(0xffffffffu, myidx, k);
        if (act) isum += g_dist[(size_t)ij * N + ik];
    }
    #pragma unroll
    for (int o = 16; o > 0; o >>= 1)
        isum += __shfl_xor_sync(0xffffffffu, isum, o);

    if (lane == 0) {
        const float avg        = dsum / (float)KNN;
        const float inter_mean = isum / (float)NPAIRS;
        const float curv       = inter_mean / (avg + 1e-8f);
        const float diff       = curv - ref_curv[i];
        g_curv_err[i] = diff * diff;
        g_knn_sum[i]  = dsum;
    }
}

// ---------------- K5: final scalar, two-stage (deterministic) --------------
__global__ void final_stage1(const float* __restrict__ ref_dist) {
    const int t = threadIdx.x;               // 256 threads, 32 blocks
    const int b = blockIdx.x;
    const int gid = b * 256 + t;             // 0..8191
    double e  = (double)g_curv_err[gid];
    double kk = (double)g_knn_sum[gid];
    double rf = 0.0;
    for (int u = gid; u < N * KNN; u += 8192) rf += (double)ref_dist[u];
    __shared__ double d1[256], d2[256], d3[256];
    d1[t] = e; d2[t] = kk; d3[t] = rf;
    __syncthreads();
    for (int s = 128; s > 0; s >>= 1) {
        if (t < s) { d1[t] += d1[t + s]; d2[t] += d2[t + s]; d3[t] += d3[t + s]; }
        __syncthreads();
    }
    if (t == 0) {
        g_part[b][0] = d1[0]; g_part[b][1] = d2[0]; g_part[b][2] = d3[0];
    }
}

__global__ void final_stage2(float* __restrict__ out) {
    const int t = threadIdx.x;               // 32 threads (1 warp)
    double e  = g_part[t][0];
    double kk = g_part[t][1];
    double rf = g_part[t][2];
    #pragma unroll
    for (int o = 16; o > 0; o >>= 1) {
        e  += __shfl_down_sync(0xffffffffu, e,  o);
        kk += __shfl_down_sync(0xffffffffu, kk, o);
        rf += __shfl_down_sync(0xffffffffu, rf, o);
    }
    if (t == 0) {
        double curv_loss = e / (double)N;
        double m_knn = kk / (double)(N * KNN);
        double m_ref = rf / (double)(N * KNN);
        double diff  = m_knn - m_ref;
        out[0] = (float)(curv_loss + 0.1 * diff * diff);
    }
}

// ---------------- launch ----------------------------------------------------
extern "C" void kernel_launch(void* const* d_in, const int* in_sizes, int n_in,
                              void* d_out, int out_size) {
    const float* emb      = (const float*)d_in[0];   // [N, D]
    const float* ref_curv = (const float*)d_in[1];   // [N]
    const float* ref_dist = (const float*)d_in[2];   // [N, K]
    float* out = (float*)d_out;

    static int smem_set = 0;
    if (!smem_set) {
        cudaFuncSetAttribute(dist_gemm_mma_kernel,
                             cudaFuncAttributeMaxDynamicSharedMemorySize, SM_TOTAL);
        smem_set = 1;
    }

    row_norms_kernel<<<N, 128>>>(emb);
    dist_gemm_mma_kernel<<<GEMM_SPLIT, 256, SM_TOTAL>>>(0);
    dist_gemm_mma_kernel<<<NTILES - GEMM_SPLIT, 256, SM_TOTAL>>>(GEMM_SPLIT);
    topk_kernel<<<N / 2, 256>>>();
    curvature_kernel<<<N / 8, 256>>>(ref_curv);
    final_stage1<<<32, 256>>>(ref_dist);
    final_stage2<<<1, 32>>>(out);
}

// round 13
// speedup vs baseline: 4.1974x; 1.0951x over previous
#include <cuda_runtime.h>
#include <cuda_fp16.h>
#include <math.h>
#include <float.h>
#include <stdint.h>

#define N 8192
#define D 512
#define KNN 16
#define NPAIRS 120   // 16*15/2

// ---------------- scratch (device globals; no runtime allocation) ----------
__device__ float  g_sq[N];
__device__ __half g_embh[(size_t)N * D];    // fp16 (rn) copy of embeddings
__device__ float  g_dist[(size_t)N * N];    // 256 MB full symmetric distance matrix
__device__ float  g_segmin[(size_t)N * 256];// per-row min over 32-col segments
__device__ int    g_knn_idx[N * KNN];
__device__ float  g_knn_d[N * KNN];
__device__ float  g_curv_err[N];
__device__ float  g_knn_sum[N];
__device__ double g_part[32][3];            // two-stage final reduction

// ---------------- PTX helpers ----------------------------------------------
__device__ __forceinline__ uint32_t smem_u32(const void* p) {
    uint32_t a;
    asm("{ .reg .u64 t; cvta.to.shared.u64 t, %1; cvt.u32.u64 %0, t; }" : "=r"(a) : "l"(p));
    return a;
}
#define CP_ASYNC16(dst, src) \
    asm volatile("cp.async.cg.shared.global [%0], [%1], 16;" :: "r"(dst), "l"(src))
#define CP_COMMIT() asm volatile("cp.async.commit_group;" ::: "memory")
#define CP_WAIT(n)  asm volatile("cp.async.wait_group %0;" :: "n"(n) : "memory")
#define GROUP_BAR(id) \
    asm volatile("bar.sync %0, %1;" :: "r"(id), "r"(128) : "memory")

__device__ __forceinline__ void ldsm_x4(uint32_t* r, uint32_t addr) {
    asm volatile("ldmatrix.sync.aligned.m8n8.x4.shared.b16 {%0,%1,%2,%3}, [%4];"
                 : "=r"(r[0]), "=r"(r[1]), "=r"(r[2]), "=r"(r[3]) : "r"(addr));
}
__device__ __forceinline__ void ldsm_x2(uint32_t* r, uint32_t addr) {
    asm volatile("ldmatrix.sync.aligned.m8n8.x2.shared.b16 {%0,%1}, [%2];"
                 : "=r"(r[0]), "=r"(r[1]) : "r"(addr));
}
__device__ __forceinline__ void mma_f16(float* c, const uint32_t* a, const uint32_t* b) {
    asm volatile(
        "mma.sync.aligned.m16n8k16.row.col.f32.f16.f16.f32 "
        "{%0,%1,%2,%3}, {%4,%5,%6,%7}, {%8,%9}, {%0,%1,%2,%3};"
        : "+f"(c[0]), "+f"(c[1]), "+f"(c[2]), "+f"(c[3])
        : "r"(a[0]), "r"(a[1]), "r"(a[2]), "r"(a[3]), "r"(b[0]), "r"(b[1]));
}

// ---------------- K1: row squared norms + fp16 copy ------------------------
__global__ void row_norms_kernel(const float* __restrict__ A) {
    int row = blockIdx.x;
    int t = threadIdx.x;                         // 128 threads, D/4 = 128
    const float4* a4 = (const float4*)(A + (size_t)row * D);
    float4 v = a4[t];
    __half2 h0 = __floats2half2_rn(v.x, v.y);
    __half2 h1 = __floats2half2_rn(v.z, v.w);
    uint2 q;
    q.x = *(uint32_t*)&h0; q.y = *(uint32_t*)&h1;
    *(uint2*)(g_embh + (size_t)row * D + t * 4) = q;
    float s = v.x * v.x + v.y * v.y + v.z * v.z + v.w * v.w;
    #pragma unroll
    for (int o = 16; o > 0; o >>= 1) s += __shfl_down_sync(0xffffffffu, s, o);
    __shared__ float red[4];
    if ((t & 31) == 0) red[t >> 5] = s;
    __syncthreads();
    if (t == 0) g_sq[row] = red[0] + red[1] + red[2] + red[3];
}

// ---------------- K2: fp16 mma.sync distance GEMM (symmetric) --------------
// 128x128 upper-triangular tiles (2 CTAs/SM); warp tile 64x32; K chunks of
// 64 halfs (128B SW128 rows); 3-stage cp.async; width-32 segmin epilogue.
#define BM 128
#define BN 128
#define BKC 64
#define NCHUNK (D / BKC)   // 8
#define NT 64              // tiles per side
#define NTILES 2080        // 64*65/2
#define GEMM_SPLIT 1776    // 6 waves at 296 concurrent CTAs

#define SM_SQJ   0
#define SM_SQI   512
#define SM_STAGE 1024
#define STAGE_BYTES 32768                   // A 16KB + B 16KB
#define SM_TOTAL (SM_STAGE + 3 * STAGE_BYTES)   // 99328 -> 2 CTAs/SM

static __device__ __forceinline__ uint32_t sw128(uint32_t b) { return b ^ ((b >> 3) & 0x70); }

__global__ __launch_bounds__(256, 2)
void dist_gemm_mma_kernel(int tile_base) {
    extern __shared__ char smem[];
    const uint32_t sbase = smem_u32(smem);
    const int t    = threadIdx.x;
    const int wid  = t >> 5;
    const int lane = t & 31;
    const int g    = lane >> 2;
    const int tq   = lane & 3;
    const int warpM = (wid >> 2) * 64;      // 0 or 64
    const int warpN = (wid & 3) * 32;       // 0,32,64,96

    // flat tile id -> (bi, bj), bi <= bj, square triangular
    int flat = tile_base + blockIdx.x;
    int bi = 0;
    while (flat >= NT - bi) { flat -= NT - bi; ++bi; }
    const int bj = bi + flat;
    const int rowA0 = bi * BM;
    const int colB0 = bj * BN;

    if (t < 128) {
        *(float*)(smem + SM_SQJ + t * 4) = g_sq[colB0 + t];
        *(float*)(smem + SM_SQI + t * 4) = g_sq[rowA0 + t];
    }

    const uint32_t laneRowA = (lane & 7) + ((lane >> 3) & 1) * 8;
    const uint32_t laneColA = (lane >> 4) * 16;
    const uint32_t laneRowB = lane & 7;
    const uint32_t laneColB = ((lane >> 3) & 1) * 16;

    // chunk staging: 8 x 16B cp.async per thread (A:4, B:4)
    auto issue_chunk = [&](int kt, int stg) {
        const int kc = kt * BKC;
        const uint32_t sb = sbase + SM_STAGE + (uint32_t)stg * STAGE_BYTES;
        #pragma unroll
        for (int l = 0; l < 8; l++) {
            int idx = t + l * 256;            // 0..2047
            int r   = idx >> 3;               // 0..255
            int c4  = idx & 7;                // 16B unit within 128B row
            int isA = (r < 128);
            int grow = isA ? (rowA0 + r) : (colB0 + r - 128);
            const __half* src = g_embh + (size_t)grow * D + kc + c4 * 8;
            uint32_t off = (isA ? 0u : 16384u) +
                           sw128((uint32_t)(isA ? r : r - 128) * 128u + (uint32_t)c4 * 16u);
            CP_ASYNC16(sb + off, src);
        }
        CP_COMMIT();
    };

    float acc[4][4][4];
    #pragma unroll
    for (int mt = 0; mt < 4; mt++)
        #pragma unroll
        for (int nt = 0; nt < 4; nt++)
            #pragma unroll
            for (int q = 0; q < 4; q++) acc[mt][nt][q] = 0.f;

    issue_chunk(0, 0);
    issue_chunk(1, 1);

    #pragma unroll 1
    for (int kt = 0; kt < NCHUNK; kt++) {
        const int stg = kt % 3;
        CP_WAIT(1);
        __syncthreads();
        if (kt + 2 < NCHUNK) issue_chunk(kt + 2, (kt + 2) % 3);

        const uint32_t abase = sbase + SM_STAGE + (uint32_t)stg * STAGE_BYTES;
        const uint32_t bbase = abase + 16384u;
        #pragma unroll
        for (int ks = 0; ks < 4; ks++) {       // 4 k-steps of 16 halfs (32B)
            uint32_t af[4][4], bf[4][2];
            #pragma unroll
            for (int mt = 0; mt < 4; mt++) {
                uint32_t byte = (uint32_t)(warpM + mt * 16 + laneRowA) * 128u +
                                (uint32_t)ks * 32u + laneColA;
                ldsm_x4(af[mt], abase + sw128(byte));
            }
            #pragma unroll
            for (int nt = 0; nt < 4; nt++) {
                uint32_t byte = (uint32_t)(warpN + nt * 8 + laneRowB) * 128u +
                                (uint32_t)ks * 32u + laneColB;
                ldsm_x2(bf[nt], bbase + sw128(byte));
            }
            #pragma unroll
            for (int mt = 0; mt < 4; mt++)
                #pragma unroll
                for (int nt = 0; nt < 4; nt++)
                    mma_f16(acc[mt][nt], af[mt], bf[nt]);
        }
        __syncthreads();
    }

    // ---- epilogue: distances; direct + mirror stores + 32-wide segmins ----
    const float* sqj = (const float*)(smem + SM_SQJ);
    const float* sqi = (const float*)(smem + SM_SQI);
    float rmin[4][2];                       // per-row mins over warp's 32 cols
    float cmin[2][4][2];                    // [32-row half][nt][p]
    #pragma unroll
    for (int mt = 0; mt < 4; mt++) { rmin[mt][0] = FLT_MAX; rmin[mt][1] = FLT_MAX; }
    #pragma unroll
    for (int mp = 0; mp < 2; mp++)
        #pragma unroll
        for (int nt = 0; nt < 4; nt++) { cmin[mp][nt][0] = FLT_MAX; cmin[mp][nt][1] = FLT_MAX; }

    #pragma unroll
    for (int mt = 0; mt < 4; mt++) {
        const int r0 = warpM + mt * 16 + g;
        const int r1 = r0 + 8;
        const int gr0 = rowA0 + r0, gr1 = rowA0 + r1;
        const float si0 = sqi[r0], si1 = sqi[r1];
        #pragma unroll
        for (int nt = 0; nt < 4; nt++) {
            const int cl = warpN + nt * 8 + tq * 2;
            const int gc = colB0 + cl;
            const float sj0 = sqj[cl], sj1 = sqj[cl + 1];
            float d2;
            float2 o0, o1;
            d2 = si0 + sj0 - 2.f * acc[mt][nt][0];
            o0.x = (d2 > 0.f) ? sqrtf(fmaxf(d2, 1e-12f)) : 0.f;
            d2 = si0 + sj1 - 2.f * acc[mt][nt][1];
            o0.y = (d2 > 0.f) ? sqrtf(fmaxf(d2, 1e-12f)) : 0.f;
            d2 = si1 + sj0 - 2.f * acc[mt][nt][2];
            o1.x = (d2 > 0.f) ? sqrtf(fmaxf(d2, 1e-12f)) : 0.f;
            d2 = si1 + sj1 - 2.f * acc[mt][nt][3];
            o1.y = (d2 > 0.f) ? sqrtf(fmaxf(d2, 1e-12f)) : 0.f;
            *(float2*)(g_dist + (size_t)gr0 * N + gc) = o0;
            *(float2*)(g_dist + (size_t)gr1 * N + gc) = o1;
            g_dist[(size_t)gc * N + gr0]       = o0.x;
            g_dist[(size_t)gc * N + gr1]       = o1.x;
            g_dist[(size_t)(gc + 1) * N + gr0] = o0.y;
            g_dist[(size_t)(gc + 1) * N + gr1] = o1.y;
            rmin[mt][0] = fminf(rmin[mt][0], fminf(o0.x, o0.y));
            rmin[mt][1] = fminf(rmin[mt][1], fminf(o1.x, o1.y));
            cmin[mt >> 1][nt][0] = fminf(cmin[mt >> 1][nt][0], fminf(o0.x, o1.x));
            cmin[mt >> 1][nt][1] = fminf(cmin[mt >> 1][nt][1], fminf(o0.y, o1.y));
        }
    }

    // row segment mins (width 32): reduce over tq lanes (same g)
    const int rseg = (colB0 + warpN) >> 5;
    #pragma unroll
    for (int mt = 0; mt < 4; mt++) {
        #pragma unroll
        for (int h = 0; h < 2; h++) {
            float x = rmin[mt][h];
            x = fminf(x, __shfl_xor_sync(0xffffffffu, x, 1));
            x = fminf(x, __shfl_xor_sync(0xffffffffu, x, 2));
            if (tq == 0) {
                const int gr = rowA0 + warpM + mt * 16 + g + h * 8;
                g_segmin[(size_t)gr * 256 + rseg] = x;
            }
        }
    }
    // col segment mins (width 32 of rows): reduce over g lanes (same tq)
    #pragma unroll
    for (int mp = 0; mp < 2; mp++) {
        const int cseg = (rowA0 + warpM + mp * 32) >> 5;
        #pragma unroll
        for (int nt = 0; nt < 4; nt++) {
            #pragma unroll
            for (int p = 0; p < 2; p++) {
                float x = cmin[mp][nt][p];
                x = fminf(x, __shfl_xor_sync(0xffffffffu, x, 4));
                x = fminf(x, __shfl_xor_sync(0xffffffffu, x, 8));
                x = fminf(x, __shfl_xor_sync(0xffffffffu, x, 16));
                if (g == 0) {
                    const int gc = colB0 + warpN + nt * 8 + tq * 2 + p;
                    g_segmin[(size_t)gc * 256 + cseg] = x;
                }
            }
        }
    }
}

// ---------------- K3: segment-pruned top-16, 2 rows per block --------------
// sv = min of adjacent 32-wide segmins -> identical 64-wide semantics.
__global__ __launch_bounds__(256)
void topk_kernel() {
    const int t    = threadIdx.x;
    const int grp  = t >> 7;              // 0 or 1
    const int gt   = t & 127;             // thread within group
    const int lane = t & 31;
    const int gw   = (t >> 5) & 3;        // warp within group
    const int i    = blockIdx.x * 2 + grp;

    __shared__ float warp5[2][4];
    __shared__ int   segs[2][128];
    __shared__ int   s_scnt[2];
    __shared__ float bufv[2][1024];
    __shared__ int   bufi[2][1024];
    __shared__ int   s_bcnt[2];

    if (gt == 0) { s_scnt[grp] = 0; s_bcnt[grp] = 0; }

    const float2 sp = *(const float2*)(g_segmin + (size_t)i * 256 + 2 * gt);
    const float sv = fminf(sp.x, sp.y);

    // each warp: its 5th-smallest sv (keyed, duplicate-safe)
    {
        unsigned long long key =
            ((unsigned long long)__float_as_uint(sv) << 32) | (unsigned)gt;
        float fifth = FLT_MAX;
        #pragma unroll
        for (int r = 0; r < 5; r++) {
            unsigned long long k2 = key;
            #pragma unroll
            for (int o = 16; o > 0; o >>= 1) {
                unsigned long long other = __shfl_xor_sync(0xffffffffu, k2, o);
                k2 = (other < k2) ? other : k2;
            }
            if (key == k2) key = ~0ULL;
            fifth = __uint_as_float((uint32_t)(k2 >> 32));
        }
        if (lane == 0) warp5[grp][gw] = fifth;
    }
    GROUP_BAR(grp + 1);
    const float T = fmaxf(fmaxf(warp5[grp][0], warp5[grp][1]),
                          fmaxf(warp5[grp][2], warp5[grp][3]));

    if (sv <= T) {
        int e = atomicAdd(&s_scnt[grp], 1);
        segs[grp][e] = gt;
    }
    GROUP_BAR(grp + 1);
    const int nseg = s_scnt[grp];

    const float* __restrict__ drow = g_dist + (size_t)i * N;
    const int total = nseg * 64;
    for (int e = gt; e < total; e += 128) {
        const int j = (segs[grp][e >> 6] << 6) | (e & 63);
        const float dv = drow[j];
        if (dv <= T && j != i) {
            int b = atomicAdd(&s_bcnt[grp], 1);
            if (b < 1024) { bufv[grp][b] = dv; bufi[grp][b] = j; }
        }
    }
    GROUP_BAR(grp + 1);
    const int n_e = (s_bcnt[grp] < 1024) ? s_bcnt[grp] : 1024;

    // rank selection (keys unique by col; ties by col like lax.top_k)
    for (int e = gt; e < n_e; e += 128) {
        const unsigned long long mykey =
            ((unsigned long long)__float_as_uint(bufv[grp][e]) << 32) | (unsigned)bufi[grp][e];
        int rank = 0;
        for (int q = 0; q < n_e; q++) {
            const unsigned long long k =
                ((unsigned long long)__float_as_uint(bufv[grp][q]) << 32) | (unsigned)bufi[grp][q];
            rank += (k < mykey);
        }
        if (rank < KNN) {
            g_knn_d[i * KNN + rank]   = bufv[grp][e];
            g_knn_idx[i * KNN + rank] = bufi[grp][e];
        }
    }
}

// ---------------- K4: curvature, warp per point -----------------------------
__global__ __launch_bounds__(256)
void curvature_kernel(const float* __restrict__ ref_curv) {
    const int w    = threadIdx.x >> 5;
    const int lane = threadIdx.x & 31;
    const int i    = blockIdx.x * 8 + w;

    int   myidx = 0;
    float myd   = 0.f;
    if (lane < KNN) {
        myidx = g_knn_idx[i * KNN + lane];
        myd   = g_knn_d[i * KNN + lane];
    }

    float dsum = myd;
    #pragma unroll
    for (int o = 16; o > 0; o >>= 1)
        dsum += __shfl_xor_sync(0xffffffffu, dsum, o);

    float isum = 0.f;
    #pragma unroll
    for (int u = 0; u < 4; u++) {
        const int p = lane + u * 32;
        const bool act = (p < NPAIRS);
        int L = act ? p : 0;
        int j = 0;
        while (L >= 15 - j) { L -= 15 - j; j++; }
        const int k = j + 1 + L;
        const int ij = __shfl_sync(0xffffffffu, myidx, j);
        const int ik = __shfl_sync(0xffffffffu, myidx, k);
        if (act) isum += g_dist[(size_t)ij * N + ik];
    }
    #pragma unroll
    for (int o = 16; o > 0; o >>= 1)
        isum += __shfl_xor_sync(0xffffffffu, isum, o);

    if (lane == 0) {
        const float avg        = dsum / (float)KNN;
        const float inter_mean = isum / (float)NPAIRS;
        const float curv       = inter_mean / (avg + 1e-8f);
        const float diff       = curv - ref_curv[i];
        g_curv_err[i] = diff * diff;
        g_knn_sum[i]  = dsum;
    }
}

// ---------------- K5: final scalar, two-stage (deterministic) --------------
__global__ void final_stage1(const float* __restrict__ ref_dist) {
    const int t = threadIdx.x;               // 256 threads, 32 blocks
    const int b = blockIdx.x;
    const int gid = b * 256 + t;             // 0..8191
    double e  = (double)g_curv_err[gid];
    double kk = (double)g_knn_sum[gid];
    double rf = 0.0;
    for (int u = gid; u < N * KNN; u += 8192) rf += (double)ref_dist[u];
    __shared__ double d1[256], d2[256], d3[256];
    d1[t] = e; d2[t] = kk; d3[t] = rf;
    __syncthreads();
    for (int s = 128; s > 0; s >>= 1) {
        if (t < s) { d1[t] += d1[t + s]; d2[t] += d2[t + s]; d3[t] += d3[t + s]; }
        __syncthreads();
    }
    if (t == 0) {
        g_part[b][0] = d1[0]; g_part[b][1] = d2[0]; g_part[b][2] = d3[0];
    }
}

__global__ void final_stage2(float* __restrict__ out) {
    const int t = threadIdx.x;               // 32 threads (1 warp)
    double e  = g_part[t][0];
    double kk = g_part[t][1];
    double rf = g_part[t][2];
    #pragma unroll
    for (int o = 16; o > 0; o >>= 1) {
        e  += __shfl_down_sync(0xffffffffu, e,  o);
        kk += __shfl_down_sync(0xffffffffu, kk, o);
        rf += __shfl_down_sync(0xffffffffu, rf, o);
    }
    if (t == 0) {
        double curv_loss = e / (double)N;
        double m_knn = kk / (double)(N * KNN);
        double m_ref = rf / (double)(N * KNN);
        double diff  = m_knn - m_ref;
        out[0] = (float)(curv_loss + 0.1 * diff * diff);
    }
}

// ---------------- launch ----------------------------------------------------
extern "C" void kernel_launch(void* const* d_in, const int* in_sizes, int n_in,
                              void* d_out, int out_size) {
    const float* emb      = (const float*)d_in[0];   // [N, D]
    const float* ref_curv = (const float*)d_in[1];   // [N]
    const float* ref_dist = (const float*)d_in[2];   // [N, K]
    float* out = (float*)d_out;

    static int smem_set = 0;
    if (!smem_set) {
        cudaFuncSetAttribute(dist_gemm_mma_kernel,
                             cudaFuncAttributeMaxDynamicSharedMemorySize, SM_TOTAL);
        smem_set = 1;
    }

    row_norms_kernel<<<N, 128>>>(emb);
    dist_gemm_mma_kernel<<<GEMM_SPLIT, 256, SM_TOTAL>>>(0);
    dist_gemm_mma_kernel<<<NTILES - GEMM_SPLIT, 256, SM_TOTAL>>>(GEMM_SPLIT);
    topk_kernel<<<N / 2, 256>>>();
    curvature_kernel<<<N / 8, 256>>>(ref_curv);
    final_stage1<<<32, 256>>>(ref_dist);
    final_stage2<<<1, 32>>>(out);
}

// round 14
// speedup vs baseline: 4.6532x; 1.1086x over previous
#include <cuda_runtime.h>
#include <cuda_fp16.h>
#include <math.h>
#include <float.h>
#include <stdint.h>

#define N 8192
#define D 512
#define KNN 16
#define NPAIRS 120   // 16*15/2

// ---------------- scratch (device globals; no runtime allocation) ----------
__device__ float  g_sq[N];
__device__ __half g_embh[(size_t)N * D];    // fp16 (rn) copy of embeddings
__device__ float  g_dist[(size_t)N * N];    // 256 MB full symmetric distance matrix
__device__ float  g_segmin[(size_t)N * 256];// per-row min over 32-col segments
__device__ int    g_knn_idx[N * KNN];
__device__ float  g_knn_d[N * KNN];
__device__ float  g_curv_err[N];
__device__ float  g_knn_sum[N];
__device__ double g_part[32][3];            // two-stage final reduction

// ---------------- PTX helpers ----------------------------------------------
__device__ __forceinline__ uint32_t smem_u32(const void* p) {
    uint32_t a;
    asm("{ .reg .u64 t; cvta.to.shared.u64 t, %1; cvt.u32.u64 %0, t; }" : "=r"(a) : "l"(p));
    return a;
}
#define CP_ASYNC16(dst, src) \
    asm volatile("cp.async.cg.shared.global [%0], [%1], 16;" :: "r"(dst), "l"(src))
#define CP_COMMIT() asm volatile("cp.async.commit_group;" ::: "memory")
#define CP_WAIT(n)  asm volatile("cp.async.wait_group %0;" :: "n"(n) : "memory")
#define GROUP_BAR(id) \
    asm volatile("bar.sync %0, %1;" :: "r"(id), "r"(128) : "memory")

__device__ __forceinline__ void ldsm_x4(uint32_t* r, uint32_t addr) {
    asm volatile("ldmatrix.sync.aligned.m8n8.x4.shared.b16 {%0,%1,%2,%3}, [%4];"
                 : "=r"(r[0]), "=r"(r[1]), "=r"(r[2]), "=r"(r[3]) : "r"(addr));
}
__device__ __forceinline__ void ldsm_x2(uint32_t* r, uint32_t addr) {
    asm volatile("ldmatrix.sync.aligned.m8n8.x2.shared.b16 {%0,%1}, [%2];"
                 : "=r"(r[0]), "=r"(r[1]) : "r"(addr));
}
__device__ __forceinline__ void mma_f16(float* c, const uint32_t* a, const uint32_t* b) {
    asm volatile(
        "mma.sync.aligned.m16n8k16.row.col.f32.f16.f16.f32 "
        "{%0,%1,%2,%3}, {%4,%5,%6,%7}, {%8,%9}, {%0,%1,%2,%3};"
        : "+f"(c[0]), "+f"(c[1]), "+f"(c[2]), "+f"(c[3])
        : "r"(a[0]), "r"(a[1]), "r"(a[2]), "r"(a[3]), "r"(b[0]), "r"(b[1]));
}

// ---------------- K1: row squared norms + fp16 copy ------------------------
__global__ void row_norms_kernel(const float* __restrict__ A) {
    int row = blockIdx.x;
    int t = threadIdx.x;                         // 128 threads, D/4 = 128
    const float4* a4 = (const float4*)(A + (size_t)row * D);
    float4 v = a4[t];
    __half2 h0 = __floats2half2_rn(v.x, v.y);
    __half2 h1 = __floats2half2_rn(v.z, v.w);
    uint2 q;
    q.x = *(uint32_t*)&h0; q.y = *(uint32_t*)&h1;
    *(uint2*)(g_embh + (size_t)row * D + t * 4) = q;
    float s = v.x * v.x + v.y * v.y + v.z * v.z + v.w * v.w;
    #pragma unroll
    for (int o = 16; o > 0; o >>= 1) s += __shfl_down_sync(0xffffffffu, s, o);
    __shared__ float red[4];
    if ((t & 31) == 0) red[t >> 5] = s;
    __syncthreads();
    if (t == 0) g_sq[row] = red[0] + red[1] + red[2] + red[3];
}

// ---------------- K2: fp16 mma.sync distance GEMM (symmetric) --------------
// 128x128 upper-triangular tiles (2 CTAs/SM); warp tile 64x32; K chunks of
// 64 halfs (128B SW128 rows); 3-stage cp.async, ONE sync per iteration;
// width-32 segmin epilogue.
#define BM 128
#define BN 128
#define BKC 64
#define NCHUNK (D / BKC)   // 8
#define NT 64              // tiles per side
#define NTILES 2080        // 64*65/2
#define GEMM_SPLIT 1776    // 6 waves at 296 concurrent CTAs

#define SM_SQJ   0
#define SM_SQI   512
#define SM_STAGE 1024
#define STAGE_BYTES 32768                   // A 16KB + B 16KB
#define SM_TOTAL (SM_STAGE + 3 * STAGE_BYTES)   // 99328 -> 2 CTAs/SM

static __device__ __forceinline__ uint32_t sw128(uint32_t b) { return b ^ ((b >> 3) & 0x70); }

__global__ __launch_bounds__(256, 2)
void dist_gemm_mma_kernel(int tile_base) {
    extern __shared__ char smem[];
    const uint32_t sbase = smem_u32(smem);
    const int t    = threadIdx.x;
    const int wid  = t >> 5;
    const int lane = t & 31;
    const int g    = lane >> 2;
    const int tq   = lane & 3;
    const int warpM = (wid >> 2) * 64;      // 0 or 64
    const int warpN = (wid & 3) * 32;       // 0,32,64,96

    // flat tile id -> (bi, bj), bi <= bj, square triangular
    int flat = tile_base + blockIdx.x;
    int bi = 0;
    while (flat >= NT - bi) { flat -= NT - bi; ++bi; }
    const int bj = bi + flat;
    const int rowA0 = bi * BM;
    const int colB0 = bj * BN;

    if (t < 128) {
        *(float*)(smem + SM_SQJ + t * 4) = g_sq[colB0 + t];
        *(float*)(smem + SM_SQI + t * 4) = g_sq[rowA0 + t];
    }

    const uint32_t laneRowA = (lane & 7) + ((lane >> 3) & 1) * 8;
    const uint32_t laneColA = (lane >> 4) * 16;
    const uint32_t laneRowB = lane & 7;
    const uint32_t laneColB = ((lane >> 3) & 1) * 16;

    // chunk staging: 8 x 16B cp.async per thread (A:4, B:4)
    auto issue_chunk = [&](int kt, int stg) {
        const int kc = kt * BKC;
        const uint32_t sb = sbase + SM_STAGE + (uint32_t)stg * STAGE_BYTES;
        #pragma unroll
        for (int l = 0; l < 8; l++) {
            int idx = t + l * 256;            // 0..2047
            int r   = idx >> 3;               // 0..255
            int c4  = idx & 7;                // 16B unit within 128B row
            int isA = (r < 128);
            int grow = isA ? (rowA0 + r) : (colB0 + r - 128);
            const __half* src = g_embh + (size_t)grow * D + kc + c4 * 8;
            uint32_t off = (isA ? 0u : 16384u) +
                           sw128((uint32_t)(isA ? r : r - 128) * 128u + (uint32_t)c4 * 16u);
            CP_ASYNC16(sb + off, src);
        }
        CP_COMMIT();
    };

    float acc[4][4][4];
    #pragma unroll
    for (int mt = 0; mt < 4; mt++)
        #pragma unroll
        for (int nt = 0; nt < 4; nt++)
            #pragma unroll
            for (int q = 0; q < 4; q++) acc[mt][nt][q] = 0.f;

    issue_chunk(0, 0);
    issue_chunk(1, 1);

    // ONE __syncthreads per iteration: the top sync of iteration kt orders all
    // warps' reads of stage (kt+2)%3 (done in iteration kt-1) before the
    // cp.async writes issued here into that same stage.
    #pragma unroll 1
    for (int kt = 0; kt < NCHUNK; kt++) {
        const int stg = kt % 3;
        CP_WAIT(1);
        __syncthreads();
        if (kt + 2 < NCHUNK) issue_chunk(kt + 2, (kt + 2) % 3);

        const uint32_t abase = sbase + SM_STAGE + (uint32_t)stg * STAGE_BYTES;
        const uint32_t bbase = abase + 16384u;
        #pragma unroll
        for (int ks = 0; ks < 4; ks++) {       // 4 k-steps of 16 halfs (32B)
            uint32_t af[4][4], bf[4][2];
            #pragma unroll
            for (int mt = 0; mt < 4; mt++) {
                uint32_t byte = (uint32_t)(warpM + mt * 16 + laneRowA) * 128u +
                                (uint32_t)ks * 32u + laneColA;
                ldsm_x4(af[mt], abase + sw128(byte));
            }
            #pragma unroll
            for (int nt = 0; nt < 4; nt++) {
                uint32_t byte = (uint32_t)(warpN + nt * 8 + laneRowB) * 128u +
                                (uint32_t)ks * 32u + laneColB;
                ldsm_x2(bf[nt], bbase + sw128(byte));
            }
            #pragma unroll
            for (int mt = 0; mt < 4; mt++)
                #pragma unroll
                for (int nt = 0; nt < 4; nt++)
                    mma_f16(acc[mt][nt], af[mt], bf[nt]);
        }
    }

    // ---- epilogue: distances; direct + mirror stores + 32-wide segmins ----
    const float* sqj = (const float*)(smem + SM_SQJ);
    const float* sqi = (const float*)(smem + SM_SQI);
    float rmin[4][2];                       // per-row mins over warp's 32 cols
    float cmin[2][4][2];                    // [32-row half][nt][p]
    #pragma unroll
    for (int mt = 0; mt < 4; mt++) { rmin[mt][0] = FLT_MAX; rmin[mt][1] = FLT_MAX; }
    #pragma unroll
    for (int mp = 0; mp < 2; mp++)
        #pragma unroll
        for (int nt = 0; nt < 4; nt++) { cmin[mp][nt][0] = FLT_MAX; cmin[mp][nt][1] = FLT_MAX; }

    #pragma unroll
    for (int mt = 0; mt < 4; mt++) {
        const int r0 = warpM + mt * 16 + g;
        const int r1 = r0 + 8;
        const int gr0 = rowA0 + r0, gr1 = rowA0 + r1;
        const float si0 = sqi[r0], si1 = sqi[r1];
        #pragma unroll
        for (int nt = 0; nt < 4; nt++) {
            const int cl = warpN + nt * 8 + tq * 2;
            const int gc = colB0 + cl;
            const float sj0 = sqj[cl], sj1 = sqj[cl + 1];
            float d2;
            float2 o0, o1;
            d2 = si0 + sj0 - 2.f * acc[mt][nt][0];
            o0.x = (d2 > 0.f) ? sqrtf(fmaxf(d2, 1e-12f)) : 0.f;
            d2 = si0 + sj1 - 2.f * acc[mt][nt][1];
            o0.y = (d2 > 0.f) ? sqrtf(fmaxf(d2, 1e-12f)) : 0.f;
            d2 = si1 + sj0 - 2.f * acc[mt][nt][2];
            o1.x = (d2 > 0.f) ? sqrtf(fmaxf(d2, 1e-12f)) : 0.f;
            d2 = si1 + sj1 - 2.f * acc[mt][nt][3];
            o1.y = (d2 > 0.f) ? sqrtf(fmaxf(d2, 1e-12f)) : 0.f;
            *(float2*)(g_dist + (size_t)gr0 * N + gc) = o0;
            *(float2*)(g_dist + (size_t)gr1 * N + gc) = o1;
            g_dist[(size_t)gc * N + gr0]       = o0.x;
            g_dist[(size_t)gc * N + gr1]       = o1.x;
            g_dist[(size_t)(gc + 1) * N + gr0] = o0.y;
            g_dist[(size_t)(gc + 1) * N + gr1] = o1.y;
            rmin[mt][0] = fminf(rmin[mt][0], fminf(o0.x, o0.y));
            rmin[mt][1] = fminf(rmin[mt][1], fminf(o1.x, o1.y));
            cmin[mt >> 1][nt][0] = fminf(cmin[mt >> 1][nt][0], fminf(o0.x, o1.x));
            cmin[mt >> 1][nt][1] = fminf(cmin[mt >> 1][nt][1], fminf(o0.y, o1.y));
        }
    }

    // row segment mins (width 32): reduce over tq lanes (same g)
    const int rseg = (colB0 + warpN) >> 5;
    #pragma unroll
    for (int mt = 0; mt < 4; mt++) {
        #pragma unroll
        for (int h = 0; h < 2; h++) {
            float x = rmin[mt][h];
            x = fminf(x, __shfl_xor_sync(0xffffffffu, x, 1));
            x = fminf(x, __shfl_xor_sync(0xffffffffu, x, 2));
            if (tq == 0) {
                const int gr = rowA0 + warpM + mt * 16 + g + h * 8;
                g_segmin[(size_t)gr * 256 + rseg] = x;
            }
        }
    }
    // col segment mins (width 32 of rows): reduce over g lanes (same tq)
    #pragma unroll
    for (int mp = 0; mp < 2; mp++) {
        const int cseg = (rowA0 + warpM + mp * 32) >> 5;
        #pragma unroll
        for (int nt = 0; nt < 4; nt++) {
            #pragma unroll
            for (int p = 0; p < 2; p++) {
                float x = cmin[mp][nt][p];
                x = fminf(x, __shfl_xor_sync(0xffffffffu, x, 4));
                x = fminf(x, __shfl_xor_sync(0xffffffffu, x, 8));
                x = fminf(x, __shfl_xor_sync(0xffffffffu, x, 16));
                if (g == 0) {
                    const int gc = colB0 + warpN + nt * 8 + tq * 2 + p;
                    g_segmin[(size_t)gc * 256 + cseg] = x;
                }
            }
        }
    }
}

// ---------------- K3: 32-wide segment-pruned top-16, 2 rows per block ------
// Each warp owns 64 raw 32-wide segmins (2/lane); T = max of the 4 warps'
// 5th-smallest -> >=20 distinct elements <= T -> >=19 non-self (safe bound).
// Qualify individual 32-wide segments -> ~half the scan volume of 64-wide.
__global__ __launch_bounds__(256)
void topk_kernel() {
    const int t    = threadIdx.x;
    const int grp  = t >> 7;              // 0 or 1
    const int gt   = t & 127;             // thread within group
    const int lane = t & 31;
    const int gw   = (t >> 5) & 3;        // warp within group
    const int i    = blockIdx.x * 2 + grp;

    __shared__ float warp5[2][4];
    __shared__ short segs[2][256];
    __shared__ int   s_scnt[2];
    __shared__ float bufv[2][1024];
    __shared__ int   bufi[2][1024];
    __shared__ int   s_bcnt[2];

    if (gt == 0) { s_scnt[grp] = 0; s_bcnt[grp] = 0; }

    // two 32-wide segmins per thread: segs 2*gt and 2*gt+1
    const float2 sp = *(const float2*)(g_segmin + (size_t)i * 256 + 2 * gt);

    // each warp: 5th-smallest of its 64 segmins (keyed, duplicate-safe)
    {
        unsigned long long k0 =
            ((unsigned long long)__float_as_uint(sp.x) << 32) | (unsigned)(2 * gt);
        unsigned long long k1 =
            ((unsigned long long)__float_as_uint(sp.y) << 32) | (unsigned)(2 * gt + 1);
        float fifth = FLT_MAX;
        #pragma unroll
        for (int r = 0; r < 5; r++) {
            unsigned long long k2 = (k0 < k1) ? k0 : k1;
            #pragma unroll
            for (int o = 16; o > 0; o >>= 1) {
                unsigned long long other = __shfl_xor_sync(0xffffffffu, k2, o);
                k2 = (other < k2) ? other : k2;
            }
            if (k0 == k2) k0 = ~0ULL;
            else if (k1 == k2) k1 = ~0ULL;
            fifth = __uint_as_float((uint32_t)(k2 >> 32));
        }
        if (lane == 0) warp5[grp][gw] = fifth;
    }
    GROUP_BAR(grp + 1);
    const float T = fmaxf(fmaxf(warp5[grp][0], warp5[grp][1]),
                          fmaxf(warp5[grp][2], warp5[grp][3]));

    // qualify individual 32-wide segments
    if (sp.x <= T) { int e = atomicAdd(&s_scnt[grp], 1); segs[grp][e] = (short)(2 * gt); }
    if (sp.y <= T) { int e = atomicAdd(&s_scnt[grp], 1); segs[grp][e] = (short)(2 * gt + 1); }
    GROUP_BAR(grp + 1);
    const int nseg = s_scnt[grp];

    const float* __restrict__ drow = g_dist + (size_t)i * N;
    const int total = nseg * 32;
    for (int e = gt; e < total; e += 128) {
        const int j = ((int)segs[grp][e >> 5] << 5) | (e & 31);
        const float dv = drow[j];
        if (dv <= T && j != i) {
            int b = atomicAdd(&s_bcnt[grp], 1);
            if (b < 1024) { bufv[grp][b] = dv; bufi[grp][b] = j; }
        }
    }
    GROUP_BAR(grp + 1);
    const int n_e = (s_bcnt[grp] < 1024) ? s_bcnt[grp] : 1024;

    // rank selection (keys unique by col; ties by col like lax.top_k)
    for (int e = gt; e < n_e; e += 128) {
        const unsigned long long mykey =
            ((unsigned long long)__float_as_uint(bufv[grp][e]) << 32) | (unsigned)bufi[grp][e];
        int rank = 0;
        for (int q = 0; q < n_e; q++) {
            const unsigned long long k =
                ((unsigned long long)__float_as_uint(bufv[grp][q]) << 32) | (unsigned)bufi[grp][q];
            rank += (k < mykey);
        }
        if (rank < KNN) {
            g_knn_d[i * KNN + rank]   = bufv[grp][e];
            g_knn_idx[i * KNN + rank] = bufi[grp][e];
        }
    }
}

// ---------------- K4: curvature, warp per point -----------------------------
__global__ __launch_bounds__(256)
void curvature_kernel(const float* __restrict__ ref_curv) {
    const int w    = threadIdx.x >> 5;
    const int lane = threadIdx.x & 31;
    const int i    = blockIdx.x * 8 + w;

    int   myidx = 0;
    float myd   = 0.f;
    if (lane < KNN) {
        myidx = g_knn_idx[i * KNN + lane];
        myd   = g_knn_d[i * KNN + lane];
    }

    float dsum = myd;
    #pragma unroll
    for (int o = 16; o > 0; o >>= 1)
        dsum += __shfl_xor_sync(0xffffffffu, dsum, o);

    float isum = 0.f;
    #pragma unroll
    for (int u = 0; u < 4; u++) {
        const int p = lane + u * 32;
        const bool act = (p < NPAIRS);
        int L = act ? p : 0;
        int j = 0;
        while (L >= 15 - j) { L -= 15 - j; j++; }
        const int k = j + 1 + L;
        const int ij = __shfl_sync(0xffffffffu, myidx, j);
        const int ik = __shfl_sync(0xffffffffu, myidx, k);
        if (act) isum += g_dist[(size_t)ij * N + ik];
    }
    #pragma unroll
    for (int o = 16; o > 0; o >>= 1)
        isum += __shfl_xor_sync(0xffffffffu, isum, o);

    if (lane == 0) {
        const float avg        = dsum / (float)KNN;
        const float inter_mean = isum / (float)NPAIRS;
        const float curv       = inter_mean / (avg + 1e-8f);
        const float diff       = curv - ref_curv[i];
        g_curv_err[i] = diff * diff;
        g_knn_sum[i]  = dsum;
    }
}

// ---------------- K5: final scalar, two-stage (deterministic) --------------
__global__ void final_stage1(const float* __restrict__ ref_dist) {
    const int t = threadIdx.x;               // 256 threads, 32 blocks
    const int b = blockIdx.x;
    const int gid = b * 256 + t;             // 0..8191
    double e  = (double)g_curv_err[gid];
    double kk = (double)g_knn_sum[gid];
    double rf = 0.0;
    for (int u = gid; u < N * KNN; u += 8192) rf += (double)ref_dist[u];
    __shared__ double d1[256], d2[256], d3[256];
    d1[t] = e; d2[t] = kk; d3[t] = rf;
    __syncthreads();
    for (int s = 128; s > 0; s >>= 1) {
        if (t < s) { d1[t] += d1[t + s]; d2[t] += d2[t + s]; d3[t] += d3[t + s]; }
        __syncthreads();
    }
    if (t == 0) {
        g_part[b][0] = d1[0]; g_part[b][1] = d2[0]; g_part[b][2] = d3[0];
    }
}

__global__ void final_stage2(float* __restrict__ out) {
    const int t = threadIdx.x;               // 32 threads (1 warp)
    double e  = g_part[t][0];
    double kk = g_part[t][1];
    double rf = g_part[t][2];
    #pragma unroll
    for (int o = 16; o > 0; o >>= 1) {
        e  += __shfl_down_sync(0xffffffffu, e,  o);
        kk += __shfl_down_sync(0xffffffffu, kk, o);
        rf += __shfl_down_sync(0xffffffffu, rf, o);
    }
    if (t == 0) {
        double curv_loss = e / (double)N;
        double m_knn = kk / (double)(N * KNN);
        double m_ref = rf / (double)(N * KNN);
        double diff  = m_knn - m_ref;
        out[0] = (float)(curv_loss + 0.1 * diff * diff);
    }
}

// ---------------- launch ----------------------------------------------------
extern "C" void kernel_launch(void* const* d_in, const int* in_sizes, int n_in,
                              void* d_out, int out_size) {
    const float* emb      = (const float*)d_in[0];   // [N, D]
    const float* ref_curv = (const float*)d_in[1];   // [N]
    const float* ref_dist = (const float*)d_in[2];   // [N, K]
    float* out = (float*)d_out;

    static int smem_set = 0;
    if (!smem_set) {
        cudaFuncSetAttribute(dist_gemm_mma_kernel,
                             cudaFuncAttributeMaxDynamicSharedMemorySize, SM_TOTAL);
        smem_set = 1;
    }

    row_norms_kernel<<<N, 128>>>(emb);
    dist_gemm_mma_kernel<<<GEMM_SPLIT, 256, SM_TOTAL>>>(0);
    dist_gemm_mma_kernel<<<NTILES - GEMM_SPLIT, 256, SM_TOTAL>>>(GEMM_SPLIT);
    topk_kernel<<<N / 2, 256>>>();
    curvature_kernel<<<N / 8, 256>>>(ref_curv);
    final_stage1<<<32, 256>>>(ref_dist);
    final_stage2<<<1, 32>>>(out);
}

// round 15
// speedup vs baseline: 4.8161x; 1.0350x over previous
#include <cuda_runtime.h>
#include <cuda_fp16.h>
#include <math.h>
#include <float.h>
#include <stdint.h>

#define N 8192
#define D 512
#define KNN 16
#define NPAIRS 120   // 16*15/2

// ---------------- scratch (device globals; no runtime allocation) ----------
__device__ float  g_sq[N];
__device__ __half g_embh[(size_t)N * D];    // fp16 (rn) copy of embeddings
__device__ float  g_dist[(size_t)N * N];    // 256 MB full symmetric distance matrix
__device__ float  g_segmin[(size_t)N * 256];// per-row min over 32-col segments
__device__ float  g_curv_err[N];
__device__ float  g_knn_sum[N];
__device__ double g_part[32][3];            // two-stage final reduction

// ---------------- PTX helpers ----------------------------------------------
__device__ __forceinline__ uint32_t smem_u32(const void* p) {
    uint32_t a;
    asm("{ .reg .u64 t; cvta.to.shared.u64 t, %1; cvt.u32.u64 %0, t; }" : "=r"(a) : "l"(p));
    return a;
}
#define CP_ASYNC16(dst, src) \
    asm volatile("cp.async.cg.shared.global [%0], [%1], 16;" :: "r"(dst), "l"(src))
#define CP_COMMIT() asm volatile("cp.async.commit_group;" ::: "memory")
#define CP_WAIT(n)  asm volatile("cp.async.wait_group %0;" :: "n"(n) : "memory")
#define BAR64(id) \
    asm volatile("bar.sync %0, %1;" :: "r"(id), "r"(64) : "memory")

__device__ __forceinline__ void ldsm_x4(uint32_t* r, uint32_t addr) {
    asm volatile("ldmatrix.sync.aligned.m8n8.x4.shared.b16 {%0,%1,%2,%3}, [%4];"
                 : "=r"(r[0]), "=r"(r[1]), "=r"(r[2]), "=r"(r[3]) : "r"(addr));
}
__device__ __forceinline__ void ldsm_x2(uint32_t* r, uint32_t addr) {
    asm volatile("ldmatrix.sync.aligned.m8n8.x2.shared.b16 {%0,%1}, [%2];"
                 : "=r"(r[0]), "=r"(r[1]) : "r"(addr));
}
__device__ __forceinline__ void mma_f16(float* c, const uint32_t* a, const uint32_t* b) {
    asm volatile(
        "mma.sync.aligned.m16n8k16.row.col.f32.f16.f16.f32 "
        "{%0,%1,%2,%3}, {%4,%5,%6,%7}, {%8,%9}, {%0,%1,%2,%3};"
        : "+f"(c[0]), "+f"(c[1]), "+f"(c[2]), "+f"(c[3])
        : "r"(a[0]), "r"(a[1]), "r"(a[2]), "r"(a[3]), "r"(b[0]), "r"(b[1]));
}

// ---------------- K1: row squared norms + fp16 copy ------------------------
__global__ void row_norms_kernel(const float* __restrict__ A) {
    int row = blockIdx.x;
    int t = threadIdx.x;                         // 128 threads, D/4 = 128
    const float4* a4 = (const float4*)(A + (size_t)row * D);
    float4 v = a4[t];
    __half2 h0 = __floats2half2_rn(v.x, v.y);
    __half2 h1 = __floats2half2_rn(v.z, v.w);
    uint2 q;
    q.x = *(uint32_t*)&h0; q.y = *(uint32_t*)&h1;
    *(uint2*)(g_embh + (size_t)row * D + t * 4) = q;
    float s = v.x * v.x + v.y * v.y + v.z * v.z + v.w * v.w;
    #pragma unroll
    for (int o = 16; o > 0; o >>= 1) s += __shfl_down_sync(0xffffffffu, s, o);
    __shared__ float red[4];
    if ((t & 31) == 0) red[t >> 5] = s;
    __syncthreads();
    if (t == 0) g_sq[row] = red[0] + red[1] + red[2] + red[3];
}

// ---------------- K2: fp16 mma.sync distance GEMM (symmetric) --------------
#define BM 128
#define BN 128
#define BKC 64
#define NCHUNK (D / BKC)   // 8
#define NT 64              // tiles per side
#define NTILES 2080        // 64*65/2
#define GEMM_SPLIT 1776    // 6 waves at 296 concurrent CTAs

#define SM_SQJ   0
#define SM_SQI   512
#define SM_STAGE 1024
#define STAGE_BYTES 32768                   // A 16KB + B 16KB
#define SM_TOTAL (SM_STAGE + 3 * STAGE_BYTES)   // 99328 -> 2 CTAs/SM

static __device__ __forceinline__ uint32_t sw128(uint32_t b) { return b ^ ((b >> 3) & 0x70); }

__global__ __launch_bounds__(256, 2)
void dist_gemm_mma_kernel(int tile_base) {
    extern __shared__ char smem[];
    const uint32_t sbase = smem_u32(smem);
    const int t    = threadIdx.x;
    const int wid  = t >> 5;
    const int lane = t & 31;
    const int g    = lane >> 2;
    const int tq   = lane & 3;
    const int warpM = (wid >> 2) * 64;      // 0 or 64
    const int warpN = (wid & 3) * 32;       // 0,32,64,96

    int flat = tile_base + blockIdx.x;
    int bi = 0;
    while (flat >= NT - bi) { flat -= NT - bi; ++bi; }
    const int bj = bi + flat;
    const int rowA0 = bi * BM;
    const int colB0 = bj * BN;

    if (t < 128) {
        *(float*)(smem + SM_SQJ + t * 4) = g_sq[colB0 + t];
        *(float*)(smem + SM_SQI + t * 4) = g_sq[rowA0 + t];
    }

    const uint32_t laneRowA = (lane & 7) + ((lane >> 3) & 1) * 8;
    const uint32_t laneColA = (lane >> 4) * 16;
    const uint32_t laneRowB = lane & 7;
    const uint32_t laneColB = ((lane >> 3) & 1) * 16;

    auto issue_chunk = [&](int kt, int stg) {
        const int kc = kt * BKC;
        const uint32_t sb = sbase + SM_STAGE + (uint32_t)stg * STAGE_BYTES;
        #pragma unroll
        for (int l = 0; l < 8; l++) {
            int idx = t + l * 256;            // 0..2047
            int r   = idx >> 3;               // 0..255
            int c4  = idx & 7;                // 16B unit within 128B row
            int isA = (r < 128);
            int grow = isA ? (rowA0 + r) : (colB0 + r - 128);
            const __half* src = g_embh + (size_t)grow * D + kc + c4 * 8;
            uint32_t off = (isA ? 0u : 16384u) +
                           sw128((uint32_t)(isA ? r : r - 128) * 128u + (uint32_t)c4 * 16u);
            CP_ASYNC16(sb + off, src);
        }
        CP_COMMIT();
    };

    float acc[4][4][4];
    #pragma unroll
    for (int mt = 0; mt < 4; mt++)
        #pragma unroll
        for (int nt = 0; nt < 4; nt++)
            #pragma unroll
            for (int q = 0; q < 4; q++) acc[mt][nt][q] = 0.f;

    issue_chunk(0, 0);
    issue_chunk(1, 1);

    #pragma unroll 1
    for (int kt = 0; kt < NCHUNK; kt++) {
        const int stg = kt % 3;
        CP_WAIT(1);
        __syncthreads();
        if (kt + 2 < NCHUNK) issue_chunk(kt + 2, (kt + 2) % 3);

        const uint32_t abase = sbase + SM_STAGE + (uint32_t)stg * STAGE_BYTES;
        const uint32_t bbase = abase + 16384u;
        #pragma unroll
        for (int ks = 0; ks < 4; ks++) {       // 4 k-steps of 16 halfs (32B)
            uint32_t af[4][4], bf[4][2];
            #pragma unroll
            for (int mt = 0; mt < 4; mt++) {
                uint32_t byte = (uint32_t)(warpM + mt * 16 + laneRowA) * 128u +
                                (uint32_t)ks * 32u + laneColA;
                ldsm_x4(af[mt], abase + sw128(byte));
            }
            #pragma unroll
            for (int nt = 0; nt < 4; nt++) {
                uint32_t byte = (uint32_t)(warpN + nt * 8 + laneRowB) * 128u +
                                (uint32_t)ks * 32u + laneColB;
                ldsm_x2(bf[nt], bbase + sw128(byte));
            }
            #pragma unroll
            for (int mt = 0; mt < 4; mt++)
                #pragma unroll
                for (int nt = 0; nt < 4; nt++)
                    mma_f16(acc[mt][nt], af[mt], bf[nt]);
        }
    }

    // ---- epilogue: distances; direct + mirror stores + 32-wide segmins ----
    const float* sqj = (const float*)(smem + SM_SQJ);
    const float* sqi = (const float*)(smem + SM_SQI);
    float rmin[4][2];
    float cmin[2][4][2];
    #pragma unroll
    for (int mt = 0; mt < 4; mt++) { rmin[mt][0] = FLT_MAX; rmin[mt][1] = FLT_MAX; }
    #pragma unroll
    for (int mp = 0; mp < 2; mp++)
        #pragma unroll
        for (int nt = 0; nt < 4; nt++) { cmin[mp][nt][0] = FLT_MAX; cmin[mp][nt][1] = FLT_MAX; }

    #pragma unroll
    for (int mt = 0; mt < 4; mt++) {
        const int r0 = warpM + mt * 16 + g;
        const int r1 = r0 + 8;
        const int gr0 = rowA0 + r0, gr1 = rowA0 + r1;
        const float si0 = sqi[r0], si1 = sqi[r1];
        #pragma unroll
        for (int nt = 0; nt < 4; nt++) {
            const int cl = warpN + nt * 8 + tq * 2;
            const int gc = colB0 + cl;
            const float sj0 = sqj[cl], sj1 = sqj[cl + 1];
            float d2;
            float2 o0, o1;
            d2 = si0 + sj0 - 2.f * acc[mt][nt][0];
            o0.x = (d2 > 0.f) ? sqrtf(fmaxf(d2, 1e-12f)) : 0.f;
            d2 = si0 + sj1 - 2.f * acc[mt][nt][1];
            o0.y = (d2 > 0.f) ? sqrtf(fmaxf(d2, 1e-12f)) : 0.f;
            d2 = si1 + sj0 - 2.f * acc[mt][nt][2];
            o1.x = (d2 > 0.f) ? sqrtf(fmaxf(d2, 1e-12f)) : 0.f;
            d2 = si1 + sj1 - 2.f * acc[mt][nt][3];
            o1.y = (d2 > 0.f) ? sqrtf(fmaxf(d2, 1e-12f)) : 0.f;
            *(float2*)(g_dist + (size_t)gr0 * N + gc) = o0;
            *(float2*)(g_dist + (size_t)gr1 * N + gc) = o1;
            g_dist[(size_t)gc * N + gr0]       = o0.x;
            g_dist[(size_t)gc * N + gr1]       = o1.x;
            g_dist[(size_t)(gc + 1) * N + gr0] = o0.y;
            g_dist[(size_t)(gc + 1) * N + gr1] = o1.y;
            rmin[mt][0] = fminf(rmin[mt][0], fminf(o0.x, o0.y));
            rmin[mt][1] = fminf(rmin[mt][1], fminf(o1.x, o1.y));
            cmin[mt >> 1][nt][0] = fminf(cmin[mt >> 1][nt][0], fminf(o0.x, o1.x));
            cmin[mt >> 1][nt][1] = fminf(cmin[mt >> 1][nt][1], fminf(o0.y, o1.y));
        }
    }

    const int rseg = (colB0 + warpN) >> 5;
    #pragma unroll
    for (int mt = 0; mt < 4; mt++) {
        #pragma unroll
        for (int h = 0; h < 2; h++) {
            float x = rmin[mt][h];
            x = fminf(x, __shfl_xor_sync(0xffffffffu, x, 1));
            x = fminf(x, __shfl_xor_sync(0xffffffffu, x, 2));
            if (tq == 0) {
                const int gr = rowA0 + warpM + mt * 16 + g + h * 8;
                g_segmin[(size_t)gr * 256 + rseg] = x;
            }
        }
    }
    #pragma unroll
    for (int mp = 0; mp < 2; mp++) {
        const int cseg = (rowA0 + warpM + mp * 32) >> 5;
        #pragma unroll
        for (int nt = 0; nt < 4; nt++) {
            #pragma unroll
            for (int p = 0; p < 2; p++) {
                float x = cmin[mp][nt][p];
                x = fminf(x, __shfl_xor_sync(0xffffffffu, x, 4));
                x = fminf(x, __shfl_xor_sync(0xffffffffu, x, 8));
                x = fminf(x, __shfl_xor_sync(0xffffffffu, x, 16));
                if (g == 0) {
                    const int gc = colB0 + warpN + nt * 8 + tq * 2 + p;
                    g_segmin[(size_t)gc * 256 + cseg] = x;
                }
            }
        }
    }
}

// ---------------- K3: fused top-16 + curvature, 4 rows per block ------------
// 64-thread groups (2 warps/row). Each warp owns 128 segmins (4/lane) and
// extracts its 9th-smallest; T = max of the two 9ths -> >=18 distinct
// elements <= T -> >=17 incl self -> >=16 non-self (safe bound on 16th NN).
// After rank selection the group's warp 0 computes curvature in-place.
#define BUFCAP 768

__global__ __launch_bounds__(256)
void topk_curv_kernel(const float* __restrict__ ref_curv) {
    const int t    = threadIdx.x;
    const int grp  = t >> 6;              // 0..3
    const int gt   = t & 63;              // thread within group
    const int lane = t & 31;
    const int gw   = (t >> 5) & 1;        // warp within group
    const int i    = blockIdx.x * 4 + grp;

    __shared__ float warp9[4][2];
    __shared__ short segs[4][256];
    __shared__ int   s_scnt[4];
    __shared__ float bufv[4][BUFCAP];
    __shared__ int   bufi[4][BUFCAP];
    __shared__ int   s_bcnt[4];
    __shared__ float knnv[4][KNN];
    __shared__ int   knni[4][KNN];

    if (gt == 0) { s_scnt[grp] = 0; s_bcnt[grp] = 0; }

    // 4 segmins per thread: segs 4*gt .. 4*gt+3
    const float4 sp = *(const float4*)(g_segmin + (size_t)i * 256 + 4 * gt);
    const float spv[4] = {sp.x, sp.y, sp.z, sp.w};

    // each warp: 9th-smallest of its 128 segmins (keyed, duplicate-safe)
    {
        unsigned long long k[4];
        #pragma unroll
        for (int c = 0; c < 4; c++)
            k[c] = ((unsigned long long)__float_as_uint(spv[c]) << 32)
                 | (unsigned)(4 * gt + c);
        float ninth = FLT_MAX;
        #pragma unroll
        for (int r = 0; r < 9; r++) {
            unsigned long long kmin = k[0];
            #pragma unroll
            for (int c = 1; c < 4; c++) kmin = (k[c] < kmin) ? k[c] : kmin;
            #pragma unroll
            for (int o = 16; o > 0; o >>= 1) {
                unsigned long long other = __shfl_xor_sync(0xffffffffu, kmin, o);
                kmin = (other < kmin) ? other : kmin;
            }
            #pragma unroll
            for (int c = 0; c < 4; c++) if (k[c] == kmin) k[c] = ~0ULL;
            ninth = __uint_as_float((uint32_t)(kmin >> 32));
        }
        if (lane == 0) warp9[grp][gw] = ninth;
    }
    BAR64(grp + 1);
    const float T = fmaxf(warp9[grp][0], warp9[grp][1]);

    // qualify individual 32-wide segments
    #pragma unroll
    for (int c = 0; c < 4; c++) {
        if (spv[c] <= T) {
            int e = atomicAdd(&s_scnt[grp], 1);
            segs[grp][e] = (short)(4 * gt + c);
        }
    }
    BAR64(grp + 1);
    const int nseg = s_scnt[grp];

    // pruned scan
    const float* __restrict__ drow = g_dist + (size_t)i * N;
    const int total = nseg * 32;
    for (int e = gt; e < total; e += 64) {
        const int j = ((int)segs[grp][e >> 5] << 5) | (e & 31);
        const float dv = drow[j];
        if (dv <= T && j != i) {
            int b = atomicAdd(&s_bcnt[grp], 1);
            if (b < BUFCAP) { bufv[grp][b] = dv; bufi[grp][b] = j; }
        }
    }
    BAR64(grp + 1);
    const int n_e = (s_bcnt[grp] < BUFCAP) ? s_bcnt[grp] : BUFCAP;

    // rank selection into smem knn (keys unique by col; ties by col)
    for (int e = gt; e < n_e; e += 64) {
        const unsigned long long mykey =
            ((unsigned long long)__float_as_uint(bufv[grp][e]) << 32) | (unsigned)bufi[grp][e];
        int rank = 0;
        for (int q = 0; q < n_e; q++) {
            const unsigned long long k =
                ((unsigned long long)__float_as_uint(bufv[grp][q]) << 32) | (unsigned)bufi[grp][q];
            rank += (k < mykey);
        }
        if (rank < KNN) {
            knnv[grp][rank] = bufv[grp][e];
            knni[grp][rank] = bufi[grp][e];
        }
    }
    BAR64(grp + 1);

    // fused curvature: warp 0 of the group
    if (gw == 0) {
        int   myidx = 0;
        float myd   = 0.f;
        if (lane < KNN) { myidx = knni[grp][lane]; myd = knnv[grp][lane]; }

        float dsum = myd;
        #pragma unroll
        for (int o = 16; o > 0; o >>= 1)
            dsum += __shfl_xor_sync(0xffffffffu, dsum, o);

        float isum = 0.f;
        #pragma unroll
        for (int u = 0; u < 4; u++) {
            const int p = lane + u * 32;
            const bool act = (p < NPAIRS);
            int L = act ? p : 0;
            int j = 0;
            while (L >= 15 - j) { L -= 15 - j; j++; }
            const int k = j + 1 + L;
            const int ij = __shfl_sync(0xffffffffu, myidx, j);
            const int ik = __shfl_sync(0xffffffffu, myidx, k);
            if (act) isum += g_dist[(size_t)ij * N + ik];
        }
        #pragma unroll
        for (int o = 16; o > 0; o >>= 1)
            isum += __shfl_xor_sync(0xffffffffu, isum, o);

        if (lane == 0) {
            const float avg        = dsum / (float)KNN;
            const float inter_mean = isum / (float)NPAIRS;
            const float curv       = inter_mean / (avg + 1e-8f);
            const float diff       = curv - ref_curv[i];
            g_curv_err[i] = diff * diff;
            g_knn_sum[i]  = dsum;
        }
    }
}

// ---------------- K5: final scalar, two-stage (deterministic) --------------
__global__ void final_stage1(const float* __restrict__ ref_dist) {
    const int t = threadIdx.x;               // 256 threads, 32 blocks
    const int b = blockIdx.x;
    const int gid = b * 256 + t;             // 0..8191
    double e  = (double)g_curv_err[gid];
    double kk = (double)g_knn_sum[gid];
    double rf = 0.0;
    for (int u = gid; u < N * KNN; u += 8192) rf += (double)ref_dist[u];
    __shared__ double d1[256], d2[256], d3[256];
    d1[t] = e; d2[t] = kk; d3[t] = rf;
    __syncthreads();
    for (int s = 128; s > 0; s >>= 1) {
        if (t < s) { d1[t] += d1[t + s]; d2[t] += d2[t + s]; d3[t] += d3[t + s]; }
        __syncthreads();
    }
    if (t == 0) {
        g_part[b][0] = d1[0]; g_part[b][1] = d2[0]; g_part[b][2] = d3[0];
    }
}

__global__ void final_stage2(float* __restrict__ out) {
    const int t = threadIdx.x;               // 32 threads (1 warp)
    double e  = g_part[t][0];
    double kk = g_part[t][1];
    double rf = g_part[t][2];
    #pragma unroll
    for (int o = 16; o > 0; o >>= 1) {
        e  += __shfl_down_sync(0xffffffffu, e,  o);
        kk += __shfl_down_sync(0xffffffffu, kk, o);
        rf += __shfl_down_sync(0xffffffffu, rf, o);
    }
    if (t == 0) {
        double curv_loss = e / (double)N;
        double m_knn = kk / (double)(N * KNN);
        double m_ref = rf / (double)(N * KNN);
        double diff  = m_knn - m_ref;
        out[0] = (float)(curv_loss + 0.1 * diff * diff);
    }
}

// ---------------- launch ----------------------------------------------------
extern "C" void kernel_launch(void* const* d_in, const int* in_sizes, int n_in,
                              void* d_out, int out_size) {
    const float* emb      = (const float*)d_in[0];   // [N, D]
    const float* ref_curv = (const float*)d_in[1];   // [N]
    const float* ref_dist = (const float*)d_in[2];   // [N, K]
    float* out = (float*)d_out;

    static int smem_set = 0;
    if (!smem_set) {
        cudaFuncSetAttribute(dist_gemm_mma_kernel,
                             cudaFuncAttributeMaxDynamicSharedMemorySize, SM_TOTAL);
        smem_set = 1;
    }

    row_norms_kernel<<<N, 128>>>(emb);
    dist_gemm_mma_kernel<<<GEMM_SPLIT, 256, SM_TOTAL>>>(0);
    dist_gemm_mma_kernel<<<NTILES - GEMM_SPLIT, 256, SM_TOTAL>>>(GEMM_SPLIT);
    topk_curv_kernel<<<N / 4, 256>>>(ref_curv);
    final_stage1<<<32, 256>>>(ref_dist);
    final_stage2<<<1, 32>>>(out);
}

// round 16
// speedup vs baseline: 5.1040x; 1.0598x over previous
#include <cuda_runtime.h>
#include <cuda_fp16.h>
#include <math.h>
#include <float.h>
#include <stdint.h>

#define N 8192
#define D 512
#define KNN 16
#define NPAIRS 120   // 16*15/2

// ---------------- scratch (device globals; no runtime allocation) ----------
__device__ float  g_sq[N];
__device__ __half g_embh[(size_t)N * D];    // fp16 (rn) copy of embeddings
__device__ float  g_dist[(size_t)N * N];    // 256 MB full symmetric distance matrix
__device__ float  g_segmin[(size_t)N * 256];// per-row min over 32-col segments
__device__ float  g_curv_err[N];
__device__ float  g_knn_sum[N];
__device__ double g_part[32][3];            // two-stage final reduction

// ---------------- PTX helpers ----------------------------------------------
__device__ __forceinline__ uint32_t smem_u32(const void* p) {
    uint32_t a;
    asm("{ .reg .u64 t; cvta.to.shared.u64 t, %1; cvt.u32.u64 %0, t; }" : "=r"(a) : "l"(p));
    return a;
}
#define CP_ASYNC16(dst, src) \
    asm volatile("cp.async.cg.shared.global [%0], [%1], 16;" :: "r"(dst), "l"(src))
#define CP_COMMIT() asm volatile("cp.async.commit_group;" ::: "memory")
#define CP_WAIT(n)  asm volatile("cp.async.wait_group %0;" :: "n"(n) : "memory")
#define BAR64(id) \
    asm volatile("bar.sync %0, %1;" :: "r"(id), "r"(64) : "memory")

__device__ __forceinline__ void ldsm_x4(uint32_t* r, uint32_t addr) {
    asm volatile("ldmatrix.sync.aligned.m8n8.x4.shared.b16 {%0,%1,%2,%3}, [%4];"
                 : "=r"(r[0]), "=r"(r[1]), "=r"(r[2]), "=r"(r[3]) : "r"(addr));
}
__device__ __forceinline__ void ldsm_x2(uint32_t* r, uint32_t addr) {
    asm volatile("ldmatrix.sync.aligned.m8n8.x2.shared.b16 {%0,%1}, [%2];"
                 : "=r"(r[0]), "=r"(r[1]) : "r"(addr));
}
__device__ __forceinline__ void mma_f16(float* c, const uint32_t* a, const uint32_t* b) {
    asm volatile(
        "mma.sync.aligned.m16n8k16.row.col.f32.f16.f16.f32 "
        "{%0,%1,%2,%3}, {%4,%5,%6,%7}, {%8,%9}, {%0,%1,%2,%3};"
        : "+f"(c[0]), "+f"(c[1]), "+f"(c[2]), "+f"(c[3])
        : "r"(a[0]), "r"(a[1]), "r"(a[2]), "r"(a[3]), "r"(b[0]), "r"(b[1]));
}

// ---------------- K1: row squared norms + fp16 copy (warp per row) ---------
__global__ __launch_bounds__(256)
void row_norms_kernel(const float* __restrict__ A) {
    const int w    = threadIdx.x >> 5;
    const int lane = threadIdx.x & 31;
    const int row  = blockIdx.x * 8 + w;
    const float4* a4 = (const float4*)(A + (size_t)row * D);
    float s = 0.f;
    #pragma unroll
    for (int u = 0; u < 4; u++) {
        const int c4 = lane + u * 32;
        float4 v = a4[c4];
        __half2 h0 = __floats2half2_rn(v.x, v.y);
        __half2 h1 = __floats2half2_rn(v.z, v.w);
        uint2 q;
        q.x = *(uint32_t*)&h0; q.y = *(uint32_t*)&h1;
        *(uint2*)(g_embh + (size_t)row * D + c4 * 4) = q;
        s += v.x * v.x + v.y * v.y + v.z * v.z + v.w * v.w;
    }
    #pragma unroll
    for (int o = 16; o > 0; o >>= 1) s += __shfl_down_sync(0xffffffffu, s, o);
    if (lane == 0) g_sq[row] = s;
}

// ---------------- K2: fp16 mma.sync distance GEMM (symmetric) --------------
#define BM 128
#define BN 128
#define BKC 64
#define NCHUNK (D / BKC)   // 8
#define NT 64              // tiles per side
#define NTILES 2080        // 64*65/2
#define GEMM_SPLIT 1776    // 6 waves at 296 concurrent CTAs

#define SM_SQJ   0
#define SM_SQI   512
#define SM_STAGE 1024
#define STAGE_BYTES 32768                   // A 16KB + B 16KB
#define SM_TOTAL (SM_STAGE + 3 * STAGE_BYTES)   // 99328 -> 2 CTAs/SM

static __device__ __forceinline__ uint32_t sw128(uint32_t b) { return b ^ ((b >> 3) & 0x70); }

__global__ __launch_bounds__(256, 2)
void dist_gemm_mma_kernel(int tile_base) {
    extern __shared__ char smem[];
    const uint32_t sbase = smem_u32(smem);
    const int t    = threadIdx.x;
    const int wid  = t >> 5;
    const int lane = t & 31;
    const int g    = lane >> 2;
    const int tq   = lane & 3;
    const int warpM = (wid >> 2) * 64;      // 0 or 64
    const int warpN = (wid & 3) * 32;       // 0,32,64,96

    int flat = tile_base + blockIdx.x;
    int bi = 0;
    while (flat >= NT - bi) { flat -= NT - bi; ++bi; }
    const int bj = bi + flat;
    const int rowA0 = bi * BM;
    const int colB0 = bj * BN;

    if (t < 128) {
        *(float*)(smem + SM_SQJ + t * 4) = g_sq[colB0 + t];
        *(float*)(smem + SM_SQI + t * 4) = g_sq[rowA0 + t];
    }

    const uint32_t laneRowA = (lane & 7) + ((lane >> 3) & 1) * 8;
    const uint32_t laneColA = (lane >> 4) * 16;
    const uint32_t laneRowB = lane & 7;
    const uint32_t laneColB = ((lane >> 3) & 1) * 16;

    auto issue_chunk = [&](int kt, int stg) {
        const int kc = kt * BKC;
        const uint32_t sb = sbase + SM_STAGE + (uint32_t)stg * STAGE_BYTES;
        #pragma unroll
        for (int l = 0; l < 8; l++) {
            int idx = t + l * 256;            // 0..2047
            int r   = idx >> 3;               // 0..255
            int c4  = idx & 7;                // 16B unit within 128B row
            int isA = (r < 128);
            int grow = isA ? (rowA0 + r) : (colB0 + r - 128);
            const __half* src = g_embh + (size_t)grow * D + kc + c4 * 8;
            uint32_t off = (isA ? 0u : 16384u) +
                           sw128((uint32_t)(isA ? r : r - 128) * 128u + (uint32_t)c4 * 16u);
            CP_ASYNC16(sb + off, src);
        }
        CP_COMMIT();
    };

    float acc[4][4][4];
    #pragma unroll
    for (int mt = 0; mt < 4; mt++)
        #pragma unroll
        for (int nt = 0; nt < 4; nt++)
            #pragma unroll
            for (int q = 0; q < 4; q++) acc[mt][nt][q] = 0.f;

    issue_chunk(0, 0);
    issue_chunk(1, 1);

    #pragma unroll 1
    for (int kt = 0; kt < NCHUNK; kt++) {
        const int stg = kt % 3;
        CP_WAIT(1);
        __syncthreads();
        if (kt + 2 < NCHUNK) issue_chunk(kt + 2, (kt + 2) % 3);

        const uint32_t abase = sbase + SM_STAGE + (uint32_t)stg * STAGE_BYTES;
        const uint32_t bbase = abase + 16384u;
        #pragma unroll
        for (int ks = 0; ks < 4; ks++) {       // 4 k-steps of 16 halfs (32B)
            uint32_t af[4][4], bf[4][2];
            #pragma unroll
            for (int mt = 0; mt < 4; mt++) {
                uint32_t byte = (uint32_t)(warpM + mt * 16 + laneRowA) * 128u +
                                (uint32_t)ks * 32u + laneColA;
                ldsm_x4(af[mt], abase + sw128(byte));
            }
            #pragma unroll
            for (int nt = 0; nt < 4; nt++) {
                uint32_t byte = (uint32_t)(warpN + nt * 8 + laneRowB) * 128u +
                                (uint32_t)ks * 32u + laneColB;
                ldsm_x2(bf[nt], bbase + sw128(byte));
            }
            #pragma unroll
            for (int mt = 0; mt < 4; mt++)
                #pragma unroll
                for (int nt = 0; nt < 4; nt++)
                    mma_f16(acc[mt][nt], af[mt], bf[nt]);
        }
    }

    // ---- epilogue: distances; direct + mirror stores + 32-wide segmins ----
    const float* sqj = (const float*)(smem + SM_SQJ);
    const float* sqi = (const float*)(smem + SM_SQI);
    float rmin[4][2];
    float cmin[2][4][2];
    #pragma unroll
    for (int mt = 0; mt < 4; mt++) { rmin[mt][0] = FLT_MAX; rmin[mt][1] = FLT_MAX; }
    #pragma unroll
    for (int mp = 0; mp < 2; mp++)
        #pragma unroll
        for (int nt = 0; nt < 4; nt++) { cmin[mp][nt][0] = FLT_MAX; cmin[mp][nt][1] = FLT_MAX; }

    #pragma unroll
    for (int mt = 0; mt < 4; mt++) {
        const int r0 = warpM + mt * 16 + g;
        const int r1 = r0 + 8;
        const int gr0 = rowA0 + r0, gr1 = rowA0 + r1;
        const float si0 = sqi[r0], si1 = sqi[r1];
        #pragma unroll
        for (int nt = 0; nt < 4; nt++) {
            const int cl = warpN + nt * 8 + tq * 2;
            const int gc = colB0 + cl;
            const float sj0 = sqj[cl], sj1 = sqj[cl + 1];
            float d2;
            float2 o0, o1;
            d2 = si0 + sj0 - 2.f * acc[mt][nt][0];
            o0.x = (d2 > 0.f) ? sqrtf(fmaxf(d2, 1e-12f)) : 0.f;
            d2 = si0 + sj1 - 2.f * acc[mt][nt][1];
            o0.y = (d2 > 0.f) ? sqrtf(fmaxf(d2, 1e-12f)) : 0.f;
            d2 = si1 + sj0 - 2.f * acc[mt][nt][2];
            o1.x = (d2 > 0.f) ? sqrtf(fmaxf(d2, 1e-12f)) : 0.f;
            d2 = si1 + sj1 - 2.f * acc[mt][nt][3];
            o1.y = (d2 > 0.f) ? sqrtf(fmaxf(d2, 1e-12f)) : 0.f;
            *(float2*)(g_dist + (size_t)gr0 * N + gc) = o0;
            *(float2*)(g_dist + (size_t)gr1 * N + gc) = o1;
            g_dist[(size_t)gc * N + gr0]       = o0.x;
            g_dist[(size_t)gc * N + gr1]       = o1.x;
            g_dist[(size_t)(gc + 1) * N + gr0] = o0.y;
            g_dist[(size_t)(gc + 1) * N + gr1] = o1.y;
            rmin[mt][0] = fminf(rmin[mt][0], fminf(o0.x, o0.y));
            rmin[mt][1] = fminf(rmin[mt][1], fminf(o1.x, o1.y));
            cmin[mt >> 1][nt][0] = fminf(cmin[mt >> 1][nt][0], fminf(o0.x, o1.x));
            cmin[mt >> 1][nt][1] = fminf(cmin[mt >> 1][nt][1], fminf(o0.y, o1.y));
        }
    }

    const int rseg = (colB0 + warpN) >> 5;
    #pragma unroll
    for (int mt = 0; mt < 4; mt++) {
        #pragma unroll
        for (int h = 0; h < 2; h++) {
            float x = rmin[mt][h];
            x = fminf(x, __shfl_xor_sync(0xffffffffu, x, 1));
            x = fminf(x, __shfl_xor_sync(0xffffffffu, x, 2));
            if (tq == 0) {
                const int gr = rowA0 + warpM + mt * 16 + g + h * 8;
                g_segmin[(size_t)gr * 256 + rseg] = x;
            }
        }
    }
    #pragma unroll
    for (int mp = 0; mp < 2; mp++) {
        const int cseg = (rowA0 + warpM + mp * 32) >> 5;
        #pragma unroll
        for (int nt = 0; nt < 4; nt++) {
            #pragma unroll
            for (int p = 0; p < 2; p++) {
                float x = cmin[mp][nt][p];
                x = fminf(x, __shfl_xor_sync(0xffffffffu, x, 4));
                x = fminf(x, __shfl_xor_sync(0xffffffffu, x, 8));
                x = fminf(x, __shfl_xor_sync(0xffffffffu, x, 16));
                if (g == 0) {
                    const int gc = colB0 + warpN + nt * 8 + tq * 2 + p;
                    g_segmin[(size_t)gc * 256 + cseg] = x;
                }
            }
        }
    }
}

// ---------------- K3: fused top-16 + curvature, 4 rows per block ------------
// 64-thread groups (2 warps/row). T = max of the two warps' 9th-smallest
// segmin (>=18 distinct elements <= T -> >=16 non-self). Pruned scan uses
// batched MLP-4 gathers + warp-aggregated ballot compaction (one shared
// atomic per warp per 32-element sub-batch). Rank selection is key-ordered
// -> buffer order irrelevant -> deterministic results.
#define BUFCAP 768

__global__ __launch_bounds__(256)
void topk_curv_kernel(const float* __restrict__ ref_curv) {
    const int t    = threadIdx.x;
    const int grp  = t >> 6;              // 0..3
    const int gt   = t & 63;              // thread within group
    const int lane = t & 31;
    const int gw   = (t >> 5) & 1;        // warp within group
    const int i    = blockIdx.x * 4 + grp;

    __shared__ float warp9[4][2];
    __shared__ short segs[4][256];
    __shared__ int   s_scnt[4];
    __shared__ float bufv[4][BUFCAP];
    __shared__ int   bufi[4][BUFCAP];
    __shared__ int   s_bcnt[4];
    __shared__ float knnv[4][KNN];
    __shared__ int   knni[4][KNN];

    if (gt == 0) { s_scnt[grp] = 0; s_bcnt[grp] = 0; }

    // 4 segmins per thread: segs 4*gt .. 4*gt+3
    const float4 sp = *(const float4*)(g_segmin + (size_t)i * 256 + 4 * gt);
    const float spv[4] = {sp.x, sp.y, sp.z, sp.w};

    // each warp: 9th-smallest of its 128 segmins (keyed, duplicate-safe)
    {
        unsigned long long k[4];
        #pragma unroll
        for (int c = 0; c < 4; c++)
            k[c] = ((unsigned long long)__float_as_uint(spv[c]) << 32)
                 | (unsigned)(4 * gt + c);
        float ninth = FLT_MAX;
        #pragma unroll
        for (int r = 0; r < 9; r++) {
            unsigned long long kmin = k[0];
            #pragma unroll
            for (int c = 1; c < 4; c++) kmin = (k[c] < kmin) ? k[c] : kmin;
            #pragma unroll
            for (int o = 16; o > 0; o >>= 1) {
                unsigned long long other = __shfl_xor_sync(0xffffffffu, kmin, o);
                kmin = (other < kmin) ? other : kmin;
            }
            #pragma unroll
            for (int c = 0; c < 4; c++) if (k[c] == kmin) k[c] = ~0ULL;
            ninth = __uint_as_float((uint32_t)(kmin >> 32));
        }
        if (lane == 0) warp9[grp][gw] = ninth;
    }
    BAR64(grp + 1);
    const float T = fmaxf(warp9[grp][0], warp9[grp][1]);

    // qualify individual 32-wide segments (aggregated compaction)
    {
        unsigned keep0 = __ballot_sync(0xffffffffu, spv[0] <= T);
        // do all four via loop for clarity
        #pragma unroll
        for (int c = 0; c < 4; c++) {
            bool keep = (spv[c] <= T);
            unsigned mask = __ballot_sync(0xffffffffu, keep);
            int cnt = __popc(mask);
            int pos = 0;
            if (lane == 0 && cnt) pos = atomicAdd(&s_scnt[grp], cnt);
            pos = __shfl_sync(0xffffffffu, pos, 0);
            int off = __popc(mask & ((1u << lane) - 1u));
            if (keep) segs[grp][pos + off] = (short)(4 * gt + c);
        }
        (void)keep0;
    }
    BAR64(grp + 1);
    const int nseg = s_scnt[grp];

    // pruned scan: batched MLP-4 gathers + ballot compaction
    const float* __restrict__ drow = g_dist + (size_t)i * N;
    const int total = nseg * 32;
    for (int base = 0; base < total; base += 256) {
        float dv[4]; int jj[4];
        #pragma unroll
        for (int u = 0; u < 4; u++) {
            const int e = base + gt + u * 64;
            if (e < total) {
                jj[u] = ((int)segs[grp][e >> 5] << 5) | (e & 31);
                dv[u] = drow[jj[u]];
            } else { jj[u] = -1; dv[u] = FLT_MAX; }
        }
        #pragma unroll
        for (int u = 0; u < 4; u++) {
            const bool keep = (dv[u] <= T) && (jj[u] != i) && (jj[u] >= 0);
            unsigned mask = __ballot_sync(0xffffffffu, keep);
            int cnt = __popc(mask);
            int pos = 0;
            if (lane == 0 && cnt) pos = atomicAdd(&s_bcnt[grp], cnt);
            pos = __shfl_sync(0xffffffffu, pos, 0);
            int off = __popc(mask & ((1u << lane) - 1u));
            if (keep) {
                const int b = pos + off;
                if (b < BUFCAP) { bufv[grp][b] = dv[u]; bufi[grp][b] = jj[u]; }
            }
        }
    }
    BAR64(grp + 1);
    const int n_e = (s_bcnt[grp] < BUFCAP) ? s_bcnt[grp] : BUFCAP;

    // rank selection into smem knn (keys unique by col; ties by col)
    for (int e = gt; e < n_e; e += 64) {
        const unsigned long long mykey =
            ((unsigned long long)__float_as_uint(bufv[grp][e]) << 32) | (unsigned)bufi[grp][e];
        int rank = 0;
        for (int q = 0; q < n_e; q++) {
            const unsigned long long k =
                ((unsigned long long)__float_as_uint(bufv[grp][q]) << 32) | (unsigned)bufi[grp][q];
            rank += (k < mykey);
        }
        if (rank < KNN) {
            knnv[grp][rank] = bufv[grp][e];
            knni[grp][rank] = bufi[grp][e];
        }
    }
    BAR64(grp + 1);

    // fused curvature: warp 0 of the group
    if (gw == 0) {
        int   myidx = 0;
        float myd   = 0.f;
        if (lane < KNN) { myidx = knni[grp][lane]; myd = knnv[grp][lane]; }

        float dsum = myd;
        #pragma unroll
        for (int o = 16; o > 0; o >>= 1)
            dsum += __shfl_xor_sync(0xffffffffu, dsum, o);

        float isum = 0.f;
        #pragma unroll
        for (int u = 0; u < 4; u++) {
            const int p = lane + u * 32;
            const bool act = (p < NPAIRS);
            int L = act ? p : 0;
            int j = 0;
            while (L >= 15 - j) { L -= 15 - j; j++; }
            const int k = j + 1 + L;
            const int ij = __shfl_sync(0xffffffffu, myidx, j);
            const int ik = __shfl_sync(0xffffffffu, myidx, k);
            if (act) isum += g_dist[(size_t)ij * N + ik];
        }
        #pragma unroll
        for (int o = 16; o > 0; o >>= 1)
            isum += __shfl_xor_sync(0xffffffffu, isum, o);

        if (lane == 0) {
            const float avg        = dsum / (float)KNN;
            const float inter_mean = isum / (float)NPAIRS;
            const float curv       = inter_mean / (avg + 1e-8f);
            const float diff       = curv - ref_curv[i];
            g_curv_err[i] = diff * diff;
            g_knn_sum[i]  = dsum;
        }
    }
}

// ---------------- K5: final scalar, two-stage (deterministic) --------------
__global__ void final_stage1(const float* __restrict__ ref_dist) {
    const int t = threadIdx.x;               // 256 threads, 32 blocks
    const int b = blockIdx.x;
    const int gid = b * 256 + t;             // 0..8191
    double e  = (double)g_curv_err[gid];
    double kk = (double)g_knn_sum[gid];
    double rf = 0.0;
    for (int u = gid; u < N * KNN; u += 8192) rf += (double)ref_dist[u];
    __shared__ double d1[256], d2[256], d3[256];
    d1[t] = e; d2[t] = kk; d3[t] = rf;
    __syncthreads();
    for (int s = 128; s > 0; s >>= 1) {
        if (t < s) { d1[t] += d1[t + s]; d2[t] += d2[t + s]; d3[t] += d3[t + s]; }
        __syncthreads();
    }
    if (t == 0) {
        g_part[b][0] = d1[0]; g_part[b][1] = d2[0]; g_part[b][2] = d3[0];
    }
}

__global__ void final_stage2(float* __restrict__ out) {
    const int t = threadIdx.x;               // 32 threads (1 warp)
    double e  = g_part[t][0];
    double kk = g_part[t][1];
    double rf = g_part[t][2];
    #pragma unroll
    for (int o = 16; o > 0; o >>= 1) {
        e  += __shfl_down_sync(0xffffffffu, e,  o);
        kk += __shfl_down_sync(0xffffffffu, kk, o);
        rf += __shfl_down_sync(0xffffffffu, rf, o);
    }
    if (t == 0) {
        double curv_loss = e / (double)N;
        double m_knn = kk / (double)(N * KNN);
        double m_ref = rf / (double)(N * KNN);
        double diff  = m_knn - m_ref;
        out[0] = (float)(curv_loss + 0.1 * diff * diff);
    }
}

// ---------------- launch ----------------------------------------------------
extern "C" void kernel_launch(void* const* d_in, const int* in_sizes, int n_in,
                              void* d_out, int out_size) {
    const float* emb      = (const float*)d_in[0];   // [N, D]
    const float* ref_curv = (const float*)d_in[1];   // [N]
    const float* ref_dist = (const float*)d_in[2];   // [N, K]
    float* out = (float*)d_out;

    static int smem_set = 0;
    if (!smem_set) {
        cudaFuncSetAttribute(dist_gemm_mma_kernel,
                             cudaFuncAttributeMaxDynamicSharedMemorySize, SM_TOTAL);
        smem_set = 1;
    }

    row_norms_kernel<<<N / 8, 256>>>(emb);
    dist_gemm_mma_kernel<<<GEMM_SPLIT, 256, SM_TOTAL>>>(0);
    dist_gemm_mma_kernel<<<NTILES - GEMM_SPLIT, 256, SM_TOTAL>>>(GEMM_SPLIT);
    topk_curv_kernel<<<N / 4, 256>>>(ref_curv);
    final_stage1<<<32, 256>>>(ref_dist);
    final_stage2<<<1, 32>>>(out);
}

// round 17
// speedup vs baseline: 5.1476x; 1.0085x over previous
#include <cuda_runtime.h>
#include <cuda_fp16.h>
#include <math.h>
#include <float.h>
#include <stdint.h>

#define N 8192
#define D 512
#define KNN 16
#define NPAIRS 120   // 16*15/2

// ---------------- scratch (device globals; no runtime allocation) ----------
__device__ float  g_sq[N];
__device__ __half g_embh[(size_t)N * D];    // fp16 (rn) copy of embeddings
__device__ float  g_dist[(size_t)N * N];    // 256 MB full symmetric distance matrix
__device__ float  g_segmin[(size_t)N * 256];// per-row min over 32-col segments
__device__ float  g_curv_err[N];
__device__ float  g_knn_sum[N];
__device__ double g_part[32][3];            // two-stage final reduction

// ---------------- PTX helpers ----------------------------------------------
__device__ __forceinline__ uint32_t smem_u32(const void* p) {
    uint32_t a;
    asm("{ .reg .u64 t; cvta.to.shared.u64 t, %1; cvt.u32.u64 %0, t; }" : "=r"(a) : "l"(p));
    return a;
}
#define CP_ASYNC16(dst, src) \
    asm volatile("cp.async.cg.shared.global [%0], [%1], 16;" :: "r"(dst), "l"(src))
#define CP_COMMIT() asm volatile("cp.async.commit_group;" ::: "memory")
#define CP_WAIT(n)  asm volatile("cp.async.wait_group %0;" :: "n"(n) : "memory")

__device__ __forceinline__ void ldsm_x4(uint32_t* r, uint32_t addr) {
    asm volatile("ldmatrix.sync.aligned.m8n8.x4.shared.b16 {%0,%1,%2,%3}, [%4];"
                 : "=r"(r[0]), "=r"(r[1]), "=r"(r[2]), "=r"(r[3]) : "r"(addr));
}
__device__ __forceinline__ void ldsm_x2(uint32_t* r, uint32_t addr) {
    asm volatile("ldmatrix.sync.aligned.m8n8.x2.shared.b16 {%0,%1}, [%2];"
                 : "=r"(r[0]), "=r"(r[1]) : "r"(addr));
}
__device__ __forceinline__ void mma_f16(float* c, const uint32_t* a, const uint32_t* b) {
    asm volatile(
        "mma.sync.aligned.m16n8k16.row.col.f32.f16.f16.f32 "
        "{%0,%1,%2,%3}, {%4,%5,%6,%7}, {%8,%9}, {%0,%1,%2,%3};"
        : "+f"(c[0]), "+f"(c[1]), "+f"(c[2]), "+f"(c[3])
        : "r"(a[0]), "r"(a[1]), "r"(a[2]), "r"(a[3]), "r"(b[0]), "r"(b[1]));
}

// ---------------- K1: row squared norms + fp16 copy (warp per row) ---------
__global__ __launch_bounds__(256)
void row_norms_kernel(const float* __restrict__ A) {
    const int w    = threadIdx.x >> 5;
    const int lane = threadIdx.x & 31;
    const int row  = blockIdx.x * 8 + w;
    const float4* a4 = (const float4*)(A + (size_t)row * D);
    float s = 0.f;
    #pragma unroll
    for (int u = 0; u < 4; u++) {
        const int c4 = lane + u * 32;
        float4 v = a4[c4];
        __half2 h0 = __floats2half2_rn(v.x, v.y);
        __half2 h1 = __floats2half2_rn(v.z, v.w);
        uint2 q;
        q.x = *(uint32_t*)&h0; q.y = *(uint32_t*)&h1;
        *(uint2*)(g_embh + (size_t)row * D + c4 * 4) = q;
        s += v.x * v.x + v.y * v.y + v.z * v.z + v.w * v.w;
    }
    #pragma unroll
    for (int o = 16; o > 0; o >>= 1) s += __shfl_down_sync(0xffffffffu, s, o);
    if (lane == 0) g_sq[row] = s;
}

// ---------------- K2: fp16 mma.sync distance GEMM (symmetric) --------------
#define BM 128
#define BN 128
#define BKC 64
#define NCHUNK (D / BKC)   // 8
#define NT 64              // tiles per side
#define NTILES 2080        // 64*65/2

#define SM_SQJ   0
#define SM_SQI   512
#define SM_STAGE 1024
#define STAGE_BYTES 32768                   // A 16KB + B 16KB
#define SM_TOTAL (SM_STAGE + 3 * STAGE_BYTES)   // 99328 -> 2 CTAs/SM

static __device__ __forceinline__ uint32_t sw128(uint32_t b) { return b ^ ((b >> 3) & 0x70); }

__global__ __launch_bounds__(256, 2)
void dist_gemm_mma_kernel() {
    extern __shared__ char smem[];
    const uint32_t sbase = smem_u32(smem);
    const int t    = threadIdx.x;
    const int wid  = t >> 5;
    const int lane = t & 31;
    const int g    = lane >> 2;
    const int tq   = lane & 3;
    const int warpM = (wid >> 2) * 64;      // 0 or 64
    const int warpN = (wid & 3) * 32;       // 0,32,64,96

    int flat = blockIdx.x;
    int bi = 0;
    while (flat >= NT - bi) { flat -= NT - bi; ++bi; }
    const int bj = bi + flat;
    const int rowA0 = bi * BM;
    const int colB0 = bj * BN;

    if (t < 128) {
        *(float*)(smem + SM_SQJ + t * 4) = g_sq[colB0 + t];
        *(float*)(smem + SM_SQI + t * 4) = g_sq[rowA0 + t];
    }

    const uint32_t laneRowA = (lane & 7) + ((lane >> 3) & 1) * 8;
    const uint32_t laneColA = (lane >> 4) * 16;
    const uint32_t laneRowB = lane & 7;
    const uint32_t laneColB = ((lane >> 3) & 1) * 16;

    auto issue_chunk = [&](int kt, int stg) {
        const int kc = kt * BKC;
        const uint32_t sb = sbase + SM_STAGE + (uint32_t)stg * STAGE_BYTES;
        #pragma unroll
        for (int l = 0; l < 8; l++) {
            int idx = t + l * 256;            // 0..2047
            int r   = idx >> 3;               // 0..255
            int c4  = idx & 7;                // 16B unit within 128B row
            int isA = (r < 128);
            int grow = isA ? (rowA0 + r) : (colB0 + r - 128);
            const __half* src = g_embh + (size_t)grow * D + kc + c4 * 8;
            uint32_t off = (isA ? 0u : 16384u) +
                           sw128((uint32_t)(isA ? r : r - 128) * 128u + (uint32_t)c4 * 16u);
            CP_ASYNC16(sb + off, src);
        }
        CP_COMMIT();
    };

    float acc[4][4][4];
    #pragma unroll
    for (int mt = 0; mt < 4; mt++)
        #pragma unroll
        for (int nt = 0; nt < 4; nt++)
            #pragma unroll
            for (int q = 0; q < 4; q++) acc[mt][nt][q] = 0.f;

    issue_chunk(0, 0);
    issue_chunk(1, 1);

    #pragma unroll 1
    for (int kt = 0; kt < NCHUNK; kt++) {
        const int stg = kt % 3;
        CP_WAIT(1);
        __syncthreads();
        if (kt + 2 < NCHUNK) issue_chunk(kt + 2, (kt + 2) % 3);

        const uint32_t abase = sbase + SM_STAGE + (uint32_t)stg * STAGE_BYTES;
        const uint32_t bbase = abase + 16384u;
        #pragma unroll
        for (int ks = 0; ks < 4; ks++) {       // 4 k-steps of 16 halfs (32B)
            uint32_t af[4][4], bf[4][2];
            #pragma unroll
            for (int mt = 0; mt < 4; mt++) {
                uint32_t byte = (uint32_t)(warpM + mt * 16 + laneRowA) * 128u +
                                (uint32_t)ks * 32u + laneColA;
                ldsm_x4(af[mt], abase + sw128(byte));
            }
            #pragma unroll
            for (int nt = 0; nt < 4; nt++) {
                uint32_t byte = (uint32_t)(warpN + nt * 8 + laneRowB) * 128u +
                                (uint32_t)ks * 32u + laneColB;
                ldsm_x2(bf[nt], bbase + sw128(byte));
            }
            #pragma unroll
            for (int mt = 0; mt < 4; mt++)
                #pragma unroll
                for (int nt = 0; nt < 4; nt++)
                    mma_f16(acc[mt][nt], af[mt], bf[nt]);
        }
    }

    // ---- epilogue: distances; direct + mirror stores + 32-wide segmins ----
    const float* sqj = (const float*)(smem + SM_SQJ);
    const float* sqi = (const float*)(smem + SM_SQI);
    float rmin[4][2];
    float cmin[2][4][2];
    #pragma unroll
    for (int mt = 0; mt < 4; mt++) { rmin[mt][0] = FLT_MAX; rmin[mt][1] = FLT_MAX; }
    #pragma unroll
    for (int mp = 0; mp < 2; mp++)
        #pragma unroll
        for (int nt = 0; nt < 4; nt++) { cmin[mp][nt][0] = FLT_MAX; cmin[mp][nt][1] = FLT_MAX; }

    #pragma unroll
    for (int mt = 0; mt < 4; mt++) {
        const int r0 = warpM + mt * 16 + g;
        const int r1 = r0 + 8;
        const int gr0 = rowA0 + r0, gr1 = rowA0 + r1;
        const float si0 = sqi[r0], si1 = sqi[r1];
        #pragma unroll
        for (int nt = 0; nt < 4; nt++) {
            const int cl = warpN + nt * 8 + tq * 2;
            const int gc = colB0 + cl;
            const float sj0 = sqj[cl], sj1 = sqj[cl + 1];
            float d2;
            float2 o0, o1;
            d2 = si0 + sj0 - 2.f * acc[mt][nt][0];
            o0.x = (d2 > 0.f) ? sqrtf(fmaxf(d2, 1e-12f)) : 0.f;
            d2 = si0 + sj1 - 2.f * acc[mt][nt][1];
            o0.y = (d2 > 0.f) ? sqrtf(fmaxf(d2, 1e-12f)) : 0.f;
            d2 = si1 + sj0 - 2.f * acc[mt][nt][2];
            o1.x = (d2 > 0.f) ? sqrtf(fmaxf(d2, 1e-12f)) : 0.f;
            d2 = si1 + sj1 - 2.f * acc[mt][nt][3];
            o1.y = (d2 > 0.f) ? sqrtf(fmaxf(d2, 1e-12f)) : 0.f;
            *(float2*)(g_dist + (size_t)gr0 * N + gc) = o0;
            *(float2*)(g_dist + (size_t)gr1 * N + gc) = o1;
            g_dist[(size_t)gc * N + gr0]       = o0.x;
            g_dist[(size_t)gc * N + gr1]       = o1.x;
            g_dist[(size_t)(gc + 1) * N + gr0] = o0.y;
            g_dist[(size_t)(gc + 1) * N + gr1] = o1.y;
            rmin[mt][0] = fminf(rmin[mt][0], fminf(o0.x, o0.y));
            rmin[mt][1] = fminf(rmin[mt][1], fminf(o1.x, o1.y));
            cmin[mt >> 1][nt][0] = fminf(cmin[mt >> 1][nt][0], fminf(o0.x, o1.x));
            cmin[mt >> 1][nt][1] = fminf(cmin[mt >> 1][nt][1], fminf(o0.y, o1.y));
        }
    }

    const int rseg = (colB0 + warpN) >> 5;
    #pragma unroll
    for (int mt = 0; mt < 4; mt++) {
        #pragma unroll
        for (int h = 0; h < 2; h++) {
            float x = rmin[mt][h];
            x = fminf(x, __shfl_xor_sync(0xffffffffu, x, 1));
            x = fminf(x, __shfl_xor_sync(0xffffffffu, x, 2));
            if (tq == 0) {
                const int gr = rowA0 + warpM + mt * 16 + g + h * 8;
                g_segmin[(size_t)gr * 256 + rseg] = x;
            }
        }
    }
    #pragma unroll
    for (int mp = 0; mp < 2; mp++) {
        const int cseg = (rowA0 + warpM + mp * 32) >> 5;
        #pragma unroll
        for (int nt = 0; nt < 4; nt++) {
            #pragma unroll
            for (int p = 0; p < 2; p++) {
                float x = cmin[mp][nt][p];
                x = fminf(x, __shfl_xor_sync(0xffffffffu, x, 4));
                x = fminf(x, __shfl_xor_sync(0xffffffffu, x, 8));
                x = fminf(x, __shfl_xor_sync(0xffffffffu, x, 16));
                if (g == 0) {
                    const int gc = colB0 + warpN + nt * 8 + tq * 2 + p;
                    g_segmin[(size_t)gc * 256 + cseg] = x;
                }
            }
        }
    }
}

// ---------------- K3: fused top-16 + curvature, warp per row ----------------
// One warp fully owns one row: T = EXACT 17th-smallest of the row's 256
// segmins (8 keys/lane, 17 keyed extraction rounds) -> >=17 distinct row
// elements <= T -> >=16 non-self (tightest segment-level safe bound).
// All compaction via ballot/popc with warp-uniform register counters:
// ZERO atomics, ZERO barriers. Rank selection is key-ordered -> deterministic.
#define BUFCAP 512

__global__ __launch_bounds__(256)
void topk_curv_kernel(const float* __restrict__ ref_curv) {
    const int w    = threadIdx.x >> 5;    // 0..7, warp = row
    const int lane = threadIdx.x & 31;
    const int i    = blockIdx.x * 8 + w;

    __shared__ short segs[8][256];
    __shared__ float bufv[8][BUFCAP];
    __shared__ int   bufi[8][BUFCAP];
    __shared__ float knnv[8][KNN];
    __shared__ int   knni[8][KNN];

    // 8 segmins per lane: segs 4*lane..4*lane+3 and 128+4*lane..128+4*lane+3
    const float4 s0 = *(const float4*)(g_segmin + (size_t)i * 256 + 4 * lane);
    const float4 s1 = *(const float4*)(g_segmin + (size_t)i * 256 + 128 + 4 * lane);
    const float spv[8] = {s0.x, s0.y, s0.z, s0.w, s1.x, s1.y, s1.z, s1.w};
    const int   sid[8] = {4 * lane, 4 * lane + 1, 4 * lane + 2, 4 * lane + 3,
                          128 + 4 * lane, 129 + 4 * lane, 130 + 4 * lane, 131 + 4 * lane};

    // T = exact 17th-smallest segmin (keyed, duplicate-safe)
    float T;
    {
        unsigned long long k[8];
        #pragma unroll
        for (int c = 0; c < 8; c++)
            k[c] = ((unsigned long long)__float_as_uint(spv[c]) << 32) | (unsigned)sid[c];
        #pragma unroll 1
        for (int r = 0; r < 17; r++) {
            unsigned long long kmin = k[0];
            #pragma unroll
            for (int c = 1; c < 8; c++) kmin = (k[c] < kmin) ? k[c] : kmin;
            #pragma unroll
            for (int o = 16; o > 0; o >>= 1) {
                unsigned long long other = __shfl_xor_sync(0xffffffffu, kmin, o);
                kmin = (other < kmin) ? other : kmin;
            }
            #pragma unroll
            for (int c = 0; c < 8; c++) if (k[c] == kmin) k[c] = ~0ULL;
            T = __uint_as_float((uint32_t)(kmin >> 32));
        }
    }

    // qualify segments (ballot compaction, uniform register counter)
    int scnt = 0;
    #pragma unroll
    for (int c = 0; c < 8; c++) {
        const bool keep = (spv[c] <= T);
        const unsigned mask = __ballot_sync(0xffffffffu, keep);
        const int off = __popc(mask & ((1u << lane) - 1u));
        if (keep) segs[w][scnt + off] = (short)sid[c];
        scnt += __popc(mask);
    }
    __syncwarp();

    // pruned scan: batched MLP-4 gathers + ballot compaction (no atomics)
    const float* __restrict__ drow = g_dist + (size_t)i * N;
    const int total = scnt * 32;
    int bcnt = 0;
    #pragma unroll 1
    for (int base = 0; base < total; base += 128) {
        float dv[4]; int jj[4];
        #pragma unroll
        for (int u = 0; u < 4; u++) {
            const int e = base + lane + u * 32;
            if (e < total) {
                jj[u] = ((int)segs[w][e >> 5] << 5) | (e & 31);
                dv[u] = drow[jj[u]];
            } else { jj[u] = -1; dv[u] = FLT_MAX; }
        }
        #pragma unroll
        for (int u = 0; u < 4; u++) {
            const bool keep = (dv[u] <= T) && (jj[u] != i) && (jj[u] >= 0);
            const unsigned mask = __ballot_sync(0xffffffffu, keep);
            const int off = __popc(mask & ((1u << lane) - 1u));
            if (keep) {
                const int b = bcnt + off;
                if (b < BUFCAP) { bufv[w][b] = dv[u]; bufi[w][b] = jj[u]; }
            }
            bcnt += __popc(mask);
        }
    }
    __syncwarp();
    const int n_e = (bcnt < BUFCAP) ? bcnt : BUFCAP;

    // rank selection into smem knn (keys unique by col; ties by col)
    for (int e = lane; e < n_e; e += 32) {
        const unsigned long long mykey =
            ((unsigned long long)__float_as_uint(bufv[w][e]) << 32) | (unsigned)bufi[w][e];
        int rank = 0;
        for (int q = 0; q < n_e; q++) {
            const unsigned long long k =
                ((unsigned long long)__float_as_uint(bufv[w][q]) << 32) | (unsigned)bufi[w][q];
            rank += (k < mykey);
        }
        if (rank < KNN) {
            knnv[w][rank] = bufv[w][e];
            knni[w][rank] = bufi[w][e];
        }
    }
    __syncwarp();

    // fused curvature (same warp)
    {
        int   myidx = 0;
        float myd   = 0.f;
        if (lane < KNN) { myidx = knni[w][lane]; myd = knnv[w][lane]; }

        float dsum = myd;
        #pragma unroll
        for (int o = 16; o > 0; o >>= 1)
            dsum += __shfl_xor_sync(0xffffffffu, dsum, o);

        float isum = 0.f;
        #pragma unroll
        for (int u = 0; u < 4; u++) {
            const int p = lane + u * 32;
            const bool act = (p < NPAIRS);
            int L = act ? p : 0;
            int j = 0;
            while (L >= 15 - j) { L -= 15 - j; j++; }
            const int k = j + 1 + L;
            const int ij = __shfl_sync(0xffffffffu, myidx, j);
            const int ik = __shfl_sync(0xffffffffu, myidx, k);
            if (act) isum += g_dist[(size_t)ij * N + ik];
        }
        #pragma unroll
        for (int o = 16; o > 0; o >>= 1)
            isum += __shfl_xor_sync(0xffffffffu, isum, o);

        if (lane == 0) {
            const float avg        = dsum / (float)KNN;
            const float inter_mean = isum / (float)NPAIRS;
            const float curv       = inter_mean / (avg + 1e-8f);
            const float diff       = curv - ref_curv[i];
            g_curv_err[i] = diff * diff;
            g_knn_sum[i]  = dsum;
        }
    }
}

// ---------------- K5: final scalar, two-stage (deterministic) --------------
__global__ void final_stage1(const float* __restrict__ ref_dist) {
    const int t = threadIdx.x;               // 256 threads, 32 blocks
    const int b = blockIdx.x;
    const int gid = b * 256 + t;             // 0..8191
    double e  = (double)g_curv_err[gid];
    double kk = (double)g_knn_sum[gid];
    double rf = 0.0;
    for (int u = gid; u < N * KNN; u += 8192) rf += (double)ref_dist[u];
    __shared__ double d1[256], d2[256], d3[256];
    d1[t] = e; d2[t] = kk; d3[t] = rf;
    __syncthreads();
    for (int s = 128; s > 0; s >>= 1) {
        if (t < s) { d1[t] += d1[t + s]; d2[t] += d2[t + s]; d3[t] += d3[t + s]; }
        __syncthreads();
    }
    if (t == 0) {
        g_part[b][0] = d1[0]; g_part[b][1] = d2[0]; g_part[b][2] = d3[0];
    }
}

__global__ void final_stage2(float* __restrict__ out) {
    const int t = threadIdx.x;               // 32 threads (1 warp)
    double e  = g_part[t][0];
    double kk = g_part[t][1];
    double rf = g_part[t][2];
    #pragma unroll
    for (int o = 16; o > 0; o >>= 1) {
        e  += __shfl_down_sync(0xffffffffu, e,  o);
        kk += __shfl_down_sync(0xffffffffu, kk, o);
        rf += __shfl_down_sync(0xffffffffu, rf, o);
    }
    if (t == 0) {
        double curv_loss = e / (double)N;
        double m_knn = kk / (double)(N * KNN);
        double m_ref = rf / (double)(N * KNN);
        double diff  = m_knn - m_ref;
        out[0] = (float)(curv_loss + 0.1 * diff * diff);
    }
}

// ---------------- launch ----------------------------------------------------
extern "C" void kernel_launch(void* const* d_in, const int* in_sizes, int n_in,
                              void* d_out, int out_size) {
    const float* emb      = (const float*)d_in[0];   // [N, D]
    const float* ref_curv = (const float*)d_in[1];   // [N]
    const float* ref_dist = (const float*)d_in[2];   // [N, K]
    float* out = (float*)d_out;

    static int smem_set = 0;
    if (!smem_set) {
        cudaFuncSetAttribute(dist_gemm_mma_kernel,
                             cudaFuncAttributeMaxDynamicSharedMemorySize, SM_TOTAL);
        smem_set = 1;
    }

    row_norms_kernel<<<N / 8, 256>>>(emb);
    dist_gemm_mma_kernel<<<NTILES, 256, SM_TOTAL>>>();
    topk_curv_kernel<<<N / 8, 256>>>(ref_curv);
    final_stage1<<<32, 256>>>(ref_dist);
    final_stage2<<<1, 32>>>(out);
}